// round 1
// baseline (speedup 1.0000x reference)
#include <cuda_runtime.h>
#include <math.h>

// ---------------- problem constants ----------------
#define BB 2
#define SS 2048
#define DM 1024
#define NH 16
#define NKV 4
#define HDIM 64
#define NE 8
#define FF 2048
#define NT (BB*SS)                    // 4096 tokens
#define QKVN (DM + 2*NKV*HDIM)        // 1536
#define CAP (2*NT + NE*128)           // 9216 padded MoE slots
#define SCALEQ 0.125f                 // 1/sqrt(64)
#define CLIPV 8.0f

// ---------------- device scratch (no runtime allocation) ----------------
__device__ float g_x1[NT*DM];
__device__ float g_qkv[NT*QKVN];
__device__ float g_attn[NT*DM];
__device__ float g_hidden[NT*DM];
__device__ float g_x2[NT*DM];
__device__ int   g_top_e[NT*2];
__device__ float g_top_w[NT*2];
__device__ int   g_cnt[NE];
__device__ int   g_fill[NE];
__device__ int   g_segoff[NE+1];
__device__ int   g_total;
__device__ int   g_perm[CAP];
__device__ int   g_tok_slot[NT*2];
__device__ float g_h1[CAP*FF];
__device__ float g_h2[CAP*FF];
__device__ float g_y[CAP*DM];

// ---------------- layernorm: one block per row (1024 cols, 256 thr x float4) ----------------
__global__ void ln_kernel(const float* __restrict__ x, const float* __restrict__ w,
                          float* __restrict__ out) {
    int row = blockIdx.x, tid = threadIdx.x;
    float4 v = ((const float4*)(x + (size_t)row*DM))[tid];
    float s = v.x+v.y+v.z+v.w;
    float q = v.x*v.x+v.y*v.y+v.z*v.z+v.w*v.w;
#pragma unroll
    for (int o = 16; o; o >>= 1) {
        s += __shfl_xor_sync(0xffffffffu, s, o);
        q += __shfl_xor_sync(0xffffffffu, q, o);
    }
    __shared__ float ssm[8], qsm[8];
    if ((tid & 31) == 0) { ssm[tid>>5] = s; qsm[tid>>5] = q; }
    __syncthreads();
    float ts = 0.f, tq = 0.f;
#pragma unroll
    for (int i = 0; i < 8; i++) { ts += ssm[i]; tq += qsm[i]; }
    float mu  = ts * (1.f/DM);
    float var = tq * (1.f/DM) - mu*mu;
    float rs  = rsqrtf(var + 1e-5f);
    float4 wv = ((const float4*)w)[tid];
    float4 r;
    r.x = (v.x-mu)*rs*wv.x; r.y = (v.y-mu)*rs*wv.y;
    r.z = (v.z-mu)*rs*wv.z; r.w = (v.w-mu)*rs*wv.w;
    ((float4*)(out + (size_t)row*DM))[tid] = r;
}

// ---------------- generic 128x128x16 SGEMM, 256 thr, 8x8 microtile ----------------
// EPI: 0 none, 1 clip(+-8), 2 add residual
// GATHER: A rows indirected through g_perm (tok<0 -> zeros)
// BT: B stored [N,K] row-major (dot-of-rows); else [K,N] row-major
// EXPERT: per-128-row-tile expert select via g_segoff; early exit past g_total
template<int EPI, bool GATHER, bool BT, bool EXPERT>
__global__ void sgemm128(const float* __restrict__ A, const float* __restrict__ Bm,
                         float* __restrict__ C, const float* __restrict__ resid,
                         int M, int N, int K, long ldbE) {
    int mbase = blockIdx.y * 128;
    if (EXPERT) {
        if (mbase >= g_total) return;
        int e = 0;
#pragma unroll
        for (int i = 0; i < NE; i++) if (g_segoff[i+1] <= mbase) e = i + 1;
        Bm += (size_t)e * ldbE;
    }
    int nbase = blockIdx.x * 128;
    __shared__ float As[16][128];
    __shared__ float Bs[16][128];
    int tid = threadIdx.x;
    int ar  = tid >> 1;           // A tile row (2 threads/row)
    int ac4 = (tid & 1) * 2;      // first float4 col (0 or 2)
    const float* arow;
    bool avalid = true;
    if (GATHER) {
        int tok = g_perm[mbase + ar];
        avalid = (tok >= 0);
        arow = A + (size_t)(avalid ? tok : 0) * K;
    } else {
        arow = A + (size_t)(mbase + ar) * K;
    }
    int tm = (tid >> 4) * 8, tn = (tid & 15) * 8;
    float acc[8][8];
#pragma unroll
    for (int i = 0; i < 8; i++)
#pragma unroll
        for (int j = 0; j < 8; j++) acc[i][j] = 0.f;

    for (int kb = 0; kb < K; kb += 16) {
        float4 a0, a1;
        if (avalid) {
            a0 = *(const float4*)(arow + kb + ac4*4);
            a1 = *(const float4*)(arow + kb + ac4*4 + 4);
        } else {
            a0 = make_float4(0.f,0.f,0.f,0.f); a1 = a0;
        }
        As[ac4*4+0][ar]=a0.x; As[ac4*4+1][ar]=a0.y; As[ac4*4+2][ar]=a0.z; As[ac4*4+3][ar]=a0.w;
        As[ac4*4+4][ar]=a1.x; As[ac4*4+5][ar]=a1.y; As[ac4*4+6][ar]=a1.z; As[ac4*4+7][ar]=a1.w;
        if (!BT) {
#pragma unroll
            for (int q = 0; q < 2; q++) {
                int f4 = tid*2 + q; int k = f4 >> 5; int n4 = f4 & 31;
                float4 bv = *(const float4*)(Bm + (size_t)(kb + k)*N + nbase + n4*4);
                *(float4*)&Bs[k][n4*4] = bv;
            }
        } else {
#pragma unroll
            for (int q = 0; q < 2; q++) {
                int f4 = tid*2 + q; int n = f4 >> 2; int k4 = f4 & 3;
                float4 bv = *(const float4*)(Bm + (size_t)(nbase + n)*K + kb + k4*4);
                Bs[k4*4+0][n]=bv.x; Bs[k4*4+1][n]=bv.y; Bs[k4*4+2][n]=bv.z; Bs[k4*4+3][n]=bv.w;
            }
        }
        __syncthreads();
#pragma unroll
        for (int kk = 0; kk < 16; kk++) {
            float a[8], b[8];
            *(float4*)&a[0] = *(float4*)&As[kk][tm];
            *(float4*)&a[4] = *(float4*)&As[kk][tm+4];
            *(float4*)&b[0] = *(float4*)&Bs[kk][tn];
            *(float4*)&b[4] = *(float4*)&Bs[kk][tn+4];
#pragma unroll
            for (int i = 0; i < 8; i++)
#pragma unroll
                for (int j = 0; j < 8; j++)
                    acc[i][j] += a[i]*b[j];
        }
        __syncthreads();
    }
#pragma unroll
    for (int i = 0; i < 8; i++) {
        int row = mbase + tm + i;
        float* crow = C + (size_t)row*N + nbase + tn;
        float vv[8];
#pragma unroll
        for (int j = 0; j < 8; j++) {
            float v = acc[i][j];
            if (EPI == 1) v = fminf(fmaxf(v, -CLIPV), CLIPV);
            if (EPI == 2) v += resid[(size_t)row*N + nbase + tn + j];
            vv[j] = v;
        }
        *(float4*)&crow[0] = *(float4*)&vv[0];
        *(float4*)&crow[4] = *(float4*)&vv[4];
    }
}

// ---------------- RoPE in-place on q (16 heads) and k (4 heads) ----------------
__global__ void rope_kernel() {
    int idx = blockIdx.x*blockDim.x + threadIdx.x;
    if (idx >= NT*20*32) return;
    int i    = idx & 31;
    int head = (idx >> 5) % 20;
    int n    = idx / (32*20);
    int s    = n & (SS - 1);
    float inv = (float)pow(10000.0, -(double)i / 32.0);
    float ang = (float)s * inv;
    float sn, cs;
    sincosf(ang, &sn, &cs);
    float* base = g_qkv + (size_t)n*QKVN + (head < NH ? head*HDIM : DM + (head-NH)*HDIM);
    float x1 = base[i], x2 = base[i+32];
    base[i]    = x1*cs - x2*sn;
    base[i+32] = x1*sn + x2*cs;
}

// ---------------- flash attention (causal, GQA rep=4), 64x64 tiles, fp32 ----------------
#define AST 68
#define FLASH_SMEM (4*64*AST*4)
__global__ void flash_attn_kernel(const float* __restrict__ qkv, float* __restrict__ out) {
    extern __shared__ float sm[];
    float* Qs = sm;
    float* Ks = Qs + 64*AST;
    float* Vs = Ks + 64*AST;
    float* Ps = Vs + 64*AST;
    int qt = blockIdx.x, bh = blockIdx.y;
    int b = bh >> 4, h = bh & 15, kh = h >> 2;
    int tid = threadIdx.x, tx = tid & 15, ty = tid >> 4;

    const float* qp = qkv + (size_t)(b*SS + qt*64)*QKVN + h*HDIM;
    for (int t = tid; t < 64*16; t += 256) {
        int r = t >> 4, c4 = t & 15;
        float4 v = *(const float4*)(qp + (size_t)r*QKVN + c4*4);
        v.x *= SCALEQ; v.y *= SCALEQ; v.z *= SCALEQ; v.w *= SCALEQ;
        *(float4*)&Qs[r*AST + c4*4] = v;
    }
    float o[4][4]; float l[4]; float m[4];
#pragma unroll
    for (int i = 0; i < 4; i++) {
        l[i] = 0.f; m[i] = -1e30f;
#pragma unroll
        for (int j = 0; j < 4; j++) o[i][j] = 0.f;
    }
    for (int kt = 0; kt <= qt; kt++) {
        __syncthreads();
        const float* kp = qkv + (size_t)(b*SS + kt*64)*QKVN + DM + kh*HDIM;
        const float* vp = kp + NKV*HDIM;
        for (int t = tid; t < 64*16; t += 256) {
            int r = t >> 4, c4 = t & 15;
            *(float4*)&Ks[r*AST + c4*4] = *(const float4*)(kp + (size_t)r*QKVN + c4*4);
            *(float4*)&Vs[r*AST + c4*4] = *(const float4*)(vp + (size_t)r*QKVN + c4*4);
        }
        __syncthreads();
        float s[4][4];
#pragma unroll
        for (int i = 0; i < 4; i++)
#pragma unroll
            for (int j = 0; j < 4; j++) s[i][j] = 0.f;
#pragma unroll
        for (int d4 = 0; d4 < 16; d4++) {
            float4 qv[4], kv[4];
#pragma unroll
            for (int i = 0; i < 4; i++) qv[i] = *(float4*)&Qs[(ty*4+i)*AST + d4*4];
#pragma unroll
            for (int j = 0; j < 4; j++) kv[j] = *(float4*)&Ks[(tx*4+j)*AST + d4*4];
#pragma unroll
            for (int i = 0; i < 4; i++)
#pragma unroll
                for (int j = 0; j < 4; j++)
                    s[i][j] += qv[i].x*kv[j].x + qv[i].y*kv[j].y + qv[i].z*kv[j].z + qv[i].w*kv[j].w;
        }
        if (kt == qt) {
#pragma unroll
            for (int i = 0; i < 4; i++)
#pragma unroll
                for (int j = 0; j < 4; j++)
                    if (kt*64 + tx*4 + j > qt*64 + ty*4 + i) s[i][j] = -1e30f;
        }
#pragma unroll
        for (int i = 0; i < 4; i++) {
            float mt = fmaxf(fmaxf(s[i][0], s[i][1]), fmaxf(s[i][2], s[i][3]));
#pragma unroll
            for (int off = 8; off; off >>= 1)
                mt = fmaxf(mt, __shfl_xor_sync(0xffffffffu, mt, off));
            float mnew = fmaxf(m[i], mt);
            float corr = __expf(m[i] - mnew);
            l[i] *= corr;
#pragma unroll
            for (int j = 0; j < 4; j++) o[i][j] *= corr;
            float rs = 0.f;
#pragma unroll
            for (int j = 0; j < 4; j++) {
                float p = __expf(s[i][j] - mnew);
                Ps[(ty*4+i)*AST + tx*4 + j] = p;
                rs += p;
            }
#pragma unroll
            for (int off = 8; off; off >>= 1)
                rs += __shfl_xor_sync(0xffffffffu, rs, off);
            l[i] += rs;
            m[i] = mnew;
        }
        __syncthreads();
#pragma unroll 8
        for (int k = 0; k < 64; k++) {
            float4 vv = *(float4*)&Vs[k*AST + tx*4];
#pragma unroll
            for (int i = 0; i < 4; i++) {
                float pr = Ps[(ty*4+i)*AST + k];
                o[i][0] += pr*vv.x; o[i][1] += pr*vv.y;
                o[i][2] += pr*vv.z; o[i][3] += pr*vv.w;
            }
        }
    }
#pragma unroll
    for (int i = 0; i < 4; i++) {
        float invl = 1.f / l[i];
        float4 r = make_float4(o[i][0]*invl, o[i][1]*invl, o[i][2]*invl, o[i][3]*invl);
        *(float4*)(out + (size_t)(b*SS + qt*64 + ty*4 + i)*DM + h*HDIM + tx*4) = r;
    }
}

// ---------------- router: one warp per token, logits->softmax->top2 ----------------
__global__ void router_kernel(const float* __restrict__ x2, const float* __restrict__ rw) {
    int t = (blockIdx.x*blockDim.x + threadIdx.x) >> 5;
    int lane = threadIdx.x & 31;
    if (t >= NT) return;
    const float* xr = x2 + (size_t)t*DM;
    float acc[NE];
#pragma unroll
    for (int e = 0; e < NE; e++) acc[e] = 0.f;
    for (int d = lane; d < DM; d += 32) {
        float xv = xr[d];
        float4 r0 = ((const float4*)rw)[d*2];
        float4 r1 = ((const float4*)rw)[d*2+1];
        acc[0]+=xv*r0.x; acc[1]+=xv*r0.y; acc[2]+=xv*r0.z; acc[3]+=xv*r0.w;
        acc[4]+=xv*r1.x; acc[5]+=xv*r1.y; acc[6]+=xv*r1.z; acc[7]+=xv*r1.w;
    }
#pragma unroll
    for (int o = 16; o; o >>= 1)
#pragma unroll
        for (int e = 0; e < NE; e++)
            acc[e] += __shfl_xor_sync(0xffffffffu, acc[e], o);
    if (lane == 0) {
        int e0 = 0; float m0 = acc[0];
#pragma unroll
        for (int e = 1; e < NE; e++) if (acc[e] > m0) { m0 = acc[e]; e0 = e; }
        int e1 = -1; float m1 = -3.4e38f;
#pragma unroll
        for (int e = 0; e < NE; e++) if (e != e0 && acc[e] > m1) { m1 = acc[e]; e1 = e; }
        float p1 = expf(m1 - m0);
        float w0 = 1.f / (1.f + p1);
        float w1 = p1 / (1.f + p1);
        g_top_e[2*t] = e0; g_top_e[2*t+1] = e1;
        g_top_w[2*t] = w0; g_top_w[2*t+1] = w1;
        atomicAdd(&g_cnt[e0], 1);
        atomicAdd(&g_cnt[e1], 1);
    }
}

__global__ void moe_init_kernel() {
    int i = blockIdx.x*blockDim.x + threadIdx.x;
    if (i < NE) { g_cnt[i] = 0; g_fill[i] = 0; }
    if (i < CAP) g_perm[i] = -1;
}

__global__ void segoff_kernel() {
    int off = 0;
    for (int e = 0; e < NE; e++) {
        g_segoff[e] = off;
        off += ((g_cnt[e] + 127) >> 7) << 7;
    }
    g_segoff[NE] = off;
    g_total = off;
}

__global__ void fill_kernel() {
    int i = blockIdx.x*blockDim.x + threadIdx.x;
    if (i >= NT*2) return;
    int e = g_top_e[i];
    int pos = g_segoff[e] + atomicAdd(&g_fill[e], 1);
    g_perm[pos] = i >> 1;
    g_tok_slot[i] = pos;
}

__global__ void silu_kernel() {
    long i = ((long)blockIdx.x*blockDim.x + threadIdx.x) * 4;
    long lim = (long)g_total * FF;
    if (i >= lim) return;
    float4 a = *(float4*)&g_h1[i];
    float4 b = *(float4*)&g_h2[i];
    a.x = a.x / (1.f + __expf(-a.x)) * b.x;
    a.y = a.y / (1.f + __expf(-a.y)) * b.y;
    a.z = a.z / (1.f + __expf(-a.z)) * b.z;
    a.w = a.w / (1.f + __expf(-a.w)) * b.w;
    *(float4*)&g_h1[i] = a;
}

__global__ void combine_kernel(float* __restrict__ out) {
    int i = blockIdx.x*blockDim.x + threadIdx.x;   // float4 index
    int n = i >> 8, d4 = i & 255;
    int s0 = g_tok_slot[2*n], s1 = g_tok_slot[2*n+1];
    float w0 = g_top_w[2*n], w1 = g_top_w[2*n+1];
    float4 hv = *(float4*)&g_hidden[(size_t)n*DM + d4*4];
    float4 y0 = *(float4*)&g_y[(size_t)s0*DM + d4*4];
    float4 y1 = *(float4*)&g_y[(size_t)s1*DM + d4*4];
    float4 r;
    r.x = hv.x + w0*y0.x + w1*y1.x;
    r.y = hv.y + w0*y0.y + w1*y1.y;
    r.z = hv.z + w0*y0.z + w1*y1.z;
    r.w = hv.w + w0*y0.w + w1*y1.w;
    *(float4*)&out[(size_t)n*DM + d4*4] = r;
}

// ---------------- launch ----------------
extern "C" void kernel_launch(void* const* d_in, const int* in_sizes, int n_in,
                              void* d_out, int out_size) {
    const float* hs   = (const float*)d_in[0];
    const float* ln1w = (const float*)d_in[1];
    const float* ln2w = (const float*)d_in[2];
    const float* wqkv = (const float*)d_in[3];
    const float* outw = (const float*)d_in[4];
    const float* rw   = (const float*)d_in[5];
    const float* w1   = (const float*)d_in[6];
    const float* v1   = (const float*)d_in[7];
    const float* w2   = (const float*)d_in[8];
    float* out = (float*)d_out;

    float *px1, *pqkv, *pattn, *phid, *px2, *ph1, *ph2, *py;
    cudaGetSymbolAddress((void**)&px1,  g_x1);
    cudaGetSymbolAddress((void**)&pqkv, g_qkv);
    cudaGetSymbolAddress((void**)&pattn,g_attn);
    cudaGetSymbolAddress((void**)&phid, g_hidden);
    cudaGetSymbolAddress((void**)&px2,  g_x2);
    cudaGetSymbolAddress((void**)&ph1,  g_h1);
    cudaGetSymbolAddress((void**)&ph2,  g_h2);
    cudaGetSymbolAddress((void**)&py,   g_y);

    cudaFuncSetAttribute(flash_attn_kernel,
                         cudaFuncAttributeMaxDynamicSharedMemorySize, FLASH_SMEM);

    // LN1 -> QKV(clip) -> RoPE -> attention -> out-proj(+resid)
    ln_kernel<<<NT, 256>>>(hs, ln1w, px1);
    sgemm128<1,false,false,false><<<dim3(QKVN/128, NT/128), 256>>>(
        px1, wqkv, pqkv, nullptr, NT, QKVN, DM, 0);
    rope_kernel<<<(NT*20*32 + 255)/256, 256>>>();
    flash_attn_kernel<<<dim3(SS/64, BB*NH), 256, FLASH_SMEM>>>(pqkv, pattn);
    sgemm128<2,false,false,false><<<dim3(DM/128, NT/128), 256>>>(
        pattn, outw, phid, hs, NT, DM, DM, 0);

    // LN2 -> router -> top-2 dispatch
    ln_kernel<<<NT, 256>>>(phid, ln2w, px2);
    moe_init_kernel<<<(CAP + 255)/256, 256>>>();
    router_kernel<<<NT/8, 256>>>(px2, rw);
    segoff_kernel<<<1, 1>>>();
    fill_kernel<<<(NT*2 + 255)/256, 256>>>();

    // MoE grouped GEMMs (gathered rows, expert-segmented, padded to 128)
    sgemm128<0,true,true,true><<<dim3(FF/128, CAP/128), 256>>>(
        px2, w1, ph1, nullptr, CAP, FF, DM, (long)FF*DM);
    sgemm128<0,true,true,true><<<dim3(FF/128, CAP/128), 256>>>(
        px2, v1, ph2, nullptr, CAP, FF, DM, (long)FF*DM);
    silu_kernel<<<(CAP*(FF/4) + 255)/256, 256>>>();
    sgemm128<0,false,false,true><<<dim3(DM/128, CAP/128), 256>>>(
        ph1, w2, py, nullptr, CAP, DM, FF, (long)FF*DM);

    // resid2 + gated expert outputs
    combine_kernel<<<NT, 256>>>(out);
}

// round 2
// speedup vs baseline: 1.6935x; 1.6935x over previous
#include <cuda_runtime.h>
#include <math.h>

// ---------------- problem constants ----------------
#define BB 2
#define SS 2048
#define DM 1024
#define NH 16
#define NKV 4
#define HDIM 64
#define NE 8
#define FF 2048
#define NT (BB*SS)                    // 4096 tokens
#define QKVN (DM + 2*NKV*HDIM)        // 1536
#define CAP (2*NT + NE*128)           // 9216 padded MoE slots
#define SCALEQ 0.125f                 // 1/sqrt(64)
#define CLIPV 8.0f

// ---------------- device scratch (no runtime allocation) ----------------
__device__ float g_x1[NT*DM];
__device__ float g_qkv[NT*QKVN];
__device__ float g_attn[NT*DM];
__device__ float g_hidden[NT*DM];
__device__ float g_x2[NT*DM];
__device__ int   g_top_e[NT*2];
__device__ float g_top_w[NT*2];
__device__ int   g_cnt[NE];
__device__ int   g_fill[NE];
__device__ int   g_segoff[NE+1];
__device__ int   g_total;
__device__ int   g_perm[CAP];
__device__ int   g_tok_slot[NT*2];
__device__ float g_h1[CAP*FF];
__device__ float g_h2[CAP*FF];
__device__ float g_y[CAP*DM];

// ---------------- layernorm ----------------
__global__ void ln_kernel(const float* __restrict__ x, const float* __restrict__ w,
                          float* __restrict__ out) {
    int row = blockIdx.x, tid = threadIdx.x;
    float4 v = ((const float4*)(x + (size_t)row*DM))[tid];
    float s = v.x+v.y+v.z+v.w;
    float q = v.x*v.x+v.y*v.y+v.z*v.z+v.w*v.w;
#pragma unroll
    for (int o = 16; o; o >>= 1) {
        s += __shfl_xor_sync(0xffffffffu, s, o);
        q += __shfl_xor_sync(0xffffffffu, q, o);
    }
    __shared__ float ssm[8], qsm[8];
    if ((tid & 31) == 0) { ssm[tid>>5] = s; qsm[tid>>5] = q; }
    __syncthreads();
    float ts = 0.f, tq = 0.f;
#pragma unroll
    for (int i = 0; i < 8; i++) { ts += ssm[i]; tq += qsm[i]; }
    float mu  = ts * (1.f/DM);
    float var = tq * (1.f/DM) - mu*mu;
    float rs  = rsqrtf(var + 1e-5f);
    float4 wv = ((const float4*)w)[tid];
    float4 r;
    r.x = (v.x-mu)*rs*wv.x; r.y = (v.y-mu)*rs*wv.y;
    r.z = (v.z-mu)*rs*wv.z; r.w = (v.w-mu)*rs*wv.w;
    ((float4*)(out + (size_t)row*DM))[tid] = r;
}

// ---------------- tf32 helpers ----------------
__device__ __forceinline__ unsigned f2tf32(float x) {
    unsigned r;
    asm("cvt.rna.tf32.f32 %0, %1;" : "=r"(r) : "f"(x));
    return r;
}
__device__ __forceinline__ void mma_tf32(float* c,
        unsigned a0, unsigned a1, unsigned a2, unsigned a3,
        unsigned b0, unsigned b1) {
    asm volatile("mma.sync.aligned.m16n8k8.row.col.f32.tf32.tf32.f32 "
        "{%0,%1,%2,%3}, {%4,%5,%6,%7}, {%8,%9}, {%0,%1,%2,%3};"
        : "+f"(c[0]), "+f"(c[1]), "+f"(c[2]), "+f"(c[3])
        : "r"(a0), "r"(a1), "r"(a2), "r"(a3), "r"(b0), "r"(b1));
}

// ---------------- tf32 tensor-core GEMM: 128x128x16 tiles, 256 thr ----------------
// EPI: 0 none, 1 clip(+-8), 2 add residual
// GATHER: A rows indirected through g_perm (tok<0 -> zeros)
// BT: B stored [N,K] row-major; else [K,N] row-major
// EXPERT: per-128-row-tile expert select via g_segoff; early exit past g_total
#define TCS 136  // shared K-row stride in words (conflict-free fragment loads)
template<int EPI, bool GATHER, bool BT, bool EXPERT>
__global__ void __launch_bounds__(256, 2)
sgemm_tc(const float* __restrict__ A, const float* __restrict__ Bm,
         float* __restrict__ C, const float* __restrict__ resid,
         int M, int N, int K, long ldbE) {
    int mbase = blockIdx.y * 128;
    if (EXPERT) {
        if (mbase >= g_total) return;
        int e = 0;
#pragma unroll
        for (int i = 0; i < NE; i++) if (g_segoff[i+1] <= mbase) e = i + 1;
        Bm += (size_t)e * ldbE;
    }
    int nbase = blockIdx.x * 128;
    __shared__ unsigned As[16*TCS];
    __shared__ unsigned Bs[16*TCS];
    int tid  = threadIdx.x;
    int lane = tid & 31, warp = tid >> 5;
    int wM = (warp & 1) * 64;        // warp M offset within tile
    int wN = (warp >> 1) * 32;       // warp N offset within tile
    int g  = lane >> 2, tg = lane & 3;

    // A-load assignment: 2 threads/row, 8 floats each
    int ar = tid >> 1, ac = (tid & 1) * 8;
    const float* arow;
    bool avalid = true;
    if (GATHER) {
        int tok = g_perm[mbase + ar];
        avalid = (tok >= 0);
        arow = A + (size_t)(avalid ? tok : 0) * K;
    } else {
        arow = A + (size_t)(mbase + ar) * K;
    }

    float acc[4][4][4];
#pragma unroll
    for (int mi = 0; mi < 4; mi++)
#pragma unroll
        for (int nj = 0; nj < 4; nj++)
#pragma unroll
            for (int r = 0; r < 4; r++) acc[mi][nj][r] = 0.f;

    for (int kb = 0; kb < K; kb += 16) {
        // ---- A -> As[k][m] (tf32) ----
        float4 a0 = make_float4(0.f,0.f,0.f,0.f), a1 = a0;
        if (avalid) {
            a0 = *(const float4*)(arow + kb + ac);
            a1 = *(const float4*)(arow + kb + ac + 4);
        }
        As[(ac+0)*TCS+ar] = f2tf32(a0.x);
        As[(ac+1)*TCS+ar] = f2tf32(a0.y);
        As[(ac+2)*TCS+ar] = f2tf32(a0.z);
        As[(ac+3)*TCS+ar] = f2tf32(a0.w);
        As[(ac+4)*TCS+ar] = f2tf32(a1.x);
        As[(ac+5)*TCS+ar] = f2tf32(a1.y);
        As[(ac+6)*TCS+ar] = f2tf32(a1.z);
        As[(ac+7)*TCS+ar] = f2tf32(a1.w);
        // ---- B -> Bs[k][n] (tf32) ----
        if (!BT) {
#pragma unroll
            for (int q = 0; q < 2; q++) {
                int f4 = tid*2 + q; int k = f4 >> 5; int n4 = f4 & 31;
                float4 bv = *(const float4*)(Bm + (size_t)(kb + k)*N + nbase + n4*4);
                unsigned* dst = &Bs[k*TCS + n4*4];
                dst[0] = f2tf32(bv.x); dst[1] = f2tf32(bv.y);
                dst[2] = f2tf32(bv.z); dst[3] = f2tf32(bv.w);
            }
        } else {
#pragma unroll
            for (int q = 0; q < 2; q++) {
                int f4 = tid*2 + q; int n = f4 >> 2; int k4 = f4 & 3;
                float4 bv = *(const float4*)(Bm + (size_t)(nbase + n)*K + kb + k4*4);
                Bs[(k4*4+0)*TCS + n] = f2tf32(bv.x);
                Bs[(k4*4+1)*TCS + n] = f2tf32(bv.y);
                Bs[(k4*4+2)*TCS + n] = f2tf32(bv.z);
                Bs[(k4*4+3)*TCS + n] = f2tf32(bv.w);
            }
        }
        __syncthreads();
#pragma unroll
        for (int ks = 0; ks < 2; ks++) {
            int k0 = ks * 8;
            unsigned bf[4][2];
#pragma unroll
            for (int nj = 0; nj < 4; nj++) {
                int n = wN + nj*8 + g;
                bf[nj][0] = Bs[(k0+tg)*TCS + n];
                bf[nj][1] = Bs[(k0+tg+4)*TCS + n];
            }
#pragma unroll
            for (int mi = 0; mi < 4; mi++) {
                int m = wM + mi*16 + g;
                unsigned fa0 = As[(k0+tg)*TCS + m];
                unsigned fa1 = As[(k0+tg)*TCS + m + 8];
                unsigned fa2 = As[(k0+tg+4)*TCS + m];
                unsigned fa3 = As[(k0+tg+4)*TCS + m + 8];
#pragma unroll
                for (int nj = 0; nj < 4; nj++)
                    mma_tf32(acc[mi][nj], fa0, fa1, fa2, fa3, bf[nj][0], bf[nj][1]);
            }
        }
        __syncthreads();
    }
    // ---- epilogue ----
#pragma unroll
    for (int mi = 0; mi < 4; mi++) {
#pragma unroll
        for (int nj = 0; nj < 4; nj++) {
            int r0 = mbase + wM + mi*16 + g;
            int r1 = r0 + 8;
            int c  = nbase + wN + nj*8 + tg*2;
            float v0 = acc[mi][nj][0], v1 = acc[mi][nj][1];
            float v2 = acc[mi][nj][2], v3 = acc[mi][nj][3];
            if (EPI == 1) {
                v0 = fminf(fmaxf(v0,-CLIPV),CLIPV); v1 = fminf(fmaxf(v1,-CLIPV),CLIPV);
                v2 = fminf(fmaxf(v2,-CLIPV),CLIPV); v3 = fminf(fmaxf(v3,-CLIPV),CLIPV);
            }
            if (EPI == 2) {
                float2 r0v = *(const float2*)(resid + (size_t)r0*N + c);
                float2 r1v = *(const float2*)(resid + (size_t)r1*N + c);
                v0 += r0v.x; v1 += r0v.y; v2 += r1v.x; v3 += r1v.y;
            }
            *(float2*)(C + (size_t)r0*N + c) = make_float2(v0, v1);
            *(float2*)(C + (size_t)r1*N + c) = make_float2(v2, v3);
        }
    }
}

// ---------------- RoPE in-place on q (16 heads) and k (4 heads) ----------------
__global__ void rope_kernel() {
    int idx = blockIdx.x*blockDim.x + threadIdx.x;
    if (idx >= NT*20*32) return;
    int i    = idx & 31;
    int head = (idx >> 5) % 20;
    int n    = idx / (32*20);
    int s    = n & (SS - 1);
    float inv = (float)pow(10000.0, -(double)i / 32.0);
    float ang = (float)s * inv;
    float sn, cs;
    sincosf(ang, &sn, &cs);
    float* base = g_qkv + (size_t)n*QKVN + (head < NH ? head*HDIM : DM + (head-NH)*HDIM);
    float x1 = base[i], x2 = base[i+32];
    base[i]    = x1*cs - x2*sn;
    base[i+32] = x1*sn + x2*cs;
}

// ---------------- flash attention (causal, GQA rep=4), 64x64 tiles, fp32 ----------------
#define AST 68
#define FLASH_SMEM (4*64*AST*4)
__global__ void flash_attn_kernel(const float* __restrict__ qkv, float* __restrict__ out) {
    extern __shared__ float sm[];
    float* Qs = sm;
    float* Ks = Qs + 64*AST;
    float* Vs = Ks + 64*AST;
    float* Ps = Vs + 64*AST;
    int qt = blockIdx.x, bh = blockIdx.y;
    int b = bh >> 4, h = bh & 15, kh = h >> 2;
    int tid = threadIdx.x, tx = tid & 15, ty = tid >> 4;

    const float* qp = qkv + (size_t)(b*SS + qt*64)*QKVN + h*HDIM;
    for (int t = tid; t < 64*16; t += 256) {
        int r = t >> 4, c4 = t & 15;
        float4 v = *(const float4*)(qp + (size_t)r*QKVN + c4*4);
        v.x *= SCALEQ; v.y *= SCALEQ; v.z *= SCALEQ; v.w *= SCALEQ;
        *(float4*)&Qs[r*AST + c4*4] = v;
    }
    float o[4][4]; float l[4]; float m[4];
#pragma unroll
    for (int i = 0; i < 4; i++) {
        l[i] = 0.f; m[i] = -1e30f;
#pragma unroll
        for (int j = 0; j < 4; j++) o[i][j] = 0.f;
    }
    for (int kt = 0; kt <= qt; kt++) {
        __syncthreads();
        const float* kp = qkv + (size_t)(b*SS + kt*64)*QKVN + DM + kh*HDIM;
        const float* vp = kp + NKV*HDIM;
        for (int t = tid; t < 64*16; t += 256) {
            int r = t >> 4, c4 = t & 15;
            *(float4*)&Ks[r*AST + c4*4] = *(const float4*)(kp + (size_t)r*QKVN + c4*4);
            *(float4*)&Vs[r*AST + c4*4] = *(const float4*)(vp + (size_t)r*QKVN + c4*4);
        }
        __syncthreads();
        float s[4][4];
#pragma unroll
        for (int i = 0; i < 4; i++)
#pragma unroll
            for (int j = 0; j < 4; j++) s[i][j] = 0.f;
#pragma unroll
        for (int d4 = 0; d4 < 16; d4++) {
            float4 qv[4], kv[4];
#pragma unroll
            for (int i = 0; i < 4; i++) qv[i] = *(float4*)&Qs[(ty*4+i)*AST + d4*4];
#pragma unroll
            for (int j = 0; j < 4; j++) kv[j] = *(float4*)&Ks[(tx*4+j)*AST + d4*4];
#pragma unroll
            for (int i = 0; i < 4; i++)
#pragma unroll
                for (int j = 0; j < 4; j++)
                    s[i][j] += qv[i].x*kv[j].x + qv[i].y*kv[j].y + qv[i].z*kv[j].z + qv[i].w*kv[j].w;
        }
        if (kt == qt) {
#pragma unroll
            for (int i = 0; i < 4; i++)
#pragma unroll
                for (int j = 0; j < 4; j++)
                    if (kt*64 + tx*4 + j > qt*64 + ty*4 + i) s[i][j] = -1e30f;
        }
#pragma unroll
        for (int i = 0; i < 4; i++) {
            float mt = fmaxf(fmaxf(s[i][0], s[i][1]), fmaxf(s[i][2], s[i][3]));
#pragma unroll
            for (int off = 8; off; off >>= 1)
                mt = fmaxf(mt, __shfl_xor_sync(0xffffffffu, mt, off));
            float mnew = fmaxf(m[i], mt);
            float corr = __expf(m[i] - mnew);
            l[i] *= corr;
#pragma unroll
            for (int j = 0; j < 4; j++) o[i][j] *= corr;
            float rs = 0.f;
#pragma unroll
            for (int j = 0; j < 4; j++) {
                float p = __expf(s[i][j] - mnew);
                Ps[(ty*4+i)*AST + tx*4 + j] = p;
                rs += p;
            }
#pragma unroll
            for (int off = 8; off; off >>= 1)
                rs += __shfl_xor_sync(0xffffffffu, rs, off);
            l[i] += rs;
            m[i] = mnew;
        }
        __syncthreads();
#pragma unroll 8
        for (int k = 0; k < 64; k++) {
            float4 vv = *(float4*)&Vs[k*AST + tx*4];
#pragma unroll
            for (int i = 0; i < 4; i++) {
                float pr = Ps[(ty*4+i)*AST + k];
                o[i][0] += pr*vv.x; o[i][1] += pr*vv.y;
                o[i][2] += pr*vv.z; o[i][3] += pr*vv.w;
            }
        }
    }
#pragma unroll
    for (int i = 0; i < 4; i++) {
        float invl = 1.f / l[i];
        float4 r = make_float4(o[i][0]*invl, o[i][1]*invl, o[i][2]*invl, o[i][3]*invl);
        *(float4*)(out + (size_t)(b*SS + qt*64 + ty*4 + i)*DM + h*HDIM + tx*4) = r;
    }
}

// ---------------- router: one warp per token ----------------
__global__ void router_kernel(const float* __restrict__ x2, const float* __restrict__ rw) {
    int t = (blockIdx.x*blockDim.x + threadIdx.x) >> 5;
    int lane = threadIdx.x & 31;
    if (t >= NT) return;
    const float* xr = x2 + (size_t)t*DM;
    float acc[NE];
#pragma unroll
    for (int e = 0; e < NE; e++) acc[e] = 0.f;
    for (int d = lane; d < DM; d += 32) {
        float xv = xr[d];
        float4 r0 = ((const float4*)rw)[d*2];
        float4 r1 = ((const float4*)rw)[d*2+1];
        acc[0]+=xv*r0.x; acc[1]+=xv*r0.y; acc[2]+=xv*r0.z; acc[3]+=xv*r0.w;
        acc[4]+=xv*r1.x; acc[5]+=xv*r1.y; acc[6]+=xv*r1.z; acc[7]+=xv*r1.w;
    }
#pragma unroll
    for (int o = 16; o; o >>= 1)
#pragma unroll
        for (int e = 0; e < NE; e++)
            acc[e] += __shfl_xor_sync(0xffffffffu, acc[e], o);
    if (lane == 0) {
        int e0 = 0; float m0 = acc[0];
#pragma unroll
        for (int e = 1; e < NE; e++) if (acc[e] > m0) { m0 = acc[e]; e0 = e; }
        int e1 = -1; float m1 = -3.4e38f;
#pragma unroll
        for (int e = 0; e < NE; e++) if (e != e0 && acc[e] > m1) { m1 = acc[e]; e1 = e; }
        float p1 = expf(m1 - m0);
        float w0 = 1.f / (1.f + p1);
        float w1 = p1 / (1.f + p1);
        g_top_e[2*t] = e0; g_top_e[2*t+1] = e1;
        g_top_w[2*t] = w0; g_top_w[2*t+1] = w1;
        atomicAdd(&g_cnt[e0], 1);
        atomicAdd(&g_cnt[e1], 1);
    }
}

__global__ void moe_init_kernel() {
    int i = blockIdx.x*blockDim.x + threadIdx.x;
    if (i < NE) { g_cnt[i] = 0; g_fill[i] = 0; }
    if (i < CAP) g_perm[i] = -1;
}

__global__ void segoff_kernel() {
    int off = 0;
    for (int e = 0; e < NE; e++) {
        g_segoff[e] = off;
        off += ((g_cnt[e] + 127) >> 7) << 7;
    }
    g_segoff[NE] = off;
    g_total = off;
}

__global__ void fill_kernel() {
    int i = blockIdx.x*blockDim.x + threadIdx.x;
    if (i >= NT*2) return;
    int e = g_top_e[i];
    int pos = g_segoff[e] + atomicAdd(&g_fill[e], 1);
    g_perm[pos] = i >> 1;
    g_tok_slot[i] = pos;
}

__global__ void silu_kernel() {
    long i = ((long)blockIdx.x*blockDim.x + threadIdx.x) * 4;
    long lim = (long)g_total * FF;
    if (i >= lim) return;
    float4 a = *(float4*)&g_h1[i];
    float4 b = *(float4*)&g_h2[i];
    a.x = a.x / (1.f + __expf(-a.x)) * b.x;
    a.y = a.y / (1.f + __expf(-a.y)) * b.y;
    a.z = a.z / (1.f + __expf(-a.z)) * b.z;
    a.w = a.w / (1.f + __expf(-a.w)) * b.w;
    *(float4*)&g_h1[i] = a;
}

__global__ void combine_kernel(float* __restrict__ out) {
    int i = blockIdx.x*blockDim.x + threadIdx.x;   // float4 index
    int n = i >> 8, d4 = i & 255;
    int s0 = g_tok_slot[2*n], s1 = g_tok_slot[2*n+1];
    float w0 = g_top_w[2*n], w1 = g_top_w[2*n+1];
    float4 hv = *(float4*)&g_hidden[(size_t)n*DM + d4*4];
    float4 y0 = *(float4*)&g_y[(size_t)s0*DM + d4*4];
    float4 y1 = *(float4*)&g_y[(size_t)s1*DM + d4*4];
    float4 r;
    r.x = hv.x + w0*y0.x + w1*y1.x;
    r.y = hv.y + w0*y0.y + w1*y1.y;
    r.z = hv.z + w0*y0.z + w1*y1.z;
    r.w = hv.w + w0*y0.w + w1*y1.w;
    *(float4*)&out[(size_t)n*DM + d4*4] = r;
}

// ---------------- launch ----------------
extern "C" void kernel_launch(void* const* d_in, const int* in_sizes, int n_in,
                              void* d_out, int out_size) {
    const float* hs   = (const float*)d_in[0];
    const float* ln1w = (const float*)d_in[1];
    const float* ln2w = (const float*)d_in[2];
    const float* wqkv = (const float*)d_in[3];
    const float* outw = (const float*)d_in[4];
    const float* rw   = (const float*)d_in[5];
    const float* w1   = (const float*)d_in[6];
    const float* v1   = (const float*)d_in[7];
    const float* w2   = (const float*)d_in[8];
    float* out = (float*)d_out;

    float *px1, *pqkv, *pattn, *phid, *px2, *ph1, *ph2, *py;
    cudaGetSymbolAddress((void**)&px1,  g_x1);
    cudaGetSymbolAddress((void**)&pqkv, g_qkv);
    cudaGetSymbolAddress((void**)&pattn,g_attn);
    cudaGetSymbolAddress((void**)&phid, g_hidden);
    cudaGetSymbolAddress((void**)&px2,  g_x2);
    cudaGetSymbolAddress((void**)&ph1,  g_h1);
    cudaGetSymbolAddress((void**)&ph2,  g_h2);
    cudaGetSymbolAddress((void**)&py,   g_y);

    cudaFuncSetAttribute(flash_attn_kernel,
                         cudaFuncAttributeMaxDynamicSharedMemorySize, FLASH_SMEM);

    // LN1 -> QKV(clip) -> RoPE -> attention -> out-proj(+resid)
    ln_kernel<<<NT, 256>>>(hs, ln1w, px1);
    sgemm_tc<1,false,false,false><<<dim3(QKVN/128, NT/128), 256>>>(
        px1, wqkv, pqkv, nullptr, NT, QKVN, DM, 0);
    rope_kernel<<<(NT*20*32 + 255)/256, 256>>>();
    flash_attn_kernel<<<dim3(SS/64, BB*NH), 256, FLASH_SMEM>>>(pqkv, pattn);
    sgemm_tc<2,false,false,false><<<dim3(DM/128, NT/128), 256>>>(
        pattn, outw, phid, hs, NT, DM, DM, 0);

    // LN2 -> router -> top-2 dispatch
    ln_kernel<<<NT, 256>>>(phid, ln2w, px2);
    moe_init_kernel<<<(CAP + 255)/256, 256>>>();
    router_kernel<<<NT/8, 256>>>(px2, rw);
    segoff_kernel<<<1, 1>>>();
    fill_kernel<<<(NT*2 + 255)/256, 256>>>();

    // MoE grouped GEMMs (gathered rows, expert-segmented, padded to 128)
    sgemm_tc<0,true,true,true><<<dim3(FF/128, CAP/128), 256>>>(
        px2, w1, ph1, nullptr, CAP, FF, DM, (long)FF*DM);
    sgemm_tc<0,true,true,true><<<dim3(FF/128, CAP/128), 256>>>(
        px2, v1, ph2, nullptr, CAP, FF, DM, (long)FF*DM);
    silu_kernel<<<(CAP*(FF/4) + 255)/256, 256>>>();
    sgemm_tc<0,false,false,true><<<dim3(DM/128, CAP/128), 256>>>(
        ph1, w2, py, nullptr, CAP, DM, FF, (long)FF*DM);

    // resid2 + gated expert outputs
    combine_kernel<<<NT, 256>>>(out);
}

// round 3
// speedup vs baseline: 2.2402x; 1.3228x over previous
#include <cuda_runtime.h>
#include <math.h>

// ---------------- problem constants ----------------
#define BB 2
#define SS 2048
#define DM 1024
#define NH 16
#define NKV 4
#define HDIM 64
#define NE 8
#define FF 2048
#define NT (BB*SS)                    // 4096 tokens
#define QKVN (DM + 2*NKV*HDIM)        // 1536
#define CAP (2*NT + NE*128)           // 9216 padded MoE slots
#define SCALEQ 0.125f                 // 1/sqrt(64)
#define CLIPV 8.0f

// ---------------- device scratch (no runtime allocation) ----------------
__device__ float g_x1[NT*DM];
__device__ float g_qkv[NT*QKVN];
__device__ float g_attn[NT*DM];
__device__ float g_hidden[NT*DM];
__device__ float g_x2[NT*DM];
__device__ int   g_top_e[NT*2];
__device__ float g_top_w[NT*2];
__device__ int   g_cnt[NE];
__device__ int   g_fill[NE];
__device__ int   g_segoff[NE+1];
__device__ int   g_total;
__device__ int   g_perm[CAP];
__device__ int   g_tok_slot[NT*2];
__device__ float g_h1[CAP*FF];
__device__ float g_h2[CAP*FF];
__device__ float g_y[CAP*DM];

// ---------------- layernorm ----------------
__global__ void ln_kernel(const float* __restrict__ x, const float* __restrict__ w,
                          float* __restrict__ out) {
    int row = blockIdx.x, tid = threadIdx.x;
    float4 v = ((const float4*)(x + (size_t)row*DM))[tid];
    float s = v.x+v.y+v.z+v.w;
    float q = v.x*v.x+v.y*v.y+v.z*v.z+v.w*v.w;
#pragma unroll
    for (int o = 16; o; o >>= 1) {
        s += __shfl_xor_sync(0xffffffffu, s, o);
        q += __shfl_xor_sync(0xffffffffu, q, o);
    }
    __shared__ float ssm[8], qsm[8];
    if ((tid & 31) == 0) { ssm[tid>>5] = s; qsm[tid>>5] = q; }
    __syncthreads();
    float ts = 0.f, tq = 0.f;
#pragma unroll
    for (int i = 0; i < 8; i++) { ts += ssm[i]; tq += qsm[i]; }
    float mu  = ts * (1.f/DM);
    float var = tq * (1.f/DM) - mu*mu;
    float rs  = rsqrtf(var + 1e-5f);
    float4 wv = ((const float4*)w)[tid];
    float4 r;
    r.x = (v.x-mu)*rs*wv.x; r.y = (v.y-mu)*rs*wv.y;
    r.z = (v.z-mu)*rs*wv.z; r.w = (v.w-mu)*rs*wv.w;
    ((float4*)(out + (size_t)row*DM))[tid] = r;
}

// ---------------- tf32 helpers ----------------
__device__ __forceinline__ unsigned f2tf32(float x) {
    unsigned r;
    asm("cvt.rna.tf32.f32 %0, %1;" : "=r"(r) : "f"(x));
    return r;
}
__device__ __forceinline__ void mma_tf32(float* c,
        unsigned a0, unsigned a1, unsigned a2, unsigned a3,
        unsigned b0, unsigned b1) {
    asm volatile("mma.sync.aligned.m16n8k8.row.col.f32.tf32.tf32.f32 "
        "{%0,%1,%2,%3}, {%4,%5,%6,%7}, {%8,%9}, {%0,%1,%2,%3};"
        : "+f"(c[0]), "+f"(c[1]), "+f"(c[2]), "+f"(c[3])
        : "r"(a0), "r"(a1), "r"(a2), "r"(a3), "r"(b0), "r"(b1));
}

// ---------------- tf32 tensor-core GEMM: 128x128x16 tiles, 256 thr ----------------
#define TCS 136
template<int EPI, bool GATHER, bool BT, bool EXPERT>
__global__ void __launch_bounds__(256, 2)
sgemm_tc(const float* __restrict__ A, const float* __restrict__ Bm,
         float* __restrict__ C, const float* __restrict__ resid,
         int M, int N, int K, long ldbE) {
    int mbase = blockIdx.y * 128;
    if (EXPERT) {
        if (mbase >= g_total) return;
        int e = 0;
#pragma unroll
        for (int i = 0; i < NE; i++) if (g_segoff[i+1] <= mbase) e = i + 1;
        Bm += (size_t)e * ldbE;
    }
    int nbase = blockIdx.x * 128;
    __shared__ unsigned As[16*TCS];
    __shared__ unsigned Bs[16*TCS];
    int tid  = threadIdx.x;
    int lane = tid & 31, warp = tid >> 5;
    int wM = (warp & 1) * 64;
    int wN = (warp >> 1) * 32;
    int g  = lane >> 2, tg = lane & 3;

    int ar = tid >> 1, ac = (tid & 1) * 8;
    const float* arow;
    bool avalid = true;
    if (GATHER) {
        int tok = g_perm[mbase + ar];
        avalid = (tok >= 0);
        arow = A + (size_t)(avalid ? tok : 0) * K;
    } else {
        arow = A + (size_t)(mbase + ar) * K;
    }

    float acc[4][4][4];
#pragma unroll
    for (int mi = 0; mi < 4; mi++)
#pragma unroll
        for (int nj = 0; nj < 4; nj++)
#pragma unroll
            for (int r = 0; r < 4; r++) acc[mi][nj][r] = 0.f;

    for (int kb = 0; kb < K; kb += 16) {
        float4 a0 = make_float4(0.f,0.f,0.f,0.f), a1 = a0;
        if (avalid) {
            a0 = *(const float4*)(arow + kb + ac);
            a1 = *(const float4*)(arow + kb + ac + 4);
        }
        As[(ac+0)*TCS+ar] = f2tf32(a0.x);
        As[(ac+1)*TCS+ar] = f2tf32(a0.y);
        As[(ac+2)*TCS+ar] = f2tf32(a0.z);
        As[(ac+3)*TCS+ar] = f2tf32(a0.w);
        As[(ac+4)*TCS+ar] = f2tf32(a1.x);
        As[(ac+5)*TCS+ar] = f2tf32(a1.y);
        As[(ac+6)*TCS+ar] = f2tf32(a1.z);
        As[(ac+7)*TCS+ar] = f2tf32(a1.w);
        if (!BT) {
#pragma unroll
            for (int q = 0; q < 2; q++) {
                int f4 = tid*2 + q; int k = f4 >> 5; int n4 = f4 & 31;
                float4 bv = *(const float4*)(Bm + (size_t)(kb + k)*N + nbase + n4*4);
                unsigned* dst = &Bs[k*TCS + n4*4];
                dst[0] = f2tf32(bv.x); dst[1] = f2tf32(bv.y);
                dst[2] = f2tf32(bv.z); dst[3] = f2tf32(bv.w);
            }
        } else {
#pragma unroll
            for (int q = 0; q < 2; q++) {
                int f4 = tid*2 + q; int n = f4 >> 2; int k4 = f4 & 3;
                float4 bv = *(const float4*)(Bm + (size_t)(nbase + n)*K + kb + k4*4);
                Bs[(k4*4+0)*TCS + n] = f2tf32(bv.x);
                Bs[(k4*4+1)*TCS + n] = f2tf32(bv.y);
                Bs[(k4*4+2)*TCS + n] = f2tf32(bv.z);
                Bs[(k4*4+3)*TCS + n] = f2tf32(bv.w);
            }
        }
        __syncthreads();
#pragma unroll
        for (int ks = 0; ks < 2; ks++) {
            int k0 = ks * 8;
            unsigned bf[4][2];
#pragma unroll
            for (int nj = 0; nj < 4; nj++) {
                int n = wN + nj*8 + g;
                bf[nj][0] = Bs[(k0+tg)*TCS + n];
                bf[nj][1] = Bs[(k0+tg+4)*TCS + n];
            }
#pragma unroll
            for (int mi = 0; mi < 4; mi++) {
                int m = wM + mi*16 + g;
                unsigned fa0 = As[(k0+tg)*TCS + m];
                unsigned fa1 = As[(k0+tg)*TCS + m + 8];
                unsigned fa2 = As[(k0+tg+4)*TCS + m];
                unsigned fa3 = As[(k0+tg+4)*TCS + m + 8];
#pragma unroll
                for (int nj = 0; nj < 4; nj++)
                    mma_tf32(acc[mi][nj], fa0, fa1, fa2, fa3, bf[nj][0], bf[nj][1]);
            }
        }
        __syncthreads();
    }
#pragma unroll
    for (int mi = 0; mi < 4; mi++) {
#pragma unroll
        for (int nj = 0; nj < 4; nj++) {
            int r0 = mbase + wM + mi*16 + g;
            int r1 = r0 + 8;
            int c  = nbase + wN + nj*8 + tg*2;
            float v0 = acc[mi][nj][0], v1 = acc[mi][nj][1];
            float v2 = acc[mi][nj][2], v3 = acc[mi][nj][3];
            if (EPI == 1) {
                v0 = fminf(fmaxf(v0,-CLIPV),CLIPV); v1 = fminf(fmaxf(v1,-CLIPV),CLIPV);
                v2 = fminf(fmaxf(v2,-CLIPV),CLIPV); v3 = fminf(fmaxf(v3,-CLIPV),CLIPV);
            }
            if (EPI == 2) {
                float2 r0v = *(const float2*)(resid + (size_t)r0*N + c);
                float2 r1v = *(const float2*)(resid + (size_t)r1*N + c);
                v0 += r0v.x; v1 += r0v.y; v2 += r1v.x; v3 += r1v.y;
            }
            *(float2*)(C + (size_t)r0*N + c) = make_float2(v0, v1);
            *(float2*)(C + (size_t)r1*N + c) = make_float2(v2, v3);
        }
    }
}

// ---------------- RoPE ----------------
__global__ void rope_kernel() {
    int idx = blockIdx.x*blockDim.x + threadIdx.x;
    if (idx >= NT*20*32) return;
    int i    = idx & 31;
    int head = (idx >> 5) % 20;
    int n    = idx / (32*20);
    int s    = n & (SS - 1);
    float inv = (float)pow(10000.0, -(double)i / 32.0);
    float ang = (float)s * inv;
    float sn, cs;
    sincosf(ang, &sn, &cs);
    float* base = g_qkv + (size_t)n*QKVN + (head < NH ? head*HDIM : DM + (head-NH)*HDIM);
    float x1 = base[i], x2 = base[i+32];
    base[i]    = x1*cs - x2*sn;
    base[i+32] = x1*sn + x2*cs;
}

// ---------------- tensor-core flash attention ----------------
// 128 q-rows/block, 64-kv tiles, 8 warps x 16 rows, tf32 mma, fp32 softmax.
#define FQ 128
#define FKT 64
#define FST 68
#define FLASH_SMEM ((FQ*FST + FKT*FST + FKT*FST + FQ*FST)*4)  // 104448 B
__global__ void __launch_bounds__(256)
flash_tc_kernel(const float* __restrict__ qkv, float* __restrict__ out) {
    extern __shared__ unsigned sm[];
    unsigned* Qs = sm;
    unsigned* Ks = Qs + FQ*FST;
    unsigned* Vs = Ks + FKT*FST;
    unsigned* Ps = Vs + FKT*FST;
    int qb = gridDim.x - 1 - blockIdx.x;      // heavy diagonal first
    int bh = blockIdx.y;
    int b = bh >> 4, h = bh & 15, kh = h >> 2;
    int tid = threadIdx.x, lane = tid & 31, warp = tid >> 5;
    int g = lane >> 2, tg = lane & 3;

    // Q tile (scaled, tf32)
    const float* qp = qkv + (size_t)(b*SS + qb*FQ)*QKVN + h*HDIM;
    for (int t = tid; t < FQ*16; t += 256) {
        int r = t >> 4, c4 = (t & 15)*4;
        float4 v = *(const float4*)(qp + (size_t)r*QKVN + c4);
        unsigned* d = &Qs[r*FST + c4];
        d[0] = f2tf32(v.x*SCALEQ); d[1] = f2tf32(v.y*SCALEQ);
        d[2] = f2tf32(v.z*SCALEQ); d[3] = f2tf32(v.w*SCALEQ);
    }

    int wrow = warp*16;
    int grow = qb*FQ + wrow;      // warp's first global row

    float m0 = -1e30f, m1 = -1e30f, l0 = 0.f, l1 = 0.f;
    float o[8][4];
#pragma unroll
    for (int nj = 0; nj < 8; nj++)
#pragma unroll
        for (int r = 0; r < 4; r++) o[nj][r] = 0.f;

    int ktmax = 2*qb + 1;
    for (int kt = 0; kt <= ktmax; kt++) {
        __syncthreads();   // prior PV reads done before K/V overwrite
        const float* kp = qkv + (size_t)(b*SS + kt*FKT)*QKVN + DM + kh*HDIM;
        const float* vp = kp + NKV*HDIM;
        for (int t = tid; t < FKT*16; t += 256) {
            int r = t >> 4, c4 = (t & 15)*4;
            float4 k4 = *(const float4*)(kp + (size_t)r*QKVN + c4);
            float4 v4 = *(const float4*)(vp + (size_t)r*QKVN + c4);
            unsigned* dk = &Ks[r*FST + c4];
            dk[0]=f2tf32(k4.x); dk[1]=f2tf32(k4.y); dk[2]=f2tf32(k4.z); dk[3]=f2tf32(k4.w);
            unsigned* dv = &Vs[r*FST + c4];
            dv[0]=f2tf32(v4.x); dv[1]=f2tf32(v4.y); dv[2]=f2tf32(v4.z); dv[3]=f2tf32(v4.w);
        }
        __syncthreads();

        if (kt*FKT > grow + 15) continue;   // tile fully above diagonal for this warp

        // ---- S = Q K^T (16 x 64 per warp) ----
        float s[8][4];
#pragma unroll
        for (int nj = 0; nj < 8; nj++)
#pragma unroll
            for (int r = 0; r < 4; r++) s[nj][r] = 0.f;
#pragma unroll
        for (int k0 = 0; k0 < HDIM; k0 += 8) {
            unsigned a0 = Qs[(wrow+g  )*FST + k0+tg];
            unsigned a1 = Qs[(wrow+g+8)*FST + k0+tg];
            unsigned a2 = Qs[(wrow+g  )*FST + k0+tg+4];
            unsigned a3 = Qs[(wrow+g+8)*FST + k0+tg+4];
#pragma unroll
            for (int nj = 0; nj < 8; nj++) {
                unsigned b0 = Ks[(nj*8+g)*FST + k0+tg];
                unsigned b1 = Ks[(nj*8+g)*FST + k0+tg+4];
                mma_tf32(s[nj], a0, a1, a2, a3, b0, b1);
            }
        }
        // ---- causal mask (only straddling tiles) ----
        if (kt >= 2*qb) {
            int r0 = grow + g, r1 = grow + g + 8;
#pragma unroll
            for (int nj = 0; nj < 8; nj++) {
                int c = kt*FKT + nj*8 + 2*tg;
                if (c     > r0) s[nj][0] = -1e30f;
                if (c + 1 > r0) s[nj][1] = -1e30f;
                if (c     > r1) s[nj][2] = -1e30f;
                if (c + 1 > r1) s[nj][3] = -1e30f;
            }
        }
        // ---- online softmax (rows g and g+8) ----
        float mt0 = -1e30f, mt1 = -1e30f;
#pragma unroll
        for (int nj = 0; nj < 8; nj++) {
            mt0 = fmaxf(mt0, fmaxf(s[nj][0], s[nj][1]));
            mt1 = fmaxf(mt1, fmaxf(s[nj][2], s[nj][3]));
        }
        mt0 = fmaxf(mt0, __shfl_xor_sync(0xffffffffu, mt0, 1));
        mt0 = fmaxf(mt0, __shfl_xor_sync(0xffffffffu, mt0, 2));
        mt1 = fmaxf(mt1, __shfl_xor_sync(0xffffffffu, mt1, 1));
        mt1 = fmaxf(mt1, __shfl_xor_sync(0xffffffffu, mt1, 2));
        float mn0 = fmaxf(m0, mt0), mn1 = fmaxf(m1, mt1);
        float c0 = __expf(m0 - mn0), c1 = __expf(m1 - mn1);
        l0 *= c0; l1 *= c1;
#pragma unroll
        for (int nj = 0; nj < 8; nj++) {
            o[nj][0] *= c0; o[nj][1] *= c0;
            o[nj][2] *= c1; o[nj][3] *= c1;
        }
        float rs0 = 0.f, rs1 = 0.f;
#pragma unroll
        for (int nj = 0; nj < 8; nj++) {
            float p0 = __expf(s[nj][0] - mn0);
            float p1 = __expf(s[nj][1] - mn0);
            float p2 = __expf(s[nj][2] - mn1);
            float p3 = __expf(s[nj][3] - mn1);
            rs0 += p0 + p1; rs1 += p2 + p3;
            int col = nj*8 + 2*tg;
            *(uint2*)&Ps[(wrow+g  )*FST + col] = make_uint2(f2tf32(p0), f2tf32(p1));
            *(uint2*)&Ps[(wrow+g+8)*FST + col] = make_uint2(f2tf32(p2), f2tf32(p3));
        }
        rs0 += __shfl_xor_sync(0xffffffffu, rs0, 1);
        rs0 += __shfl_xor_sync(0xffffffffu, rs0, 2);
        rs1 += __shfl_xor_sync(0xffffffffu, rs1, 1);
        rs1 += __shfl_xor_sync(0xffffffffu, rs1, 2);
        l0 += rs0; l1 += rs1;
        m0 = mn0; m1 = mn1;

        __syncwarp();   // warp reads back only its own P rows
        // ---- O += P V (16 x 64 per warp) ----
#pragma unroll
        for (int k0 = 0; k0 < FKT; k0 += 8) {
            unsigned a0 = Ps[(wrow+g  )*FST + k0+tg];
            unsigned a1 = Ps[(wrow+g+8)*FST + k0+tg];
            unsigned a2 = Ps[(wrow+g  )*FST + k0+tg+4];
            unsigned a3 = Ps[(wrow+g+8)*FST + k0+tg+4];
#pragma unroll
            for (int nj = 0; nj < 8; nj++) {
                unsigned b0 = Vs[(k0+tg  )*FST + nj*8+g];
                unsigned b1 = Vs[(k0+tg+4)*FST + nj*8+g];
                mma_tf32(o[nj], a0, a1, a2, a3, b0, b1);
            }
        }
    }
    // ---- epilogue ----
    float il0 = 1.f/l0, il1 = 1.f/l1;
    size_t tok0 = (size_t)(b*SS + qb*FQ + wrow + g);
    size_t tok1 = tok0 + 8;
#pragma unroll
    for (int nj = 0; nj < 8; nj++) {
        int col = h*HDIM + nj*8 + 2*tg;
        *(float2*)(out + tok0*DM + col) = make_float2(o[nj][0]*il0, o[nj][1]*il0);
        *(float2*)(out + tok1*DM + col) = make_float2(o[nj][2]*il1, o[nj][3]*il1);
    }
}

// ---------------- router ----------------
__global__ void router_kernel(const float* __restrict__ x2, const float* __restrict__ rw) {
    int t = (blockIdx.x*blockDim.x + threadIdx.x) >> 5;
    int lane = threadIdx.x & 31;
    if (t >= NT) return;
    const float* xr = x2 + (size_t)t*DM;
    float acc[NE];
#pragma unroll
    for (int e = 0; e < NE; e++) acc[e] = 0.f;
    for (int d = lane; d < DM; d += 32) {
        float xv = xr[d];
        float4 r0 = ((const float4*)rw)[d*2];
        float4 r1 = ((const float4*)rw)[d*2+1];
        acc[0]+=xv*r0.x; acc[1]+=xv*r0.y; acc[2]+=xv*r0.z; acc[3]+=xv*r0.w;
        acc[4]+=xv*r1.x; acc[5]+=xv*r1.y; acc[6]+=xv*r1.z; acc[7]+=xv*r1.w;
    }
#pragma unroll
    for (int o = 16; o; o >>= 1)
#pragma unroll
        for (int e = 0; e < NE; e++)
            acc[e] += __shfl_xor_sync(0xffffffffu, acc[e], o);
    if (lane == 0) {
        int e0 = 0; float m0 = acc[0];
#pragma unroll
        for (int e = 1; e < NE; e++) if (acc[e] > m0) { m0 = acc[e]; e0 = e; }
        int e1 = -1; float m1 = -3.4e38f;
#pragma unroll
        for (int e = 0; e < NE; e++) if (e != e0 && acc[e] > m1) { m1 = acc[e]; e1 = e; }
        float p1 = expf(m1 - m0);
        float w0 = 1.f / (1.f + p1);
        float w1 = p1 / (1.f + p1);
        g_top_e[2*t] = e0; g_top_e[2*t+1] = e1;
        g_top_w[2*t] = w0; g_top_w[2*t+1] = w1;
        atomicAdd(&g_cnt[e0], 1);
        atomicAdd(&g_cnt[e1], 1);
    }
}

__global__ void moe_init_kernel() {
    int i = blockIdx.x*blockDim.x + threadIdx.x;
    if (i < NE) { g_cnt[i] = 0; g_fill[i] = 0; }
    if (i < CAP) g_perm[i] = -1;
}

__global__ void segoff_kernel() {
    int off = 0;
    for (int e = 0; e < NE; e++) {
        g_segoff[e] = off;
        off += ((g_cnt[e] + 127) >> 7) << 7;
    }
    g_segoff[NE] = off;
    g_total = off;
}

__global__ void fill_kernel() {
    int i = blockIdx.x*blockDim.x + threadIdx.x;
    if (i >= NT*2) return;
    int e = g_top_e[i];
    int pos = g_segoff[e] + atomicAdd(&g_fill[e], 1);
    g_perm[pos] = i >> 1;
    g_tok_slot[i] = pos;
}

__global__ void silu_kernel() {
    long i = ((long)blockIdx.x*blockDim.x + threadIdx.x) * 4;
    long lim = (long)g_total * FF;
    if (i >= lim) return;
    float4 a = *(float4*)&g_h1[i];
    float4 b = *(float4*)&g_h2[i];
    a.x = a.x / (1.f + __expf(-a.x)) * b.x;
    a.y = a.y / (1.f + __expf(-a.y)) * b.y;
    a.z = a.z / (1.f + __expf(-a.z)) * b.z;
    a.w = a.w / (1.f + __expf(-a.w)) * b.w;
    *(float4*)&g_h1[i] = a;
}

__global__ void combine_kernel(float* __restrict__ out) {
    int i = blockIdx.x*blockDim.x + threadIdx.x;
    int n = i >> 8, d4 = i & 255;
    int s0 = g_tok_slot[2*n], s1 = g_tok_slot[2*n+1];
    float w0 = g_top_w[2*n], w1 = g_top_w[2*n+1];
    float4 hv = *(float4*)&g_hidden[(size_t)n*DM + d4*4];
    float4 y0 = *(float4*)&g_y[(size_t)s0*DM + d4*4];
    float4 y1 = *(float4*)&g_y[(size_t)s1*DM + d4*4];
    float4 r;
    r.x = hv.x + w0*y0.x + w1*y1.x;
    r.y = hv.y + w0*y0.y + w1*y1.y;
    r.z = hv.z + w0*y0.z + w1*y1.z;
    r.w = hv.w + w0*y0.w + w1*y1.w;
    *(float4*)&out[(size_t)n*DM + d4*4] = r;
}

// ---------------- launch ----------------
extern "C" void kernel_launch(void* const* d_in, const int* in_sizes, int n_in,
                              void* d_out, int out_size) {
    const float* hs   = (const float*)d_in[0];
    const float* ln1w = (const float*)d_in[1];
    const float* ln2w = (const float*)d_in[2];
    const float* wqkv = (const float*)d_in[3];
    const float* outw = (const float*)d_in[4];
    const float* rw   = (const float*)d_in[5];
    const float* w1   = (const float*)d_in[6];
    const float* v1   = (const float*)d_in[7];
    const float* w2   = (const float*)d_in[8];
    float* out = (float*)d_out;

    float *px1, *pqkv, *pattn, *phid, *px2, *ph1, *ph2, *py;
    cudaGetSymbolAddress((void**)&px1,  g_x1);
    cudaGetSymbolAddress((void**)&pqkv, g_qkv);
    cudaGetSymbolAddress((void**)&pattn,g_attn);
    cudaGetSymbolAddress((void**)&phid, g_hidden);
    cudaGetSymbolAddress((void**)&px2,  g_x2);
    cudaGetSymbolAddress((void**)&ph1,  g_h1);
    cudaGetSymbolAddress((void**)&ph2,  g_h2);
    cudaGetSymbolAddress((void**)&py,   g_y);

    cudaFuncSetAttribute(flash_tc_kernel,
                         cudaFuncAttributeMaxDynamicSharedMemorySize, FLASH_SMEM);

    // LN1 -> QKV(clip) -> RoPE -> attention -> out-proj(+resid)
    ln_kernel<<<NT, 256>>>(hs, ln1w, px1);
    sgemm_tc<1,false,false,false><<<dim3(QKVN/128, NT/128), 256>>>(
        px1, wqkv, pqkv, nullptr, NT, QKVN, DM, 0);
    rope_kernel<<<(NT*20*32 + 255)/256, 256>>>();
    flash_tc_kernel<<<dim3(SS/FQ, BB*NH), 256, FLASH_SMEM>>>(pqkv, pattn);
    sgemm_tc<2,false,false,false><<<dim3(DM/128, NT/128), 256>>>(
        pattn, outw, phid, hs, NT, DM, DM, 0);

    // LN2 -> router -> top-2 dispatch
    ln_kernel<<<NT, 256>>>(phid, ln2w, px2);
    moe_init_kernel<<<(CAP + 255)/256, 256>>>();
    router_kernel<<<NT/8, 256>>>(px2, rw);
    segoff_kernel<<<1, 1>>>();
    fill_kernel<<<(NT*2 + 255)/256, 256>>>();

    // MoE grouped GEMMs
    sgemm_tc<0,true,true,true><<<dim3(FF/128, CAP/128), 256>>>(
        px2, w1, ph1, nullptr, CAP, FF, DM, (long)FF*DM);
    sgemm_tc<0,true,true,true><<<dim3(FF/128, CAP/128), 256>>>(
        px2, v1, ph2, nullptr, CAP, FF, DM, (long)FF*DM);
    silu_kernel<<<(CAP*(FF/4) + 255)/256, 256>>>();
    sgemm_tc<0,false,false,true><<<dim3(DM/128, CAP/128), 256>>>(
        ph1, w2, py, nullptr, CAP, DM, FF, (long)FF*DM);

    // resid2 + gated expert outputs
    combine_kernel<<<NT, 256>>>(out);
}

// round 4
// speedup vs baseline: 2.5212x; 1.1254x over previous
#include <cuda_runtime.h>
#include <math.h>

// ---------------- problem constants ----------------
#define BB 2
#define SS 2048
#define DM 1024
#define NH 16
#define NKV 4
#define HDIM 64
#define NE 8
#define FF 2048
#define NT (BB*SS)                    // 4096 tokens
#define QKVN (DM + 2*NKV*HDIM)        // 1536
#define CAP (2*NT + NE*128)           // 9216 padded MoE slots
#define SCALEQ 0.125f                 // 1/sqrt(64)
#define CLIPV 8.0f

// ---------------- device scratch ----------------
__device__ float g_x1[NT*DM];
__device__ float g_qkv[NT*QKVN];
__device__ float g_attn[NT*DM];
__device__ float g_hidden[NT*DM];
__device__ float g_x2[NT*DM];
__device__ int   g_top_e[NT*2];
__device__ float g_top_w[NT*2];
__device__ int   g_cnt[NE];
__device__ int   g_fill[NE];
__device__ int   g_segoff[NE+1];
__device__ int   g_total;
__device__ int   g_perm[CAP];
__device__ int   g_tok_slot[NT*2];
__device__ float g_h1[CAP*FF];
__device__ float g_h2[CAP*FF];
__device__ float g_y[CAP*DM];

// ---------------- layernorm ----------------
__global__ void ln_kernel(const float* __restrict__ x, const float* __restrict__ w,
                          float* __restrict__ out) {
    int row = blockIdx.x, tid = threadIdx.x;
    float4 v = ((const float4*)(x + (size_t)row*DM))[tid];
    float s = v.x+v.y+v.z+v.w;
    float q = v.x*v.x+v.y*v.y+v.z*v.z+v.w*v.w;
#pragma unroll
    for (int o = 16; o; o >>= 1) {
        s += __shfl_xor_sync(0xffffffffu, s, o);
        q += __shfl_xor_sync(0xffffffffu, q, o);
    }
    __shared__ float ssm[8], qsm[8];
    if ((tid & 31) == 0) { ssm[tid>>5] = s; qsm[tid>>5] = q; }
    __syncthreads();
    float ts = 0.f, tq = 0.f;
#pragma unroll
    for (int i = 0; i < 8; i++) { ts += ssm[i]; tq += qsm[i]; }
    float mu  = ts * (1.f/DM);
    float var = tq * (1.f/DM) - mu*mu;
    float rs  = rsqrtf(var + 1e-5f);
    float4 wv = ((const float4*)w)[tid];
    float4 r;
    r.x = (v.x-mu)*rs*wv.x; r.y = (v.y-mu)*rs*wv.y;
    r.z = (v.z-mu)*rs*wv.z; r.w = (v.w-mu)*rs*wv.w;
    ((float4*)(out + (size_t)row*DM))[tid] = r;
}

// ---------------- tf32 / cp.async helpers ----------------
__device__ __forceinline__ unsigned f2tf32(float x) {
    unsigned r;
    asm("cvt.rna.tf32.f32 %0, %1;" : "=r"(r) : "f"(x));
    return r;
}
__device__ __forceinline__ void mma_tf32(float* c,
        unsigned a0, unsigned a1, unsigned a2, unsigned a3,
        unsigned b0, unsigned b1) {
    asm volatile("mma.sync.aligned.m16n8k8.row.col.f32.tf32.tf32.f32 "
        "{%0,%1,%2,%3}, {%4,%5,%6,%7}, {%8,%9}, {%0,%1,%2,%3};"
        : "+f"(c[0]), "+f"(c[1]), "+f"(c[2]), "+f"(c[3])
        : "r"(a0), "r"(a1), "r"(a2), "r"(a3), "r"(b0), "r"(b1));
}
__device__ __forceinline__ void cp16(float* smem_dst, const float* gsrc, int src_bytes) {
    unsigned sa = (unsigned)__cvta_generic_to_shared(smem_dst);
    asm volatile("cp.async.cg.shared.global [%0], [%1], 16, %2;\n"
                 :: "r"(sa), "l"(gsrc), "r"(src_bytes));
}
#define CP_COMMIT() asm volatile("cp.async.commit_group;\n")
#define CP_WAIT0()  asm volatile("cp.async.wait_group 0;\n")

// ---------------- pipelined tf32 GEMM: 128x128x16 tiles, 2-stage cp.async ----------------
// A in smem [m][k] stride 20; B: BT -> [n][k] stride 20, else [k][n] stride 136.
#define ASTR 20
#define BSTR 136
#define SLAB 2560   // floats per stage per matrix (=128*20 = max(16*136,128*20))
template<int EPI, bool GATHER, bool BT, bool EXPERT>
__global__ void __launch_bounds__(256, 2)
sgemm_tc(const float* __restrict__ A, const float* __restrict__ Bm,
         float* __restrict__ C, const float* __restrict__ resid,
         int M, int N, int K, long ldbE) {
    int mbase = blockIdx.y * 128;
    if (EXPERT) {
        if (mbase >= g_total) return;
        int e = 0;
#pragma unroll
        for (int i = 0; i < NE; i++) if (g_segoff[i+1] <= mbase) e = i + 1;
        Bm += (size_t)e * ldbE;
    }
    int nbase = blockIdx.x * 128;
    __shared__ float As[2][SLAB];
    __shared__ float Bs[2][SLAB];
    int tid  = threadIdx.x;
    int lane = tid & 31, warp = tid >> 5;
    int wM = (warp & 1) * 64;
    int wN = (warp >> 1) * 32;
    int g  = lane >> 2, tg = lane & 3;

    // per-thread copy assignments (fixed across slabs)
    int ar = tid >> 1, ac = (tid & 1) * 8;        // A: row, first col (2x float4)
    const float* arow;
    int asz = 16;
    if (GATHER) {
        int tok = g_perm[mbase + ar];
        asz  = (tok >= 0) ? 16 : 0;
        arow = A + (size_t)(tok >= 0 ? tok : 0) * K;
    } else {
        arow = A + (size_t)(mbase + ar) * K;
    }
    int bk = tid >> 4, bn = (tid & 15) * 8;       // B[k][n] path: k row, first col

    float acc[4][4][4];
#pragma unroll
    for (int mi = 0; mi < 4; mi++)
#pragma unroll
        for (int nj = 0; nj < 4; nj++)
#pragma unroll
            for (int r = 0; r < 4; r++) acc[mi][nj][r] = 0.f;

    // ---- slab copy (stage s, k-offset kb) ----
    auto load_slab = [&](int s, int kb) {
        cp16(&As[s][ar*ASTR + ac],     arow + kb + ac,     asz);
        cp16(&As[s][ar*ASTR + ac + 4], arow + kb + ac + 4, asz);
        if (!BT) {
            const float* bp = Bm + (size_t)(kb + bk)*N + nbase + bn;
            cp16(&Bs[s][bk*BSTR + bn],     bp,     16);
            cp16(&Bs[s][bk*BSTR + bn + 4], bp + 4, 16);
        } else {
            const float* bp = Bm + (size_t)(nbase + ar)*K + kb + ac;
            cp16(&Bs[s][ar*ASTR + ac],     bp,     16);
            cp16(&Bs[s][ar*ASTR + ac + 4], bp + 4, 16);
        }
    };

    load_slab(0, 0);
    CP_COMMIT();

    for (int kb = 0; kb < K; kb += 16) {
        int s = (kb >> 4) & 1;
        CP_WAIT0();
        __syncthreads();
        if (kb + 16 < K) { load_slab(s ^ 1, kb + 16); CP_COMMIT(); }
        const float* as = As[s];
        const float* bs = Bs[s];
#pragma unroll
        for (int ks = 0; ks < 2; ks++) {
            int k0 = ks * 8;
            unsigned bf[4][2];
#pragma unroll
            for (int nj = 0; nj < 4; nj++) {
                int n = wN + nj*8 + g;
                if (!BT) {
                    bf[nj][0] = __float_as_uint(bs[(k0+tg)*BSTR + n]);
                    bf[nj][1] = __float_as_uint(bs[(k0+tg+4)*BSTR + n]);
                } else {
                    bf[nj][0] = __float_as_uint(bs[n*ASTR + k0+tg]);
                    bf[nj][1] = __float_as_uint(bs[n*ASTR + k0+tg+4]);
                }
            }
#pragma unroll
            for (int mi = 0; mi < 4; mi++) {
                int m = wM + mi*16 + g;
                unsigned fa0 = __float_as_uint(as[m*ASTR + k0+tg]);
                unsigned fa1 = __float_as_uint(as[(m+8)*ASTR + k0+tg]);
                unsigned fa2 = __float_as_uint(as[m*ASTR + k0+tg+4]);
                unsigned fa3 = __float_as_uint(as[(m+8)*ASTR + k0+tg+4]);
#pragma unroll
                for (int nj = 0; nj < 4; nj++)
                    mma_tf32(acc[mi][nj], fa0, fa1, fa2, fa3, bf[nj][0], bf[nj][1]);
            }
        }
    }
    // ---- epilogue ----
#pragma unroll
    for (int mi = 0; mi < 4; mi++) {
#pragma unroll
        for (int nj = 0; nj < 4; nj++) {
            int r0 = mbase + wM + mi*16 + g;
            int r1 = r0 + 8;
            int c  = nbase + wN + nj*8 + tg*2;
            float v0 = acc[mi][nj][0], v1 = acc[mi][nj][1];
            float v2 = acc[mi][nj][2], v3 = acc[mi][nj][3];
            if (EPI == 1) {
                v0 = fminf(fmaxf(v0,-CLIPV),CLIPV); v1 = fminf(fmaxf(v1,-CLIPV),CLIPV);
                v2 = fminf(fmaxf(v2,-CLIPV),CLIPV); v3 = fminf(fmaxf(v3,-CLIPV),CLIPV);
            }
            if (EPI == 2) {
                float2 r0v = *(const float2*)(resid + (size_t)r0*N + c);
                float2 r1v = *(const float2*)(resid + (size_t)r1*N + c);
                v0 += r0v.x; v1 += r0v.y; v2 += r1v.x; v3 += r1v.y;
            }
            *(float2*)(C + (size_t)r0*N + c) = make_float2(v0, v1);
            *(float2*)(C + (size_t)r1*N + c) = make_float2(v2, v3);
        }
    }
}

// ---------------- RoPE ----------------
__global__ void rope_kernel() {
    int idx = blockIdx.x*blockDim.x + threadIdx.x;
    if (idx >= NT*20*32) return;
    int i    = idx & 31;
    int head = (idx >> 5) % 20;
    int n    = idx / (32*20);
    int s    = n & (SS - 1);
    float inv = (float)pow(10000.0, -(double)i / 32.0);
    float ang = (float)s * inv;
    float sn, cs;
    sincosf(ang, &sn, &cs);
    float* base = g_qkv + (size_t)n*QKVN + (head < NH ? head*HDIM : DM + (head-NH)*HDIM);
    float x1 = base[i], x2 = base[i+32];
    base[i]    = x1*cs - x2*sn;
    base[i+32] = x1*sn + x2*cs;
}

// ---------------- tensor-core flash attention ----------------
#define FQ 128
#define FKT 64
#define FST 68
#define FLASH_SMEM ((FQ*FST + FKT*FST + FKT*FST + FQ*FST)*4)
__global__ void __launch_bounds__(256)
flash_tc_kernel(const float* __restrict__ qkv, float* __restrict__ out) {
    extern __shared__ unsigned sm[];
    unsigned* Qs = sm;
    unsigned* Ks = Qs + FQ*FST;
    unsigned* Vs = Ks + FKT*FST;
    unsigned* Ps = Vs + FKT*FST;
    int qb = gridDim.x - 1 - blockIdx.x;
    int bh = blockIdx.y;
    int b = bh >> 4, h = bh & 15, kh = h >> 2;
    int tid = threadIdx.x, lane = tid & 31, warp = tid >> 5;
    int g = lane >> 2, tg = lane & 3;

    const float* qp = qkv + (size_t)(b*SS + qb*FQ)*QKVN + h*HDIM;
    for (int t = tid; t < FQ*16; t += 256) {
        int r = t >> 4, c4 = (t & 15)*4;
        float4 v = *(const float4*)(qp + (size_t)r*QKVN + c4);
        unsigned* d = &Qs[r*FST + c4];
        d[0] = f2tf32(v.x*SCALEQ); d[1] = f2tf32(v.y*SCALEQ);
        d[2] = f2tf32(v.z*SCALEQ); d[3] = f2tf32(v.w*SCALEQ);
    }

    int wrow = warp*16;
    int grow = qb*FQ + wrow;

    float m0 = -1e30f, m1 = -1e30f, l0 = 0.f, l1 = 0.f;
    float o[8][4];
#pragma unroll
    for (int nj = 0; nj < 8; nj++)
#pragma unroll
        for (int r = 0; r < 4; r++) o[nj][r] = 0.f;

    int ktmax = 2*qb + 1;
    for (int kt = 0; kt <= ktmax; kt++) {
        __syncthreads();
        const float* kp = qkv + (size_t)(b*SS + kt*FKT)*QKVN + DM + kh*HDIM;
        const float* vp = kp + NKV*HDIM;
        for (int t = tid; t < FKT*16; t += 256) {
            int r = t >> 4, c4 = (t & 15)*4;
            float4 k4 = *(const float4*)(kp + (size_t)r*QKVN + c4);
            float4 v4 = *(const float4*)(vp + (size_t)r*QKVN + c4);
            unsigned* dk = &Ks[r*FST + c4];
            dk[0]=f2tf32(k4.x); dk[1]=f2tf32(k4.y); dk[2]=f2tf32(k4.z); dk[3]=f2tf32(k4.w);
            unsigned* dv = &Vs[r*FST + c4];
            dv[0]=f2tf32(v4.x); dv[1]=f2tf32(v4.y); dv[2]=f2tf32(v4.z); dv[3]=f2tf32(v4.w);
        }
        __syncthreads();

        if (kt*FKT > grow + 15) continue;

        float s[8][4];
#pragma unroll
        for (int nj = 0; nj < 8; nj++)
#pragma unroll
            for (int r = 0; r < 4; r++) s[nj][r] = 0.f;
#pragma unroll
        for (int k0 = 0; k0 < HDIM; k0 += 8) {
            unsigned a0 = Qs[(wrow+g  )*FST + k0+tg];
            unsigned a1 = Qs[(wrow+g+8)*FST + k0+tg];
            unsigned a2 = Qs[(wrow+g  )*FST + k0+tg+4];
            unsigned a3 = Qs[(wrow+g+8)*FST + k0+tg+4];
#pragma unroll
            for (int nj = 0; nj < 8; nj++) {
                unsigned b0 = Ks[(nj*8+g)*FST + k0+tg];
                unsigned b1 = Ks[(nj*8+g)*FST + k0+tg+4];
                mma_tf32(s[nj], a0, a1, a2, a3, b0, b1);
            }
        }
        if (kt >= 2*qb) {
            int r0 = grow + g, r1 = grow + g + 8;
#pragma unroll
            for (int nj = 0; nj < 8; nj++) {
                int c = kt*FKT + nj*8 + 2*tg;
                if (c     > r0) s[nj][0] = -1e30f;
                if (c + 1 > r0) s[nj][1] = -1e30f;
                if (c     > r1) s[nj][2] = -1e30f;
                if (c + 1 > r1) s[nj][3] = -1e30f;
            }
        }
        float mt0 = -1e30f, mt1 = -1e30f;
#pragma unroll
        for (int nj = 0; nj < 8; nj++) {
            mt0 = fmaxf(mt0, fmaxf(s[nj][0], s[nj][1]));
            mt1 = fmaxf(mt1, fmaxf(s[nj][2], s[nj][3]));
        }
        mt0 = fmaxf(mt0, __shfl_xor_sync(0xffffffffu, mt0, 1));
        mt0 = fmaxf(mt0, __shfl_xor_sync(0xffffffffu, mt0, 2));
        mt1 = fmaxf(mt1, __shfl_xor_sync(0xffffffffu, mt1, 1));
        mt1 = fmaxf(mt1, __shfl_xor_sync(0xffffffffu, mt1, 2));
        float mn0 = fmaxf(m0, mt0), mn1 = fmaxf(m1, mt1);
        float c0 = __expf(m0 - mn0), c1 = __expf(m1 - mn1);
        l0 *= c0; l1 *= c1;
#pragma unroll
        for (int nj = 0; nj < 8; nj++) {
            o[nj][0] *= c0; o[nj][1] *= c0;
            o[nj][2] *= c1; o[nj][3] *= c1;
        }
        float rs0 = 0.f, rs1 = 0.f;
#pragma unroll
        for (int nj = 0; nj < 8; nj++) {
            float p0 = __expf(s[nj][0] - mn0);
            float p1 = __expf(s[nj][1] - mn0);
            float p2 = __expf(s[nj][2] - mn1);
            float p3 = __expf(s[nj][3] - mn1);
            rs0 += p0 + p1; rs1 += p2 + p3;
            int col = nj*8 + 2*tg;
            *(uint2*)&Ps[(wrow+g  )*FST + col] = make_uint2(f2tf32(p0), f2tf32(p1));
            *(uint2*)&Ps[(wrow+g+8)*FST + col] = make_uint2(f2tf32(p2), f2tf32(p3));
        }
        rs0 += __shfl_xor_sync(0xffffffffu, rs0, 1);
        rs0 += __shfl_xor_sync(0xffffffffu, rs0, 2);
        rs1 += __shfl_xor_sync(0xffffffffu, rs1, 1);
        rs1 += __shfl_xor_sync(0xffffffffu, rs1, 2);
        l0 += rs0; l1 += rs1;
        m0 = mn0; m1 = mn1;

        __syncwarp();
#pragma unroll
        for (int k0 = 0; k0 < FKT; k0 += 8) {
            unsigned a0 = Ps[(wrow+g  )*FST + k0+tg];
            unsigned a1 = Ps[(wrow+g+8)*FST + k0+tg];
            unsigned a2 = Ps[(wrow+g  )*FST + k0+tg+4];
            unsigned a3 = Ps[(wrow+g+8)*FST + k0+tg+4];
#pragma unroll
            for (int nj = 0; nj < 8; nj++) {
                unsigned b0 = Vs[(k0+tg  )*FST + nj*8+g];
                unsigned b1 = Vs[(k0+tg+4)*FST + nj*8+g];
                mma_tf32(o[nj], a0, a1, a2, a3, b0, b1);
            }
        }
    }
    float il0 = 1.f/l0, il1 = 1.f/l1;
    size_t tok0 = (size_t)(b*SS + qb*FQ + wrow + g);
    size_t tok1 = tok0 + 8;
#pragma unroll
    for (int nj = 0; nj < 8; nj++) {
        int col = h*HDIM + nj*8 + 2*tg;
        *(float2*)(out + tok0*DM + col) = make_float2(o[nj][0]*il0, o[nj][1]*il0);
        *(float2*)(out + tok1*DM + col) = make_float2(o[nj][2]*il1, o[nj][3]*il1);
    }
}

// ---------------- router ----------------
__global__ void router_kernel(const float* __restrict__ x2, const float* __restrict__ rw) {
    int t = (blockIdx.x*blockDim.x + threadIdx.x) >> 5;
    int lane = threadIdx.x & 31;
    if (t >= NT) return;
    const float* xr = x2 + (size_t)t*DM;
    float acc[NE];
#pragma unroll
    for (int e = 0; e < NE; e++) acc[e] = 0.f;
    for (int d = lane; d < DM; d += 32) {
        float xv = xr[d];
        float4 r0 = ((const float4*)rw)[d*2];
        float4 r1 = ((const float4*)rw)[d*2+1];
        acc[0]+=xv*r0.x; acc[1]+=xv*r0.y; acc[2]+=xv*r0.z; acc[3]+=xv*r0.w;
        acc[4]+=xv*r1.x; acc[5]+=xv*r1.y; acc[6]+=xv*r1.z; acc[7]+=xv*r1.w;
    }
#pragma unroll
    for (int o = 16; o; o >>= 1)
#pragma unroll
        for (int e = 0; e < NE; e++)
            acc[e] += __shfl_xor_sync(0xffffffffu, acc[e], o);
    if (lane == 0) {
        int e0 = 0; float m0 = acc[0];
#pragma unroll
        for (int e = 1; e < NE; e++) if (acc[e] > m0) { m0 = acc[e]; e0 = e; }
        int e1 = -1; float m1 = -3.4e38f;
#pragma unroll
        for (int e = 0; e < NE; e++) if (e != e0 && acc[e] > m1) { m1 = acc[e]; e1 = e; }
        float p1 = expf(m1 - m0);
        float w0 = 1.f / (1.f + p1);
        float w1 = p1 / (1.f + p1);
        g_top_e[2*t] = e0; g_top_e[2*t+1] = e1;
        g_top_w[2*t] = w0; g_top_w[2*t+1] = w1;
        atomicAdd(&g_cnt[e0], 1);
        atomicAdd(&g_cnt[e1], 1);
    }
}

__global__ void moe_init_kernel() {
    int i = blockIdx.x*blockDim.x + threadIdx.x;
    if (i < NE) { g_cnt[i] = 0; g_fill[i] = 0; }
    if (i < CAP) g_perm[i] = -1;
}

__global__ void segoff_kernel() {
    int off = 0;
    for (int e = 0; e < NE; e++) {
        g_segoff[e] = off;
        off += ((g_cnt[e] + 127) >> 7) << 7;
    }
    g_segoff[NE] = off;
    g_total = off;
}

__global__ void fill_kernel() {
    int i = blockIdx.x*blockDim.x + threadIdx.x;
    if (i >= NT*2) return;
    int e = g_top_e[i];
    int pos = g_segoff[e] + atomicAdd(&g_fill[e], 1);
    g_perm[pos] = i >> 1;
    g_tok_slot[i] = pos;
}

__global__ void silu_kernel() {
    long i = ((long)blockIdx.x*blockDim.x + threadIdx.x) * 4;
    long lim = (long)g_total * FF;
    if (i >= lim) return;
    float4 a = *(float4*)&g_h1[i];
    float4 b = *(float4*)&g_h2[i];
    a.x = a.x / (1.f + __expf(-a.x)) * b.x;
    a.y = a.y / (1.f + __expf(-a.y)) * b.y;
    a.z = a.z / (1.f + __expf(-a.z)) * b.z;
    a.w = a.w / (1.f + __expf(-a.w)) * b.w;
    *(float4*)&g_h1[i] = a;
}

__global__ void combine_kernel(float* __restrict__ out) {
    int i = blockIdx.x*blockDim.x + threadIdx.x;
    int n = i >> 8, d4 = i & 255;
    int s0 = g_tok_slot[2*n], s1 = g_tok_slot[2*n+1];
    float w0 = g_top_w[2*n], w1 = g_top_w[2*n+1];
    float4 hv = *(float4*)&g_hidden[(size_t)n*DM + d4*4];
    float4 y0 = *(float4*)&g_y[(size_t)s0*DM + d4*4];
    float4 y1 = *(float4*)&g_y[(size_t)s1*DM + d4*4];
    float4 r;
    r.x = hv.x + w0*y0.x + w1*y1.x;
    r.y = hv.y + w0*y0.y + w1*y1.y;
    r.z = hv.z + w0*y0.z + w1*y1.z;
    r.w = hv.w + w0*y0.w + w1*y1.w;
    *(float4*)&out[(size_t)n*DM + d4*4] = r;
}

// ---------------- launch ----------------
extern "C" void kernel_launch(void* const* d_in, const int* in_sizes, int n_in,
                              void* d_out, int out_size) {
    const float* hs   = (const float*)d_in[0];
    const float* ln1w = (const float*)d_in[1];
    const float* ln2w = (const float*)d_in[2];
    const float* wqkv = (const float*)d_in[3];
    const float* outw = (const float*)d_in[4];
    const float* rw   = (const float*)d_in[5];
    const float* w1   = (const float*)d_in[6];
    const float* v1   = (const float*)d_in[7];
    const float* w2   = (const float*)d_in[8];
    float* out = (float*)d_out;

    float *px1, *pqkv, *pattn, *phid, *px2, *ph1, *ph2, *py;
    cudaGetSymbolAddress((void**)&px1,  g_x1);
    cudaGetSymbolAddress((void**)&pqkv, g_qkv);
    cudaGetSymbolAddress((void**)&pattn,g_attn);
    cudaGetSymbolAddress((void**)&phid, g_hidden);
    cudaGetSymbolAddress((void**)&px2,  g_x2);
    cudaGetSymbolAddress((void**)&ph1,  g_h1);
    cudaGetSymbolAddress((void**)&ph2,  g_h2);
    cudaGetSymbolAddress((void**)&py,   g_y);

    cudaFuncSetAttribute(flash_tc_kernel,
                         cudaFuncAttributeMaxDynamicSharedMemorySize, FLASH_SMEM);

    // LN1 -> QKV(clip) -> RoPE -> attention -> out-proj(+resid)
    ln_kernel<<<NT, 256>>>(hs, ln1w, px1);
    sgemm_tc<1,false,false,false><<<dim3(QKVN/128, NT/128), 256>>>(
        px1, wqkv, pqkv, nullptr, NT, QKVN, DM, 0);
    rope_kernel<<<(NT*20*32 + 255)/256, 256>>>();
    flash_tc_kernel<<<dim3(SS/FQ, BB*NH), 256, FLASH_SMEM>>>(pqkv, pattn);
    sgemm_tc<2,false,false,false><<<dim3(DM/128, NT/128), 256>>>(
        pattn, outw, phid, hs, NT, DM, DM, 0);

    // LN2 -> router -> top-2 dispatch
    ln_kernel<<<NT, 256>>>(phid, ln2w, px2);
    moe_init_kernel<<<(CAP + 255)/256, 256>>>();
    router_kernel<<<NT/8, 256>>>(px2, rw);
    segoff_kernel<<<1, 1>>>();
    fill_kernel<<<(NT*2 + 255)/256, 256>>>();

    // MoE grouped GEMMs
    sgemm_tc<0,true,true,true><<<dim3(FF/128, CAP/128), 256>>>(
        px2, w1, ph1, nullptr, CAP, FF, DM, (long)FF*DM);
    sgemm_tc<0,true,true,true><<<dim3(FF/128, CAP/128), 256>>>(
        px2, v1, ph2, nullptr, CAP, FF, DM, (long)FF*DM);
    silu_kernel<<<(CAP*(FF/4) + 255)/256, 256>>>();
    sgemm_tc<0,false,false,true><<<dim3(DM/128, CAP/128), 256>>>(
        ph1, w2, py, nullptr, CAP, DM, FF, (long)FF*DM);

    // resid2 + gated expert outputs
    combine_kernel<<<NT, 256>>>(out);
}

// round 6
// speedup vs baseline: 2.5865x; 1.0259x over previous
#include <cuda_runtime.h>
#include <math.h>

// ---------------- problem constants ----------------
#define BB 2
#define SS 2048
#define DM 1024
#define NH 16
#define NKV 4
#define HDIM 64
#define NE 8
#define FF 2048
#define NT (BB*SS)                    // 4096 tokens
#define QKVN (DM + 2*NKV*HDIM)        // 1536
#define CAP (2*NT + NE*128)           // 9216 padded MoE slots
#define SCALEQ 0.125f
#define CLIPV 8.0f

// ---------------- device scratch ----------------
__device__ float g_x1[NT*DM];
__device__ float g_qkv[NT*QKVN];
__device__ float g_attn[NT*DM];
__device__ float g_hidden[NT*DM];
__device__ float g_x2[NT*DM];
__device__ int   g_top_e[NT*2];
__device__ float g_top_w[NT*2];
__device__ int   g_cnt[NE];
__device__ int   g_fill[NE];
__device__ int   g_segoff[NE+1];
__device__ int   g_total;
__device__ int   g_perm[CAP];
__device__ int   g_tok_slot[NT*2];
__device__ float g_h1[CAP*FF];
__device__ float g_h2[CAP*FF];
__device__ float g_y[CAP*DM];

// ---------------- layernorm ----------------
__global__ void ln_kernel(const float* __restrict__ x, const float* __restrict__ w,
                          float* __restrict__ out) {
    int row = blockIdx.x, tid = threadIdx.x;
    float4 v = ((const float4*)(x + (size_t)row*DM))[tid];
    float s = v.x+v.y+v.z+v.w;
    float q = v.x*v.x+v.y*v.y+v.z*v.z+v.w*v.w;
#pragma unroll
    for (int o = 16; o; o >>= 1) {
        s += __shfl_xor_sync(0xffffffffu, s, o);
        q += __shfl_xor_sync(0xffffffffu, q, o);
    }
    __shared__ float ssm[8], qsm[8];
    if ((tid & 31) == 0) { ssm[tid>>5] = s; qsm[tid>>5] = q; }
    __syncthreads();
    float ts = 0.f, tq = 0.f;
#pragma unroll
    for (int i = 0; i < 8; i++) { ts += ssm[i]; tq += qsm[i]; }
    float mu  = ts * (1.f/DM);
    float var = tq * (1.f/DM) - mu*mu;
    float rs  = rsqrtf(var + 1e-5f);
    float4 wv = ((const float4*)w)[tid];
    float4 r;
    r.x = (v.x-mu)*rs*wv.x; r.y = (v.y-mu)*rs*wv.y;
    r.z = (v.z-mu)*rs*wv.z; r.w = (v.w-mu)*rs*wv.w;
    ((float4*)(out + (size_t)row*DM))[tid] = r;
}

// ---------------- tf32 / cp.async helpers ----------------
__device__ __forceinline__ unsigned f2tf32(float x) {
    unsigned r;
    asm("cvt.rna.tf32.f32 %0, %1;" : "=r"(r) : "f"(x));
    return r;
}
__device__ __forceinline__ void mma_tf32(float* c,
        unsigned a0, unsigned a1, unsigned a2, unsigned a3,
        unsigned b0, unsigned b1) {
    asm volatile("mma.sync.aligned.m16n8k8.row.col.f32.tf32.tf32.f32 "
        "{%0,%1,%2,%3}, {%4,%5,%6,%7}, {%8,%9}, {%0,%1,%2,%3};"
        : "+f"(c[0]), "+f"(c[1]), "+f"(c[2]), "+f"(c[3])
        : "r"(a0), "r"(a1), "r"(a2), "r"(a3), "r"(b0), "r"(b1));
}
__device__ __forceinline__ void cp16(float* smem_dst, const float* gsrc, int src_bytes) {
    unsigned sa = (unsigned)__cvta_generic_to_shared(smem_dst);
    asm volatile("cp.async.cg.shared.global [%0], [%1], 16, %2;\n"
                 :: "r"(sa), "l"(gsrc), "r"(src_bytes));
}
#define CP_COMMIT() asm volatile("cp.async.commit_group;\n")
#define CP_WAITG2() asm volatile("cp.async.wait_group 2;\n")

// ---------------- pipelined tf32 GEMM: 128x128x16 tiles, 4-stage cp.async ----------------
// A in smem [m][k] stride 20; B: BT -> [n][k] stride 20, else [k][n] stride 136.
#define ASTR 20
#define BSTR 136
#define SLAB 2560                         // floats per matrix per stage
#define NSTG 4
#define GEMM_SMEM (NSTG*2*SLAB*4)         // 81920 B dynamic
template<int EPI, bool GATHER, bool BT, bool EXPERT>
__global__ void __launch_bounds__(256, 2)
sgemm_tc(const float* __restrict__ A, const float* __restrict__ Bm,
         float* __restrict__ C, const float* __restrict__ resid,
         int M, int N, int K, long ldbE) {
    int mbase = blockIdx.y * 128;
    if (EXPERT) {
        if (mbase >= g_total) return;
        int e = 0;
#pragma unroll
        for (int i = 0; i < NE; i++) if (g_segoff[i+1] <= mbase) e = i + 1;
        Bm += (size_t)e * ldbE;
    }
    int nbase = blockIdx.x * 128;
    extern __shared__ float smp[];
    int tid  = threadIdx.x;
    int lane = tid & 31, warp = tid >> 5;
    int wM = (warp & 1) * 64;
    int wN = (warp >> 1) * 32;
    int g  = lane >> 2, tg = lane & 3;

    int ar = tid >> 1, ac = (tid & 1) * 8;        // A: row, first col (2x float4)
    const float* arow;
    int asz = 16;
    if (GATHER) {
        int tok = g_perm[mbase + ar];
        asz  = (tok >= 0) ? 16 : 0;
        arow = A + (size_t)(tok >= 0 ? tok : 0) * K;
    } else {
        arow = A + (size_t)(mbase + ar) * K;
    }
    int bk = tid >> 4, bn = (tid & 15) * 8;       // B[k][n] path

    float acc[4][4][4];
#pragma unroll
    for (int mi = 0; mi < 4; mi++)
#pragma unroll
        for (int nj = 0; nj < 4; nj++)
#pragma unroll
            for (int r = 0; r < 4; r++) acc[mi][nj][r] = 0.f;

    auto load_slab = [&](int s, int kb) {
        float* As = smp + s*(2*SLAB);
        float* Bs = As + SLAB;
        cp16(&As[ar*ASTR + ac],     arow + kb + ac,     asz);
        cp16(&As[ar*ASTR + ac + 4], arow + kb + ac + 4, asz);
        if (!BT) {
            const float* bp = Bm + (size_t)(kb + bk)*N + nbase + bn;
            cp16(&Bs[bk*BSTR + bn],     bp,     16);
            cp16(&Bs[bk*BSTR + bn + 4], bp + 4, 16);
        } else {
            const float* bp = Bm + (size_t)(nbase + ar)*K + kb + ac;
            cp16(&Bs[ar*ASTR + ac],     bp,     16);
            cp16(&Bs[ar*ASTR + ac + 4], bp + 4, 16);
        }
    };

    int ns = K >> 4;
    // prologue: 3 stages in flight
#pragma unroll
    for (int j = 0; j < 3; j++) { load_slab(j, j*16); CP_COMMIT(); }

    for (int i = 0; i < ns; i++) {
        int s = i & (NSTG-1);
        CP_WAITG2();             // slab i's group complete; i+1, i+2 still in flight
        __syncthreads();         // all warps done with stage (i-1) -> safe to overwrite
        int j = i + 3;
        if (j < ns) load_slab(j & (NSTG-1), j*16);
        CP_COMMIT();             // (possibly empty) keeps group accounting exact
        const float* as = smp + s*(2*SLAB);
        const float* bs = as + SLAB;
#pragma unroll
        for (int ks = 0; ks < 2; ks++) {
            int k0 = ks * 8;
            unsigned bf[4][2];
#pragma unroll
            for (int nj = 0; nj < 4; nj++) {
                int n = wN + nj*8 + g;
                if (!BT) {
                    bf[nj][0] = __float_as_uint(bs[(k0+tg)*BSTR + n]);
                    bf[nj][1] = __float_as_uint(bs[(k0+tg+4)*BSTR + n]);
                } else {
                    bf[nj][0] = __float_as_uint(bs[n*ASTR + k0+tg]);
                    bf[nj][1] = __float_as_uint(bs[n*ASTR + k0+tg+4]);
                }
            }
#pragma unroll
            for (int mi = 0; mi < 4; mi++) {
                int m = wM + mi*16 + g;
                unsigned fa0 = __float_as_uint(as[m*ASTR + k0+tg]);
                unsigned fa1 = __float_as_uint(as[(m+8)*ASTR + k0+tg]);
                unsigned fa2 = __float_as_uint(as[m*ASTR + k0+tg+4]);
                unsigned fa3 = __float_as_uint(as[(m+8)*ASTR + k0+tg+4]);
#pragma unroll
                for (int nj = 0; nj < 4; nj++)
                    mma_tf32(acc[mi][nj], fa0, fa1, fa2, fa3, bf[nj][0], bf[nj][1]);
            }
        }
    }
    // ---- epilogue ----
#pragma unroll
    for (int mi = 0; mi < 4; mi++) {
#pragma unroll
        for (int nj = 0; nj < 4; nj++) {
            int r0 = mbase + wM + mi*16 + g;
            int r1 = r0 + 8;
            int c  = nbase + wN + nj*8 + tg*2;
            float v0 = acc[mi][nj][0], v1 = acc[mi][nj][1];
            float v2 = acc[mi][nj][2], v3 = acc[mi][nj][3];
            if (EPI == 1) {
                v0 = fminf(fmaxf(v0,-CLIPV),CLIPV); v1 = fminf(fmaxf(v1,-CLIPV),CLIPV);
                v2 = fminf(fmaxf(v2,-CLIPV),CLIPV); v3 = fminf(fmaxf(v3,-CLIPV),CLIPV);
            }
            if (EPI == 2) {
                float2 r0v = *(const float2*)(resid + (size_t)r0*N + c);
                float2 r1v = *(const float2*)(resid + (size_t)r1*N + c);
                v0 += r0v.x; v1 += r0v.y; v2 += r1v.x; v3 += r1v.y;
            }
            *(float2*)(C + (size_t)r0*N + c) = make_float2(v0, v1);
            *(float2*)(C + (size_t)r1*N + c) = make_float2(v2, v3);
        }
    }
}

// ---------------- RoPE ----------------
__global__ void rope_kernel() {
    int idx = blockIdx.x*blockDim.x + threadIdx.x;
    if (idx >= NT*20*32) return;
    int i    = idx & 31;
    int head = (idx >> 5) % 20;
    int n    = idx / (32*20);
    int s    = n & (SS - 1);
    float inv = (float)pow(10000.0, -(double)i / 32.0);
    float ang = (float)s * inv;
    float sn, cs;
    sincosf(ang, &sn, &cs);
    float* base = g_qkv + (size_t)n*QKVN + (head < NH ? head*HDIM : DM + (head-NH)*HDIM);
    float x1 = base[i], x2 = base[i+32];
    base[i]    = x1*cs - x2*sn;
    base[i+32] = x1*sn + x2*cs;
}

// ---------------- tensor-core flash attention ----------------
#define FQ 128
#define FKT 64
#define FST 68
#define FLASH_SMEM ((FQ*FST + FKT*FST + FKT*FST + FQ*FST)*4)
__global__ void __launch_bounds__(256)
flash_tc_kernel(const float* __restrict__ qkv, float* __restrict__ out) {
    extern __shared__ unsigned sm[];
    unsigned* Qs = sm;
    unsigned* Ks = Qs + FQ*FST;
    unsigned* Vs = Ks + FKT*FST;
    unsigned* Ps = Vs + FKT*FST;
    int qb = gridDim.x - 1 - blockIdx.x;
    int bh = blockIdx.y;
    int b = bh >> 4, h = bh & 15, kh = h >> 2;
    int tid = threadIdx.x, lane = tid & 31, warp = tid >> 5;
    int g = lane >> 2, tg = lane & 3;

    const float* qp = qkv + (size_t)(b*SS + qb*FQ)*QKVN + h*HDIM;
    for (int t = tid; t < FQ*16; t += 256) {
        int r = t >> 4, c4 = (t & 15)*4;
        float4 v = *(const float4*)(qp + (size_t)r*QKVN + c4);
        unsigned* d = &Qs[r*FST + c4];
        d[0] = f2tf32(v.x*SCALEQ); d[1] = f2tf32(v.y*SCALEQ);
        d[2] = f2tf32(v.z*SCALEQ); d[3] = f2tf32(v.w*SCALEQ);
    }

    int wrow = warp*16;
    int grow = qb*FQ + wrow;

    float m0 = -1e30f, m1 = -1e30f, l0 = 0.f, l1 = 0.f;
    float o[8][4];
#pragma unroll
    for (int nj = 0; nj < 8; nj++)
#pragma unroll
        for (int r = 0; r < 4; r++) o[nj][r] = 0.f;

    int ktmax = 2*qb + 1;
    for (int kt = 0; kt <= ktmax; kt++) {
        __syncthreads();
        const float* kp = qkv + (size_t)(b*SS + kt*FKT)*QKVN + DM + kh*HDIM;
        const float* vp = kp + NKV*HDIM;
        for (int t = tid; t < FKT*16; t += 256) {
            int r = t >> 4, c4 = (t & 15)*4;
            float4 k4 = *(const float4*)(kp + (size_t)r*QKVN + c4);
            float4 v4 = *(const float4*)(vp + (size_t)r*QKVN + c4);
            unsigned* dk = &Ks[r*FST + c4];
            dk[0]=f2tf32(k4.x); dk[1]=f2tf32(k4.y); dk[2]=f2tf32(k4.z); dk[3]=f2tf32(k4.w);
            unsigned* dv = &Vs[r*FST + c4];
            dv[0]=f2tf32(v4.x); dv[1]=f2tf32(v4.y); dv[2]=f2tf32(v4.z); dv[3]=f2tf32(v4.w);
        }
        __syncthreads();

        if (kt*FKT > grow + 15) continue;

        float s[8][4];
#pragma unroll
        for (int nj = 0; nj < 8; nj++)
#pragma unroll
            for (int r = 0; r < 4; r++) s[nj][r] = 0.f;
#pragma unroll
        for (int k0 = 0; k0 < HDIM; k0 += 8) {
            unsigned a0 = Qs[(wrow+g  )*FST + k0+tg];
            unsigned a1 = Qs[(wrow+g+8)*FST + k0+tg];
            unsigned a2 = Qs[(wrow+g  )*FST + k0+tg+4];
            unsigned a3 = Qs[(wrow+g+8)*FST + k0+tg+4];
#pragma unroll
            for (int nj = 0; nj < 8; nj++) {
                unsigned b0 = Ks[(nj*8+g)*FST + k0+tg];
                unsigned b1 = Ks[(nj*8+g)*FST + k0+tg+4];
                mma_tf32(s[nj], a0, a1, a2, a3, b0, b1);
            }
        }
        if (kt >= 2*qb) {
            int r0 = grow + g, r1 = grow + g + 8;
#pragma unroll
            for (int nj = 0; nj < 8; nj++) {
                int c = kt*FKT + nj*8 + 2*tg;
                if (c     > r0) s[nj][0] = -1e30f;
                if (c + 1 > r0) s[nj][1] = -1e30f;
                if (c     > r1) s[nj][2] = -1e30f;
                if (c + 1 > r1) s[nj][3] = -1e30f;
            }
        }
        float mt0 = -1e30f, mt1 = -1e30f;
#pragma unroll
        for (int nj = 0; nj < 8; nj++) {
            mt0 = fmaxf(mt0, fmaxf(s[nj][0], s[nj][1]));
            mt1 = fmaxf(mt1, fmaxf(s[nj][2], s[nj][3]));
        }
        mt0 = fmaxf(mt0, __shfl_xor_sync(0xffffffffu, mt0, 1));
        mt0 = fmaxf(mt0, __shfl_xor_sync(0xffffffffu, mt0, 2));
        mt1 = fmaxf(mt1, __shfl_xor_sync(0xffffffffu, mt1, 1));
        mt1 = fmaxf(mt1, __shfl_xor_sync(0xffffffffu, mt1, 2));
        float mn0 = fmaxf(m0, mt0), mn1 = fmaxf(m1, mt1);
        float c0 = __expf(m0 - mn0), c1 = __expf(m1 - mn1);
        l0 *= c0; l1 *= c1;
#pragma unroll
        for (int nj = 0; nj < 8; nj++) {
            o[nj][0] *= c0; o[nj][1] *= c0;
            o[nj][2] *= c1; o[nj][3] *= c1;
        }
        float rs0 = 0.f, rs1 = 0.f;
#pragma unroll
        for (int nj = 0; nj < 8; nj++) {
            float p0 = __expf(s[nj][0] - mn0);
            float p1 = __expf(s[nj][1] - mn0);
            float p2 = __expf(s[nj][2] - mn1);
            float p3 = __expf(s[nj][3] - mn1);
            rs0 += p0 + p1; rs1 += p2 + p3;
            int col = nj*8 + 2*tg;
            *(uint2*)&Ps[(wrow+g  )*FST + col] = make_uint2(f2tf32(p0), f2tf32(p1));
            *(uint2*)&Ps[(wrow+g+8)*FST + col] = make_uint2(f2tf32(p2), f2tf32(p3));
        }
        rs0 += __shfl_xor_sync(0xffffffffu, rs0, 1);
        rs0 += __shfl_xor_sync(0xffffffffu, rs0, 2);
        rs1 += __shfl_xor_sync(0xffffffffu, rs1, 1);
        rs1 += __shfl_xor_sync(0xffffffffu, rs1, 2);
        l0 += rs0; l1 += rs1;
        m0 = mn0; m1 = mn1;

        __syncwarp();
#pragma unroll
        for (int k0 = 0; k0 < FKT; k0 += 8) {
            unsigned a0 = Ps[(wrow+g  )*FST + k0+tg];
            unsigned a1 = Ps[(wrow+g+8)*FST + k0+tg];
            unsigned a2 = Ps[(wrow+g  )*FST + k0+tg+4];
            unsigned a3 = Ps[(wrow+g+8)*FST + k0+tg+4];
#pragma unroll
            for (int nj = 0; nj < 8; nj++) {
                unsigned b0 = Vs[(k0+tg  )*FST + nj*8+g];
                unsigned b1 = Vs[(k0+tg+4)*FST + nj*8+g];
                mma_tf32(o[nj], a0, a1, a2, a3, b0, b1);
            }
        }
    }
    float il0 = 1.f/l0, il1 = 1.f/l1;
    size_t tok0 = (size_t)(b*SS + qb*FQ + wrow + g);
    size_t tok1 = tok0 + 8;
#pragma unroll
    for (int nj = 0; nj < 8; nj++) {
        int col = h*HDIM + nj*8 + 2*tg;
        *(float2*)(out + tok0*DM + col) = make_float2(o[nj][0]*il0, o[nj][1]*il0);
        *(float2*)(out + tok1*DM + col) = make_float2(o[nj][2]*il1, o[nj][3]*il1);
    }
}

// ---------------- router ----------------
__global__ void router_kernel(const float* __restrict__ x2, const float* __restrict__ rw) {
    int t = (blockIdx.x*blockDim.x + threadIdx.x) >> 5;
    int lane = threadIdx.x & 31;
    if (t >= NT) return;
    const float* xr = x2 + (size_t)t*DM;
    float acc[NE];
#pragma unroll
    for (int e = 0; e < NE; e++) acc[e] = 0.f;
    for (int d = lane; d < DM; d += 32) {
        float xv = xr[d];
        float4 r0 = ((const float4*)rw)[d*2];
        float4 r1 = ((const float4*)rw)[d*2+1];
        acc[0]+=xv*r0.x; acc[1]+=xv*r0.y; acc[2]+=xv*r0.z; acc[3]+=xv*r0.w;
        acc[4]+=xv*r1.x; acc[5]+=xv*r1.y; acc[6]+=xv*r1.z; acc[7]+=xv*r1.w;
    }
#pragma unroll
    for (int o = 16; o; o >>= 1)
#pragma unroll
        for (int e = 0; e < NE; e++)
            acc[e] += __shfl_xor_sync(0xffffffffu, acc[e], o);
    if (lane == 0) {
        int e0 = 0; float m0 = acc[0];
#pragma unroll
        for (int e = 1; e < NE; e++) if (acc[e] > m0) { m0 = acc[e]; e0 = e; }
        int e1 = -1; float m1 = -3.4e38f;
#pragma unroll
        for (int e = 0; e < NE; e++) if (e != e0 && acc[e] > m1) { m1 = acc[e]; e1 = e; }
        float p1 = expf(m1 - m0);
        float w0 = 1.f / (1.f + p1);
        float w1 = p1 / (1.f + p1);
        g_top_e[2*t] = e0; g_top_e[2*t+1] = e1;
        g_top_w[2*t] = w0; g_top_w[2*t+1] = w1;
        atomicAdd(&g_cnt[e0], 1);
        atomicAdd(&g_cnt[e1], 1);
    }
}

__global__ void moe_init_kernel() {
    int i = blockIdx.x*blockDim.x + threadIdx.x;
    if (i < NE) { g_cnt[i] = 0; g_fill[i] = 0; }
    if (i < CAP) g_perm[i] = -1;
}

__global__ void segoff_kernel() {
    int off = 0;
    for (int e = 0; e < NE; e++) {
        g_segoff[e] = off;
        off += ((g_cnt[e] + 127) >> 7) << 7;
    }
    g_segoff[NE] = off;
    g_total = off;
}

__global__ void fill_kernel() {
    int i = blockIdx.x*blockDim.x + threadIdx.x;
    if (i >= NT*2) return;
    int e = g_top_e[i];
    int pos = g_segoff[e] + atomicAdd(&g_fill[e], 1);
    g_perm[pos] = i >> 1;
    g_tok_slot[i] = pos;
}

__global__ void silu_kernel() {
    long i = ((long)blockIdx.x*blockDim.x + threadIdx.x) * 4;
    long lim = (long)g_total * FF;
    if (i >= lim) return;
    float4 a = *(float4*)&g_h1[i];
    float4 b = *(float4*)&g_h2[i];
    a.x = a.x / (1.f + __expf(-a.x)) * b.x;
    a.y = a.y / (1.f + __expf(-a.y)) * b.y;
    a.z = a.z / (1.f + __expf(-a.z)) * b.z;
    a.w = a.w / (1.f + __expf(-a.w)) * b.w;
    *(float4*)&g_h1[i] = a;
}

__global__ void combine_kernel(float* __restrict__ out) {
    int i = blockIdx.x*blockDim.x + threadIdx.x;
    int n = i >> 8, d4 = i & 255;
    int s0 = g_tok_slot[2*n], s1 = g_tok_slot[2*n+1];
    float w0 = g_top_w[2*n], w1 = g_top_w[2*n+1];
    float4 hv = *(float4*)&g_hidden[(size_t)n*DM + d4*4];
    float4 y0 = *(float4*)&g_y[(size_t)s0*DM + d4*4];
    float4 y1 = *(float4*)&g_y[(size_t)s1*DM + d4*4];
    float4 r;
    r.x = hv.x + w0*y0.x + w1*y1.x;
    r.y = hv.y + w0*y0.y + w1*y1.y;
    r.z = hv.z + w0*y0.z + w1*y1.z;
    r.w = hv.w + w0*y0.w + w1*y1.w;
    *(float4*)&out[(size_t)n*DM + d4*4] = r;
}

// ---------------- launch ----------------
extern "C" void kernel_launch(void* const* d_in, const int* in_sizes, int n_in,
                              void* d_out, int out_size) {
    const float* hs   = (const float*)d_in[0];
    const float* ln1w = (const float*)d_in[1];
    const float* ln2w = (const float*)d_in[2];
    const float* wqkv = (const float*)d_in[3];
    const float* outw = (const float*)d_in[4];
    const float* rw   = (const float*)d_in[5];
    const float* w1   = (const float*)d_in[6];
    const float* v1   = (const float*)d_in[7];
    const float* w2   = (const float*)d_in[8];
    float* out = (float*)d_out;

    float *px1, *pqkv, *pattn, *phid, *px2, *ph1, *ph2, *py;
    cudaGetSymbolAddress((void**)&px1,  g_x1);
    cudaGetSymbolAddress((void**)&pqkv, g_qkv);
    cudaGetSymbolAddress((void**)&pattn,g_attn);
    cudaGetSymbolAddress((void**)&phid, g_hidden);
    cudaGetSymbolAddress((void**)&px2,  g_x2);
    cudaGetSymbolAddress((void**)&ph1,  g_h1);
    cudaGetSymbolAddress((void**)&ph2,  g_h2);
    cudaGetSymbolAddress((void**)&py,   g_y);

    cudaFuncSetAttribute(flash_tc_kernel,
                         cudaFuncAttributeMaxDynamicSharedMemorySize, FLASH_SMEM);
    cudaFuncSetAttribute(sgemm_tc<1,false,false,false>,
                         cudaFuncAttributeMaxDynamicSharedMemorySize, GEMM_SMEM);
    cudaFuncSetAttribute(sgemm_tc<2,false,false,false>,
                         cudaFuncAttributeMaxDynamicSharedMemorySize, GEMM_SMEM);
    cudaFuncSetAttribute(sgemm_tc<0,true,true,true>,
                         cudaFuncAttributeMaxDynamicSharedMemorySize, GEMM_SMEM);
    cudaFuncSetAttribute(sgemm_tc<0,false,false,true>,
                         cudaFuncAttributeMaxDynamicSharedMemorySize, GEMM_SMEM);

    // LN1 -> QKV(clip) -> RoPE -> attention -> out-proj(+resid)
    ln_kernel<<<NT, 256>>>(hs, ln1w, px1);
    sgemm_tc<1,false,false,false><<<dim3(QKVN/128, NT/128), 256, GEMM_SMEM>>>(
        px1, wqkv, pqkv, nullptr, NT, QKVN, DM, 0);
    rope_kernel<<<(NT*20*32 + 255)/256, 256>>>();
    flash_tc_kernel<<<dim3(SS/FQ, BB*NH), 256, FLASH_SMEM>>>(pqkv, pattn);
    sgemm_tc<2,false,false,false><<<dim3(DM/128, NT/128), 256, GEMM_SMEM>>>(
        pattn, outw, phid, hs, NT, DM, DM, 0);

    // LN2 -> router -> top-2 dispatch
    ln_kernel<<<NT, 256>>>(phid, ln2w, px2);
    moe_init_kernel<<<(CAP + 255)/256, 256>>>();
    router_kernel<<<NT/8, 256>>>(px2, rw);
    segoff_kernel<<<1, 1>>>();
    fill_kernel<<<(NT*2 + 255)/256, 256>>>();

    // MoE grouped GEMMs
    sgemm_tc<0,true,true,true><<<dim3(FF/128, CAP/128), 256, GEMM_SMEM>>>(
        px2, w1, ph1, nullptr, CAP, FF, DM, (long)FF*DM);
    sgemm_tc<0,true,true,true><<<dim3(FF/128, CAP/128), 256, GEMM_SMEM>>>(
        px2, v1, ph2, nullptr, CAP, FF, DM, (long)FF*DM);
    silu_kernel<<<(CAP*(FF/4) + 255)/256, 256>>>();
    sgemm_tc<0,false,false,true><<<dim3(DM/128, CAP/128), 256, GEMM_SMEM>>>(
        ph1, w2, py, nullptr, CAP, DM, FF, (long)FF*DM);

    // resid2 + gated expert outputs
    combine_kernel<<<NT, 256>>>(out);
}

// round 7
// speedup vs baseline: 3.1950x; 1.2353x over previous
#include <cuda_runtime.h>
#include <math.h>

// ---------------- problem constants ----------------
#define BB 2
#define SS 2048
#define DM 1024
#define NH 16
#define NKV 4
#define HDIM 64
#define NE 8
#define FF 2048
#define NT (BB*SS)                    // 4096 tokens
#define QKVN (DM + 2*NKV*HDIM)        // 1536
#define CAP (2*NT + NE*128)           // 9216 padded MoE slots
#define SCALEQ 0.125f
#define CLIPV 8.0f

// ---------------- device scratch ----------------
__device__ float g_x1[NT*DM];
__device__ float g_qkv[NT*QKVN];
__device__ float g_attn[NT*DM];
__device__ float g_hidden[NT*DM];
__device__ float g_x2[NT*DM];
__device__ int   g_top_e[NT*2];
__device__ float g_top_w[NT*2];
__device__ int   g_cnt[NE];
__device__ int   g_fill[NE];
__device__ int   g_segoff[NE+1];
__device__ int   g_total;
__device__ int   g_perm[CAP];
__device__ int   g_tok_slot[NT*2];
__device__ float g_h1[CAP*FF];
__device__ float g_y[CAP*DM];
__device__ float g_invfreq[32];

// ---------------- layernorm ----------------
__global__ void ln_kernel(const float* __restrict__ x, const float* __restrict__ w,
                          float* __restrict__ out) {
    int row = blockIdx.x, tid = threadIdx.x;
    float4 v = ((const float4*)(x + (size_t)row*DM))[tid];
    float s = v.x+v.y+v.z+v.w;
    float q = v.x*v.x+v.y*v.y+v.z*v.z+v.w*v.w;
#pragma unroll
    for (int o = 16; o; o >>= 1) {
        s += __shfl_xor_sync(0xffffffffu, s, o);
        q += __shfl_xor_sync(0xffffffffu, q, o);
    }
    __shared__ float ssm[8], qsm[8];
    if ((tid & 31) == 0) { ssm[tid>>5] = s; qsm[tid>>5] = q; }
    __syncthreads();
    float ts = 0.f, tq = 0.f;
#pragma unroll
    for (int i = 0; i < 8; i++) { ts += ssm[i]; tq += qsm[i]; }
    float mu  = ts * (1.f/DM);
    float var = tq * (1.f/DM) - mu*mu;
    float rs  = rsqrtf(var + 1e-5f);
    float4 wv = ((const float4*)w)[tid];
    float4 r;
    r.x = (v.x-mu)*rs*wv.x; r.y = (v.y-mu)*rs*wv.y;
    r.z = (v.z-mu)*rs*wv.z; r.w = (v.w-mu)*rs*wv.w;
    ((float4*)(out + (size_t)row*DM))[tid] = r;
}

// ---------------- tf32 / cp.async helpers ----------------
__device__ __forceinline__ void mma_tf32(float* c,
        unsigned a0, unsigned a1, unsigned a2, unsigned a3,
        unsigned b0, unsigned b1) {
    asm volatile("mma.sync.aligned.m16n8k8.row.col.f32.tf32.tf32.f32 "
        "{%0,%1,%2,%3}, {%4,%5,%6,%7}, {%8,%9}, {%0,%1,%2,%3};"
        : "+f"(c[0]), "+f"(c[1]), "+f"(c[2]), "+f"(c[3])
        : "r"(a0), "r"(a1), "r"(a2), "r"(a3), "r"(b0), "r"(b1));
}
__device__ __forceinline__ void cp16(float* smem_dst, const float* gsrc, int src_bytes) {
    unsigned sa = (unsigned)__cvta_generic_to_shared(smem_dst);
    asm volatile("cp.async.cg.shared.global [%0], [%1], 16, %2;\n"
                 :: "r"(sa), "l"(gsrc), "r"(src_bytes));
}
#define CP_COMMIT() asm volatile("cp.async.commit_group;\n")
#define CP_WAITG2() asm volatile("cp.async.wait_group 2;\n")
#define CP_WAITG1() asm volatile("cp.async.wait_group 1;\n")

// ---------------- pipelined tf32 GEMM: 128x128x16 tiles, 4-stage cp.async ----------------
// EPI: 0 none, 1 clip, 2 +resid, 3 silu(prev)*acc (prev read from resid==C base)
#define ASTR 20
#define BSTR 136
#define SLAB 2560
#define NSTG 4
#define GEMM_SMEM (NSTG*2*SLAB*4)         // 81920 B dynamic
template<int EPI, bool GATHER, bool BT, bool EXPERT>
__global__ void __launch_bounds__(256, 2)
sgemm_tc(const float* __restrict__ A, const float* __restrict__ Bm,
         float* __restrict__ C, const float* __restrict__ resid,
         int M, int N, int K, long ldbE) {
    int mbase = blockIdx.y * 128;
    if (EXPERT) {
        if (mbase >= g_total) return;
        int e = 0;
#pragma unroll
        for (int i = 0; i < NE; i++) if (g_segoff[i+1] <= mbase) e = i + 1;
        Bm += (size_t)e * ldbE;
    }
    int nbase = blockIdx.x * 128;
    extern __shared__ float smp[];
    int tid  = threadIdx.x;
    int lane = tid & 31, warp = tid >> 5;
    int wM = (warp & 1) * 64;
    int wN = (warp >> 1) * 32;
    int g  = lane >> 2, tg = lane & 3;

    int ar = tid >> 1, ac = (tid & 1) * 8;
    const float* arow;
    int asz = 16;
    if (GATHER) {
        int tok = g_perm[mbase + ar];
        asz  = (tok >= 0) ? 16 : 0;
        arow = A + (size_t)(tok >= 0 ? tok : 0) * K;
    } else {
        arow = A + (size_t)(mbase + ar) * K;
    }
    int bk = tid >> 4, bn = (tid & 15) * 8;

    float acc[4][4][4];
#pragma unroll
    for (int mi = 0; mi < 4; mi++)
#pragma unroll
        for (int nj = 0; nj < 4; nj++)
#pragma unroll
            for (int r = 0; r < 4; r++) acc[mi][nj][r] = 0.f;

    auto load_slab = [&](int s, int kb) {
        float* As = smp + s*(2*SLAB);
        float* Bs = As + SLAB;
        cp16(&As[ar*ASTR + ac],     arow + kb + ac,     asz);
        cp16(&As[ar*ASTR + ac + 4], arow + kb + ac + 4, asz);
        if (!BT) {
            const float* bp = Bm + (size_t)(kb + bk)*N + nbase + bn;
            cp16(&Bs[bk*BSTR + bn],     bp,     16);
            cp16(&Bs[bk*BSTR + bn + 4], bp + 4, 16);
        } else {
            const float* bp = Bm + (size_t)(nbase + ar)*K + kb + ac;
            cp16(&Bs[ar*ASTR + ac],     bp,     16);
            cp16(&Bs[ar*ASTR + ac + 4], bp + 4, 16);
        }
    };

    int ns = K >> 4;
#pragma unroll
    for (int j = 0; j < 3; j++) { load_slab(j, j*16); CP_COMMIT(); }

    for (int i = 0; i < ns; i++) {
        int s = i & (NSTG-1);
        CP_WAITG2();
        __syncthreads();
        int j = i + 3;
        if (j < ns) load_slab(j & (NSTG-1), j*16);
        CP_COMMIT();
        const float* as = smp + s*(2*SLAB);
        const float* bs = as + SLAB;
#pragma unroll
        for (int ks = 0; ks < 2; ks++) {
            int k0 = ks * 8;
            unsigned bf[4][2];
#pragma unroll
            for (int nj = 0; nj < 4; nj++) {
                int n = wN + nj*8 + g;
                if (!BT) {
                    bf[nj][0] = __float_as_uint(bs[(k0+tg)*BSTR + n]);
                    bf[nj][1] = __float_as_uint(bs[(k0+tg+4)*BSTR + n]);
                } else {
                    bf[nj][0] = __float_as_uint(bs[n*ASTR + k0+tg]);
                    bf[nj][1] = __float_as_uint(bs[n*ASTR + k0+tg+4]);
                }
            }
#pragma unroll
            for (int mi = 0; mi < 4; mi++) {
                int m = wM + mi*16 + g;
                unsigned fa0 = __float_as_uint(as[m*ASTR + k0+tg]);
                unsigned fa1 = __float_as_uint(as[(m+8)*ASTR + k0+tg]);
                unsigned fa2 = __float_as_uint(as[m*ASTR + k0+tg+4]);
                unsigned fa3 = __float_as_uint(as[(m+8)*ASTR + k0+tg+4]);
#pragma unroll
                for (int nj = 0; nj < 4; nj++)
                    mma_tf32(acc[mi][nj], fa0, fa1, fa2, fa3, bf[nj][0], bf[nj][1]);
            }
        }
    }
    // ---- epilogue ----
#pragma unroll
    for (int mi = 0; mi < 4; mi++) {
#pragma unroll
        for (int nj = 0; nj < 4; nj++) {
            int r0 = mbase + wM + mi*16 + g;
            int r1 = r0 + 8;
            int c  = nbase + wN + nj*8 + tg*2;
            float v0 = acc[mi][nj][0], v1 = acc[mi][nj][1];
            float v2 = acc[mi][nj][2], v3 = acc[mi][nj][3];
            if (EPI == 1) {
                v0 = fminf(fmaxf(v0,-CLIPV),CLIPV); v1 = fminf(fmaxf(v1,-CLIPV),CLIPV);
                v2 = fminf(fmaxf(v2,-CLIPV),CLIPV); v3 = fminf(fmaxf(v3,-CLIPV),CLIPV);
            }
            if (EPI == 2) {
                float2 r0v = *(const float2*)(resid + (size_t)r0*N + c);
                float2 r1v = *(const float2*)(resid + (size_t)r1*N + c);
                v0 += r0v.x; v1 += r0v.y; v2 += r1v.x; v3 += r1v.y;
            }
            if (EPI == 3) {   // h = silu(prev) * acc
                float2 p0 = *(const float2*)(resid + (size_t)r0*N + c);
                float2 p1 = *(const float2*)(resid + (size_t)r1*N + c);
                v0 *= p0.x / (1.f + __expf(-p0.x));
                v1 *= p0.y / (1.f + __expf(-p0.y));
                v2 *= p1.x / (1.f + __expf(-p1.x));
                v3 *= p1.y / (1.f + __expf(-p1.y));
            }
            *(float2*)(C + (size_t)r0*N + c) = make_float2(v0, v1);
            *(float2*)(C + (size_t)r1*N + c) = make_float2(v2, v3);
        }
    }
}

// ---------------- RoPE ----------------
__global__ void ropetab_kernel() {
    int i = threadIdx.x;
    if (i < 32) g_invfreq[i] = (float)pow(10000.0, -(double)i / 32.0);
}
__global__ void rope_kernel() {
    int idx = blockIdx.x*blockDim.x + threadIdx.x;
    if (idx >= NT*20*32) return;
    int i    = idx & 31;
    int head = (idx >> 5) % 20;
    int n    = idx / (32*20);
    int s    = n & (SS - 1);
    float ang = (float)s * g_invfreq[i];
    float sn, cs;
    sincosf(ang, &sn, &cs);
    float* base = g_qkv + (size_t)n*QKVN + (head < NH ? head*HDIM : DM + (head-NH)*HDIM);
    float x1 = base[i], x2 = base[i+32];
    base[i]    = x1*cs - x2*sn;
    base[i+32] = x1*sn + x2*cs;
}

// ---------------- tensor-core flash attention, cp.async K/V double buffer ----------------
#define FQ 128
#define FKT 64
#define FST 68
// Q:128 + K:2x64 + V:2x64 + P:128 rows, stride 68 words
#define FLASH_SMEM ((FQ + 2*FKT + 2*FKT + FQ)*FST*4)   // 139264 B
__global__ void __launch_bounds__(256)
flash_tc_kernel(const float* __restrict__ qkv, float* __restrict__ out) {
    extern __shared__ float sm[];
    float* Qs = sm;
    float* Kst = Qs + FQ*FST;           // 2 stages
    float* Vst = Kst + 2*FKT*FST;       // 2 stages
    float* Ps = Vst + 2*FKT*FST;
    int qb = gridDim.x - 1 - blockIdx.x;
    int bh = blockIdx.y;
    int b = bh >> 4, h = bh & 15, kh = h >> 2;
    int tid = threadIdx.x, lane = tid & 31, warp = tid >> 5;
    int g = lane >> 2, tg = lane & 3;

    // Q tile (scaled, raw fp32 — mma truncates to tf32)
    const float* qp = qkv + (size_t)(b*SS + qb*FQ)*QKVN + h*HDIM;
    for (int t = tid; t < FQ*16; t += 256) {
        int r = t >> 4, c4 = (t & 15)*4;
        float4 v = *(const float4*)(qp + (size_t)r*QKVN + c4);
        v.x *= SCALEQ; v.y *= SCALEQ; v.z *= SCALEQ; v.w *= SCALEQ;
        *(float4*)&Qs[r*FST + c4] = v;
    }

    // K/V copy assignment: 256 thr x 4 chunks covers 64 rows x 16 chunks
    int kvr = tid >> 2, kvc = (tid & 3) * 4;   // row, first float4 (of 16)
    const float* kbase = qkv + (size_t)(b*SS)*QKVN + DM + kh*HDIM;
    auto load_kv = [&](int st, int kt) {
        const float* kp = kbase + (size_t)(kt*FKT + kvr)*QKVN;
        const float* vp = kp + NKV*HDIM;
        float* kd = Kst + st*FKT*FST + kvr*FST;
        float* vd = Vst + st*FKT*FST + kvr*FST;
#pragma unroll
        for (int q = 0; q < 4; q++) {
            cp16(kd + (kvc+q)*4, kp + (kvc+q)*4, 16);
            cp16(vd + (kvc+q)*4, vp + (kvc+q)*4, 16);
        }
    };

    int wrow = warp*16;
    int grow = qb*FQ + wrow;

    float m0 = -1e30f, m1 = -1e30f, l0 = 0.f, l1 = 0.f;
    float o[8][4];
#pragma unroll
    for (int nj = 0; nj < 8; nj++)
#pragma unroll
        for (int r = 0; r < 4; r++) o[nj][r] = 0.f;

    int ktmax = 2*qb + 1;
    load_kv(0, 0);
    CP_COMMIT();

    for (int kt = 0; kt <= ktmax; kt++) {
        int st = kt & 1;
        __syncthreads();                 // all warps done reading buffer st (from kt-2) / Ps
        if (kt < ktmax) load_kv(st ^ 1, kt + 1);
        CP_COMMIT();
        CP_WAITG1();                     // buffer st (tile kt) complete
        __syncthreads();                 // visibility across threads

        if (kt*FKT > grow + 15) continue;
        const float* Ks = Kst + st*FKT*FST;
        const float* Vs = Vst + st*FKT*FST;

        float s[8][4];
#pragma unroll
        for (int nj = 0; nj < 8; nj++)
#pragma unroll
            for (int r = 0; r < 4; r++) s[nj][r] = 0.f;
#pragma unroll
        for (int k0 = 0; k0 < HDIM; k0 += 8) {
            unsigned a0 = __float_as_uint(Qs[(wrow+g  )*FST + k0+tg]);
            unsigned a1 = __float_as_uint(Qs[(wrow+g+8)*FST + k0+tg]);
            unsigned a2 = __float_as_uint(Qs[(wrow+g  )*FST + k0+tg+4]);
            unsigned a3 = __float_as_uint(Qs[(wrow+g+8)*FST + k0+tg+4]);
#pragma unroll
            for (int nj = 0; nj < 8; nj++) {
                unsigned b0 = __float_as_uint(Ks[(nj*8+g)*FST + k0+tg]);
                unsigned b1 = __float_as_uint(Ks[(nj*8+g)*FST + k0+tg+4]);
                mma_tf32(s[nj], a0, a1, a2, a3, b0, b1);
            }
        }
        if (kt >= 2*qb) {
            int r0 = grow + g, r1 = grow + g + 8;
#pragma unroll
            for (int nj = 0; nj < 8; nj++) {
                int c = kt*FKT + nj*8 + 2*tg;
                if (c     > r0) s[nj][0] = -1e30f;
                if (c + 1 > r0) s[nj][1] = -1e30f;
                if (c     > r1) s[nj][2] = -1e30f;
                if (c + 1 > r1) s[nj][3] = -1e30f;
            }
        }
        float mt0 = -1e30f, mt1 = -1e30f;
#pragma unroll
        for (int nj = 0; nj < 8; nj++) {
            mt0 = fmaxf(mt0, fmaxf(s[nj][0], s[nj][1]));
            mt1 = fmaxf(mt1, fmaxf(s[nj][2], s[nj][3]));
        }
        mt0 = fmaxf(mt0, __shfl_xor_sync(0xffffffffu, mt0, 1));
        mt0 = fmaxf(mt0, __shfl_xor_sync(0xffffffffu, mt0, 2));
        mt1 = fmaxf(mt1, __shfl_xor_sync(0xffffffffu, mt1, 1));
        mt1 = fmaxf(mt1, __shfl_xor_sync(0xffffffffu, mt1, 2));
        float mn0 = fmaxf(m0, mt0), mn1 = fmaxf(m1, mt1);
        float c0 = __expf(m0 - mn0), c1 = __expf(m1 - mn1);
        l0 *= c0; l1 *= c1;
#pragma unroll
        for (int nj = 0; nj < 8; nj++) {
            o[nj][0] *= c0; o[nj][1] *= c0;
            o[nj][2] *= c1; o[nj][3] *= c1;
        }
        float rs0 = 0.f, rs1 = 0.f;
#pragma unroll
        for (int nj = 0; nj < 8; nj++) {
            float p0 = __expf(s[nj][0] - mn0);
            float p1 = __expf(s[nj][1] - mn0);
            float p2 = __expf(s[nj][2] - mn1);
            float p3 = __expf(s[nj][3] - mn1);
            rs0 += p0 + p1; rs1 += p2 + p3;
            int col = nj*8 + 2*tg;
            *(float2*)&Ps[(wrow+g  )*FST + col] = make_float2(p0, p1);
            *(float2*)&Ps[(wrow+g+8)*FST + col] = make_float2(p2, p3);
        }
        rs0 += __shfl_xor_sync(0xffffffffu, rs0, 1);
        rs0 += __shfl_xor_sync(0xffffffffu, rs0, 2);
        rs1 += __shfl_xor_sync(0xffffffffu, rs1, 1);
        rs1 += __shfl_xor_sync(0xffffffffu, rs1, 2);
        l0 += rs0; l1 += rs1;
        m0 = mn0; m1 = mn1;

        __syncwarp();
#pragma unroll
        for (int k0 = 0; k0 < FKT; k0 += 8) {
            unsigned a0 = __float_as_uint(Ps[(wrow+g  )*FST + k0+tg]);
            unsigned a1 = __float_as_uint(Ps[(wrow+g+8)*FST + k0+tg]);
            unsigned a2 = __float_as_uint(Ps[(wrow+g  )*FST + k0+tg+4]);
            unsigned a3 = __float_as_uint(Ps[(wrow+g+8)*FST + k0+tg+4]);
#pragma unroll
            for (int nj = 0; nj < 8; nj++) {
                unsigned b0 = __float_as_uint(Vs[(k0+tg  )*FST + nj*8+g]);
                unsigned b1 = __float_as_uint(Vs[(k0+tg+4)*FST + nj*8+g]);
                mma_tf32(o[nj], a0, a1, a2, a3, b0, b1);
            }
        }
    }
    float il0 = 1.f/l0, il1 = 1.f/l1;
    size_t tok0 = (size_t)(b*SS + qb*FQ + wrow + g);
    size_t tok1 = tok0 + 8;
#pragma unroll
    for (int nj = 0; nj < 8; nj++) {
        int col = h*HDIM + nj*8 + 2*tg;
        *(float2*)(out + tok0*DM + col) = make_float2(o[nj][0]*il0, o[nj][1]*il0);
        *(float2*)(out + tok1*DM + col) = make_float2(o[nj][2]*il1, o[nj][3]*il1);
    }
}

// ---------------- router ----------------
__global__ void router_kernel(const float* __restrict__ x2, const float* __restrict__ rw) {
    int t = (blockIdx.x*blockDim.x + threadIdx.x) >> 5;
    int lane = threadIdx.x & 31;
    if (t >= NT) return;
    const float* xr = x2 + (size_t)t*DM;
    float acc[NE];
#pragma unroll
    for (int e = 0; e < NE; e++) acc[e] = 0.f;
    for (int d = lane; d < DM; d += 32) {
        float xv = xr[d];
        float4 r0 = ((const float4*)rw)[d*2];
        float4 r1 = ((const float4*)rw)[d*2+1];
        acc[0]+=xv*r0.x; acc[1]+=xv*r0.y; acc[2]+=xv*r0.z; acc[3]+=xv*r0.w;
        acc[4]+=xv*r1.x; acc[5]+=xv*r1.y; acc[6]+=xv*r1.z; acc[7]+=xv*r1.w;
    }
#pragma unroll
    for (int o = 16; o; o >>= 1)
#pragma unroll
        for (int e = 0; e < NE; e++)
            acc[e] += __shfl_xor_sync(0xffffffffu, acc[e], o);
    if (lane == 0) {
        int e0 = 0; float m0 = acc[0];
#pragma unroll
        for (int e = 1; e < NE; e++) if (acc[e] > m0) { m0 = acc[e]; e0 = e; }
        int e1 = -1; float m1 = -3.4e38f;
#pragma unroll
        for (int e = 0; e < NE; e++) if (e != e0 && acc[e] > m1) { m1 = acc[e]; e1 = e; }
        float p1 = expf(m1 - m0);
        float w0 = 1.f / (1.f + p1);
        float w1 = p1 / (1.f + p1);
        g_top_e[2*t] = e0; g_top_e[2*t+1] = e1;
        g_top_w[2*t] = w0; g_top_w[2*t+1] = w1;
        atomicAdd(&g_cnt[e0], 1);
        atomicAdd(&g_cnt[e1], 1);
    }
}

__global__ void moe_init_kernel() {
    int i = blockIdx.x*blockDim.x + threadIdx.x;
    if (i < NE) { g_cnt[i] = 0; g_fill[i] = 0; }
    if (i < CAP) g_perm[i] = -1;
}

__global__ void segoff_kernel() {
    int off = 0;
    for (int e = 0; e < NE; e++) {
        g_segoff[e] = off;
        off += ((g_cnt[e] + 127) >> 7) << 7;
    }
    g_segoff[NE] = off;
    g_total = off;
}

__global__ void fill_kernel() {
    int i = blockIdx.x*blockDim.x + threadIdx.x;
    if (i >= NT*2) return;
    int e = g_top_e[i];
    int pos = g_segoff[e] + atomicAdd(&g_fill[e], 1);
    g_perm[pos] = i >> 1;
    g_tok_slot[i] = pos;
}

__global__ void combine_kernel(float* __restrict__ out) {
    int i = blockIdx.x*blockDim.x + threadIdx.x;
    int n = i >> 8, d4 = i & 255;
    int s0 = g_tok_slot[2*n], s1 = g_tok_slot[2*n+1];
    float w0 = g_top_w[2*n], w1 = g_top_w[2*n+1];
    float4 hv = *(float4*)&g_hidden[(size_t)n*DM + d4*4];
    float4 y0 = *(float4*)&g_y[(size_t)s0*DM + d4*4];
    float4 y1 = *(float4*)&g_y[(size_t)s1*DM + d4*4];
    float4 r;
    r.x = hv.x + w0*y0.x + w1*y1.x;
    r.y = hv.y + w0*y0.y + w1*y1.y;
    r.z = hv.z + w0*y0.z + w1*y1.z;
    r.w = hv.w + w0*y0.w + w1*y1.w;
    *(float4*)&out[(size_t)n*DM + d4*4] = r;
}

// ---------------- launch ----------------
extern "C" void kernel_launch(void* const* d_in, const int* in_sizes, int n_in,
                              void* d_out, int out_size) {
    const float* hs   = (const float*)d_in[0];
    const float* ln1w = (const float*)d_in[1];
    const float* ln2w = (const float*)d_in[2];
    const float* wqkv = (const float*)d_in[3];
    const float* outw = (const float*)d_in[4];
    const float* rw   = (const float*)d_in[5];
    const float* w1   = (const float*)d_in[6];
    const float* v1   = (const float*)d_in[7];
    const float* w2   = (const float*)d_in[8];
    float* out = (float*)d_out;

    float *px1, *pqkv, *pattn, *phid, *px2, *ph1, *py;
    cudaGetSymbolAddress((void**)&px1,  g_x1);
    cudaGetSymbolAddress((void**)&pqkv, g_qkv);
    cudaGetSymbolAddress((void**)&pattn,g_attn);
    cudaGetSymbolAddress((void**)&phid, g_hidden);
    cudaGetSymbolAddress((void**)&px2,  g_x2);
    cudaGetSymbolAddress((void**)&ph1,  g_h1);
    cudaGetSymbolAddress((void**)&py,   g_y);

    cudaFuncSetAttribute(flash_tc_kernel,
                         cudaFuncAttributeMaxDynamicSharedMemorySize, FLASH_SMEM);
    cudaFuncSetAttribute(sgemm_tc<1,false,false,false>,
                         cudaFuncAttributeMaxDynamicSharedMemorySize, GEMM_SMEM);
    cudaFuncSetAttribute(sgemm_tc<2,false,false,false>,
                         cudaFuncAttributeMaxDynamicSharedMemorySize, GEMM_SMEM);
    cudaFuncSetAttribute(sgemm_tc<0,true,true,true>,
                         cudaFuncAttributeMaxDynamicSharedMemorySize, GEMM_SMEM);
    cudaFuncSetAttribute(sgemm_tc<3,true,true,true>,
                         cudaFuncAttributeMaxDynamicSharedMemorySize, GEMM_SMEM);
    cudaFuncSetAttribute(sgemm_tc<0,false,false,true>,
                         cudaFuncAttributeMaxDynamicSharedMemorySize, GEMM_SMEM);

    // LN1 -> QKV(clip) -> RoPE -> attention -> out-proj(+resid)
    ln_kernel<<<NT, 256>>>(hs, ln1w, px1);
    sgemm_tc<1,false,false,false><<<dim3(QKVN/128, NT/128), 256, GEMM_SMEM>>>(
        px1, wqkv, pqkv, nullptr, NT, QKVN, DM, 0);
    ropetab_kernel<<<1, 32>>>();
    rope_kernel<<<(NT*20*32 + 255)/256, 256>>>();
    flash_tc_kernel<<<dim3(SS/FQ, BB*NH), 256, FLASH_SMEM>>>(pqkv, pattn);
    sgemm_tc<2,false,false,false><<<dim3(DM/128, NT/128), 256, GEMM_SMEM>>>(
        pattn, outw, phid, hs, NT, DM, DM, 0);

    // LN2 -> router -> top-2 dispatch
    ln_kernel<<<NT, 256>>>(phid, ln2w, px2);
    moe_init_kernel<<<(CAP + 255)/256, 256>>>();
    router_kernel<<<NT/8, 256>>>(px2, rw);
    segoff_kernel<<<1, 1>>>();
    fill_kernel<<<(NT*2 + 255)/256, 256>>>();

    // MoE grouped GEMMs: h1 = x@w1^T, then h1 = silu(h1)*(x@v1^T) fused, then down
    sgemm_tc<0,true,true,true><<<dim3(FF/128, CAP/128), 256, GEMM_SMEM>>>(
        px2, w1, ph1, nullptr, CAP, FF, DM, (long)FF*DM);
    sgemm_tc<3,true,true,true><<<dim3(FF/128, CAP/128), 256, GEMM_SMEM>>>(
        px2, v1, ph1, ph1, CAP, FF, DM, (long)FF*DM);
    sgemm_tc<0,false,false,true><<<dim3(DM/128, CAP/128), 256, GEMM_SMEM>>>(
        ph1, w2, py, nullptr, CAP, DM, FF, (long)FF*DM);

    // resid2 + gated expert outputs
    combine_kernel<<<NT, 256>>>(out);
}

// round 8
// speedup vs baseline: 3.2561x; 1.0191x over previous
#include <cuda_runtime.h>
#include <math.h>

// ---------------- problem constants ----------------
#define BB 2
#define SS 2048
#define DM 1024
#define NH 16
#define NKV 4
#define HDIM 64
#define NE 8
#define FF 2048
#define NT (BB*SS)                    // 4096 tokens
#define QKVN (DM + 2*NKV*HDIM)        // 1536
#define CAP (2*NT + NE*128)           // 9216 padded MoE slots
#define SCALEQ 0.125f
#define CLIPV 8.0f

// ---------------- device scratch ----------------
__device__ float g_x1[NT*DM];
__device__ float g_qkv[NT*QKVN];
__device__ float g_attn[NT*DM];
__device__ float g_hidden[NT*DM];
__device__ float g_x2[NT*DM];
__device__ int   g_top_e[NT*2];
__device__ float g_top_w[NT*2];
__device__ int   g_cnt[NE];
__device__ int   g_fill[NE];
__device__ int   g_segoff[NE+1];
__device__ int   g_total;
__device__ int   g_perm[CAP];
__device__ int   g_tok_slot[NT*2];
__device__ float g_h1[CAP*FF];
__device__ float g_y[CAP*DM];
__device__ float g_invfreq[32];

// ---------------- layernorm ----------------
__global__ void ln_kernel(const float* __restrict__ x, const float* __restrict__ w,
                          float* __restrict__ out) {
    int row = blockIdx.x, tid = threadIdx.x;
    float4 v = ((const float4*)(x + (size_t)row*DM))[tid];
    float s = v.x+v.y+v.z+v.w;
    float q = v.x*v.x+v.y*v.y+v.z*v.z+v.w*v.w;
#pragma unroll
    for (int o = 16; o; o >>= 1) {
        s += __shfl_xor_sync(0xffffffffu, s, o);
        q += __shfl_xor_sync(0xffffffffu, q, o);
    }
    __shared__ float ssm[8], qsm[8];
    if ((tid & 31) == 0) { ssm[tid>>5] = s; qsm[tid>>5] = q; }
    __syncthreads();
    float ts = 0.f, tq = 0.f;
#pragma unroll
    for (int i = 0; i < 8; i++) { ts += ssm[i]; tq += qsm[i]; }
    float mu  = ts * (1.f/DM);
    float var = tq * (1.f/DM) - mu*mu;
    float rs  = rsqrtf(var + 1e-5f);
    float4 wv = ((const float4*)w)[tid];
    float4 r;
    r.x = (v.x-mu)*rs*wv.x; r.y = (v.y-mu)*rs*wv.y;
    r.z = (v.z-mu)*rs*wv.z; r.w = (v.w-mu)*rs*wv.w;
    ((float4*)(out + (size_t)row*DM))[tid] = r;
}

// ---------------- tf32 / cp.async helpers ----------------
__device__ __forceinline__ void mma_tf32(float* c,
        unsigned a0, unsigned a1, unsigned a2, unsigned a3,
        unsigned b0, unsigned b1) {
    asm volatile("mma.sync.aligned.m16n8k8.row.col.f32.tf32.tf32.f32 "
        "{%0,%1,%2,%3}, {%4,%5,%6,%7}, {%8,%9}, {%0,%1,%2,%3};"
        : "+f"(c[0]), "+f"(c[1]), "+f"(c[2]), "+f"(c[3])
        : "r"(a0), "r"(a1), "r"(a2), "r"(a3), "r"(b0), "r"(b1));
}
__device__ __forceinline__ void cp16(float* smem_dst, const float* gsrc, int src_bytes) {
    unsigned sa = (unsigned)__cvta_generic_to_shared(smem_dst);
    asm volatile("cp.async.cg.shared.global [%0], [%1], 16, %2;\n"
                 :: "r"(sa), "l"(gsrc), "r"(src_bytes));
}
#define CP_COMMIT() asm volatile("cp.async.commit_group;\n")
#define CP_WAITG2() asm volatile("cp.async.wait_group 2;\n")
#define CP_WAITG1() asm volatile("cp.async.wait_group 1;\n")

// ---------------- pipelined tf32 GEMM: 128x128x16 tiles, 4-stage cp.async ----------------
// EPI: 0 none, 1 clip, 2 +resid
#define ASTR 20
#define BSTR 136
#define SLAB 2560
#define NSTG 4
#define GEMM_SMEM (NSTG*2*SLAB*4)         // 81920 B dynamic
template<int EPI, bool GATHER, bool BT, bool EXPERT>
__global__ void __launch_bounds__(256, 2)
sgemm_tc(const float* __restrict__ A, const float* __restrict__ Bm,
         float* __restrict__ C, const float* __restrict__ resid,
         int M, int N, int K, long ldbE) {
    int mbase = blockIdx.y * 128;
    if (EXPERT) {
        if (mbase >= g_total) return;
        int e = 0;
#pragma unroll
        for (int i = 0; i < NE; i++) if (g_segoff[i+1] <= mbase) e = i + 1;
        Bm += (size_t)e * ldbE;
    }
    int nbase = blockIdx.x * 128;
    extern __shared__ float smp[];
    int tid  = threadIdx.x;
    int lane = tid & 31, warp = tid >> 5;
    int wM = (warp & 1) * 64;
    int wN = (warp >> 1) * 32;
    int g  = lane >> 2, tg = lane & 3;

    int ar = tid >> 1, ac = (tid & 1) * 8;
    const float* arow;
    int asz = 16;
    if (GATHER) {
        int tok = g_perm[mbase + ar];
        asz  = (tok >= 0) ? 16 : 0;
        arow = A + (size_t)(tok >= 0 ? tok : 0) * K;
    } else {
        arow = A + (size_t)(mbase + ar) * K;
    }
    int bk = tid >> 4, bn = (tid & 15) * 8;

    float acc[4][4][4];
#pragma unroll
    for (int mi = 0; mi < 4; mi++)
#pragma unroll
        for (int nj = 0; nj < 4; nj++)
#pragma unroll
            for (int r = 0; r < 4; r++) acc[mi][nj][r] = 0.f;

    auto load_slab = [&](int s, int kb) {
        float* As = smp + s*(2*SLAB);
        float* Bs = As + SLAB;
        cp16(&As[ar*ASTR + ac],     arow + kb + ac,     asz);
        cp16(&As[ar*ASTR + ac + 4], arow + kb + ac + 4, asz);
        if (!BT) {
            const float* bp = Bm + (size_t)(kb + bk)*N + nbase + bn;
            cp16(&Bs[bk*BSTR + bn],     bp,     16);
            cp16(&Bs[bk*BSTR + bn + 4], bp + 4, 16);
        } else {
            const float* bp = Bm + (size_t)(nbase + ar)*K + kb + ac;
            cp16(&Bs[ar*ASTR + ac],     bp,     16);
            cp16(&Bs[ar*ASTR + ac + 4], bp + 4, 16);
        }
    };

    int ns = K >> 4;
#pragma unroll
    for (int j = 0; j < 3; j++) { load_slab(j, j*16); CP_COMMIT(); }

    for (int i = 0; i < ns; i++) {
        int s = i & (NSTG-1);
        CP_WAITG2();
        __syncthreads();
        int j = i + 3;
        if (j < ns) load_slab(j & (NSTG-1), j*16);
        CP_COMMIT();
        const float* as = smp + s*(2*SLAB);
        const float* bs = as + SLAB;
#pragma unroll
        for (int ks = 0; ks < 2; ks++) {
            int k0 = ks * 8;
            unsigned bf[4][2];
#pragma unroll
            for (int nj = 0; nj < 4; nj++) {
                int n = wN + nj*8 + g;
                if (!BT) {
                    bf[nj][0] = __float_as_uint(bs[(k0+tg)*BSTR + n]);
                    bf[nj][1] = __float_as_uint(bs[(k0+tg+4)*BSTR + n]);
                } else {
                    bf[nj][0] = __float_as_uint(bs[n*ASTR + k0+tg]);
                    bf[nj][1] = __float_as_uint(bs[n*ASTR + k0+tg+4]);
                }
            }
#pragma unroll
            for (int mi = 0; mi < 4; mi++) {
                int m = wM + mi*16 + g;
                unsigned fa0 = __float_as_uint(as[m*ASTR + k0+tg]);
                unsigned fa1 = __float_as_uint(as[(m+8)*ASTR + k0+tg]);
                unsigned fa2 = __float_as_uint(as[m*ASTR + k0+tg+4]);
                unsigned fa3 = __float_as_uint(as[(m+8)*ASTR + k0+tg+4]);
#pragma unroll
                for (int nj = 0; nj < 4; nj++)
                    mma_tf32(acc[mi][nj], fa0, fa1, fa2, fa3, bf[nj][0], bf[nj][1]);
            }
        }
    }
    // ---- epilogue ----
#pragma unroll
    for (int mi = 0; mi < 4; mi++) {
#pragma unroll
        for (int nj = 0; nj < 4; nj++) {
            int r0 = mbase + wM + mi*16 + g;
            int r1 = r0 + 8;
            int c  = nbase + wN + nj*8 + tg*2;
            float v0 = acc[mi][nj][0], v1 = acc[mi][nj][1];
            float v2 = acc[mi][nj][2], v3 = acc[mi][nj][3];
            if (EPI == 1) {
                v0 = fminf(fmaxf(v0,-CLIPV),CLIPV); v1 = fminf(fmaxf(v1,-CLIPV),CLIPV);
                v2 = fminf(fmaxf(v2,-CLIPV),CLIPV); v3 = fminf(fmaxf(v3,-CLIPV),CLIPV);
            }
            if (EPI == 2) {
                float2 r0v = *(const float2*)(resid + (size_t)r0*N + c);
                float2 r1v = *(const float2*)(resid + (size_t)r1*N + c);
                v0 += r0v.x; v1 += r0v.y; v2 += r1v.x; v3 += r1v.y;
            }
            *(float2*)(C + (size_t)r0*N + c) = make_float2(v0, v1);
            *(float2*)(C + (size_t)r1*N + c) = make_float2(v2, v3);
        }
    }
}

// ---------------- dual-B up-projection GEMM: h1 = silu(x@w1^T) * (x@v1^T) ----------------
// 128x128 tile, both B operands [N,K] (expert-segmented), A gathered. 3-stage cp.async.
#define UNSTG 3
#define UP_SMEM (UNSTG*3*SLAB*4)          // 92160 B dynamic
__global__ void __launch_bounds__(256, 1)
up_gemm(const float* __restrict__ A, const float* __restrict__ Bw,
        const float* __restrict__ Bv, float* __restrict__ C) {
    const int N = FF, K = DM;
    int mbase = blockIdx.y * 128;
    if (mbase >= g_total) return;
    int e = 0;
#pragma unroll
    for (int i = 0; i < NE; i++) if (g_segoff[i+1] <= mbase) e = i + 1;
    Bw += (size_t)e * FF * DM;
    Bv += (size_t)e * FF * DM;
    int nbase = blockIdx.x * 128;
    extern __shared__ float smp[];
    int tid  = threadIdx.x;
    int lane = tid & 31, warp = tid >> 5;
    int wM = (warp & 1) * 64;
    int wN = (warp >> 1) * 32;
    int g  = lane >> 2, tg = lane & 3;

    int ar = tid >> 1, ac = (tid & 1) * 8;
    int tok = g_perm[mbase + ar];
    int asz  = (tok >= 0) ? 16 : 0;
    const float* arow = A + (size_t)(tok >= 0 ? tok : 0) * K;
    const float* wrow = Bw + (size_t)(nbase + ar) * K;
    const float* vrow = Bv + (size_t)(nbase + ar) * K;

    float accw[4][4][4], accv[4][4][4];
#pragma unroll
    for (int mi = 0; mi < 4; mi++)
#pragma unroll
        for (int nj = 0; nj < 4; nj++)
#pragma unroll
            for (int r = 0; r < 4; r++) { accw[mi][nj][r] = 0.f; accv[mi][nj][r] = 0.f; }

    auto load_slab = [&](int s, int kb) {
        float* As = smp + s*(3*SLAB);
        float* Ws = As + SLAB;
        float* Vs = Ws + SLAB;
        cp16(&As[ar*ASTR + ac],     arow + kb + ac,     asz);
        cp16(&As[ar*ASTR + ac + 4], arow + kb + ac + 4, asz);
        cp16(&Ws[ar*ASTR + ac],     wrow + kb + ac,     16);
        cp16(&Ws[ar*ASTR + ac + 4], wrow + kb + ac + 4, 16);
        cp16(&Vs[ar*ASTR + ac],     vrow + kb + ac,     16);
        cp16(&Vs[ar*ASTR + ac + 4], vrow + kb + ac + 4, 16);
    };

    const int ns = K >> 4;   // 64
#pragma unroll
    for (int j = 0; j < 2; j++) { load_slab(j, j*16); CP_COMMIT(); }

    for (int i = 0; i < ns; i++) {
        int s = i % UNSTG;
        CP_WAITG1();
        __syncthreads();
        int j = i + 2;
        if (j < ns) load_slab(j % UNSTG, j*16);
        CP_COMMIT();
        const float* as = smp + s*(3*SLAB);
        const float* ws = as + SLAB;
        const float* vs = ws + SLAB;
#pragma unroll
        for (int ks = 0; ks < 2; ks++) {
            int k0 = ks * 8;
            unsigned bw[4][2], bv[4][2];
#pragma unroll
            for (int nj = 0; nj < 4; nj++) {
                int n = wN + nj*8 + g;
                bw[nj][0] = __float_as_uint(ws[n*ASTR + k0+tg]);
                bw[nj][1] = __float_as_uint(ws[n*ASTR + k0+tg+4]);
                bv[nj][0] = __float_as_uint(vs[n*ASTR + k0+tg]);
                bv[nj][1] = __float_as_uint(vs[n*ASTR + k0+tg+4]);
            }
#pragma unroll
            for (int mi = 0; mi < 4; mi++) {
                int m = wM + mi*16 + g;
                unsigned fa0 = __float_as_uint(as[m*ASTR + k0+tg]);
                unsigned fa1 = __float_as_uint(as[(m+8)*ASTR + k0+tg]);
                unsigned fa2 = __float_as_uint(as[m*ASTR + k0+tg+4]);
                unsigned fa3 = __float_as_uint(as[(m+8)*ASTR + k0+tg+4]);
#pragma unroll
                for (int nj = 0; nj < 4; nj++) {
                    mma_tf32(accw[mi][nj], fa0, fa1, fa2, fa3, bw[nj][0], bw[nj][1]);
                    mma_tf32(accv[mi][nj], fa0, fa1, fa2, fa3, bv[nj][0], bv[nj][1]);
                }
            }
        }
    }
    // ---- epilogue: h = silu(accw) * accv ----
#pragma unroll
    for (int mi = 0; mi < 4; mi++) {
#pragma unroll
        for (int nj = 0; nj < 4; nj++) {
            int r0 = mbase + wM + mi*16 + g;
            int r1 = r0 + 8;
            int c  = nbase + wN + nj*8 + tg*2;
            float w0 = accw[mi][nj][0], w1 = accw[mi][nj][1];
            float w2 = accw[mi][nj][2], w3 = accw[mi][nj][3];
            float v0 = accv[mi][nj][0] * (w0 / (1.f + __expf(-w0)));
            float v1 = accv[mi][nj][1] * (w1 / (1.f + __expf(-w1)));
            float v2 = accv[mi][nj][2] * (w2 / (1.f + __expf(-w2)));
            float v3 = accv[mi][nj][3] * (w3 / (1.f + __expf(-w3)));
            *(float2*)(C + (size_t)r0*N + c) = make_float2(v0, v1);
            *(float2*)(C + (size_t)r1*N + c) = make_float2(v2, v3);
        }
    }
}

// ---------------- RoPE ----------------
__global__ void ropetab_kernel() {
    int i = threadIdx.x;
    if (i < 32) g_invfreq[i] = (float)pow(10000.0, -(double)i / 32.0);
}
__global__ void rope_kernel() {
    int idx = blockIdx.x*blockDim.x + threadIdx.x;
    if (idx >= NT*20*32) return;
    int i    = idx & 31;
    int head = (idx >> 5) % 20;
    int n    = idx / (32*20);
    int s    = n & (SS - 1);
    float ang = (float)s * g_invfreq[i];
    float sn, cs;
    sincosf(ang, &sn, &cs);
    float* base = g_qkv + (size_t)n*QKVN + (head < NH ? head*HDIM : DM + (head-NH)*HDIM);
    float x1 = base[i], x2 = base[i+32];
    base[i]    = x1*cs - x2*sn;
    base[i+32] = x1*sn + x2*cs;
}

// ---------------- tensor-core flash attention, cp.async K/V double buffer ----------------
#define FQ 128
#define FKT 64
#define FST 68
#define FLASH_SMEM ((FQ + 2*FKT + 2*FKT + FQ)*FST*4)   // 139264 B
__global__ void __launch_bounds__(256)
flash_tc_kernel(const float* __restrict__ qkv, float* __restrict__ out) {
    extern __shared__ float sm[];
    float* Qs = sm;
    float* Kst = Qs + FQ*FST;
    float* Vst = Kst + 2*FKT*FST;
    float* Ps = Vst + 2*FKT*FST;
    int qb = gridDim.x - 1 - blockIdx.x;
    int bh = blockIdx.y;
    int b = bh >> 4, h = bh & 15, kh = h >> 2;
    int tid = threadIdx.x, lane = tid & 31, warp = tid >> 5;
    int g = lane >> 2, tg = lane & 3;

    const float* qp = qkv + (size_t)(b*SS + qb*FQ)*QKVN + h*HDIM;
    for (int t = tid; t < FQ*16; t += 256) {
        int r = t >> 4, c4 = (t & 15)*4;
        float4 v = *(const float4*)(qp + (size_t)r*QKVN + c4);
        v.x *= SCALEQ; v.y *= SCALEQ; v.z *= SCALEQ; v.w *= SCALEQ;
        *(float4*)&Qs[r*FST + c4] = v;
    }

    int kvr = tid >> 2, kvc = (tid & 3) * 4;
    const float* kbase = qkv + (size_t)(b*SS)*QKVN + DM + kh*HDIM;
    auto load_kv = [&](int st, int kt) {
        const float* kp = kbase + (size_t)(kt*FKT + kvr)*QKVN;
        const float* vp = kp + NKV*HDIM;
        float* kd = Kst + st*FKT*FST + kvr*FST;
        float* vd = Vst + st*FKT*FST + kvr*FST;
#pragma unroll
        for (int q = 0; q < 4; q++) {
            cp16(kd + (kvc+q)*4, kp + (kvc+q)*4, 16);
            cp16(vd + (kvc+q)*4, vp + (kvc+q)*4, 16);
        }
    };

    int wrow = warp*16;
    int grow = qb*FQ + wrow;

    float m0 = -1e30f, m1 = -1e30f, l0 = 0.f, l1 = 0.f;
    float o[8][4];
#pragma unroll
    for (int nj = 0; nj < 8; nj++)
#pragma unroll
        for (int r = 0; r < 4; r++) o[nj][r] = 0.f;

    int ktmax = 2*qb + 1;
    load_kv(0, 0);
    CP_COMMIT();

    for (int kt = 0; kt <= ktmax; kt++) {
        int st = kt & 1;
        __syncthreads();
        if (kt < ktmax) load_kv(st ^ 1, kt + 1);
        CP_COMMIT();
        CP_WAITG1();
        __syncthreads();

        if (kt*FKT > grow + 15) continue;
        const float* Ks = Kst + st*FKT*FST;
        const float* Vs = Vst + st*FKT*FST;

        float s[8][4];
#pragma unroll
        for (int nj = 0; nj < 8; nj++)
#pragma unroll
            for (int r = 0; r < 4; r++) s[nj][r] = 0.f;
#pragma unroll
        for (int k0 = 0; k0 < HDIM; k0 += 8) {
            unsigned a0 = __float_as_uint(Qs[(wrow+g  )*FST + k0+tg]);
            unsigned a1 = __float_as_uint(Qs[(wrow+g+8)*FST + k0+tg]);
            unsigned a2 = __float_as_uint(Qs[(wrow+g  )*FST + k0+tg+4]);
            unsigned a3 = __float_as_uint(Qs[(wrow+g+8)*FST + k0+tg+4]);
#pragma unroll
            for (int nj = 0; nj < 8; nj++) {
                unsigned b0 = __float_as_uint(Ks[(nj*8+g)*FST + k0+tg]);
                unsigned b1 = __float_as_uint(Ks[(nj*8+g)*FST + k0+tg+4]);
                mma_tf32(s[nj], a0, a1, a2, a3, b0, b1);
            }
        }
        if (kt >= 2*qb) {
            int r0 = grow + g, r1 = grow + g + 8;
#pragma unroll
            for (int nj = 0; nj < 8; nj++) {
                int c = kt*FKT + nj*8 + 2*tg;
                if (c     > r0) s[nj][0] = -1e30f;
                if (c + 1 > r0) s[nj][1] = -1e30f;
                if (c     > r1) s[nj][2] = -1e30f;
                if (c + 1 > r1) s[nj][3] = -1e30f;
            }
        }
        float mt0 = -1e30f, mt1 = -1e30f;
#pragma unroll
        for (int nj = 0; nj < 8; nj++) {
            mt0 = fmaxf(mt0, fmaxf(s[nj][0], s[nj][1]));
            mt1 = fmaxf(mt1, fmaxf(s[nj][2], s[nj][3]));
        }
        mt0 = fmaxf(mt0, __shfl_xor_sync(0xffffffffu, mt0, 1));
        mt0 = fmaxf(mt0, __shfl_xor_sync(0xffffffffu, mt0, 2));
        mt1 = fmaxf(mt1, __shfl_xor_sync(0xffffffffu, mt1, 1));
        mt1 = fmaxf(mt1, __shfl_xor_sync(0xffffffffu, mt1, 2));
        float mn0 = fmaxf(m0, mt0), mn1 = fmaxf(m1, mt1);
        float c0 = __expf(m0 - mn0), c1 = __expf(m1 - mn1);
        l0 *= c0; l1 *= c1;
#pragma unroll
        for (int nj = 0; nj < 8; nj++) {
            o[nj][0] *= c0; o[nj][1] *= c0;
            o[nj][2] *= c1; o[nj][3] *= c1;
        }
        float rs0 = 0.f, rs1 = 0.f;
#pragma unroll
        for (int nj = 0; nj < 8; nj++) {
            float p0 = __expf(s[nj][0] - mn0);
            float p1 = __expf(s[nj][1] - mn0);
            float p2 = __expf(s[nj][2] - mn1);
            float p3 = __expf(s[nj][3] - mn1);
            rs0 += p0 + p1; rs1 += p2 + p3;
            int col = nj*8 + 2*tg;
            *(float2*)&Ps[(wrow+g  )*FST + col] = make_float2(p0, p1);
            *(float2*)&Ps[(wrow+g+8)*FST + col] = make_float2(p2, p3);
        }
        rs0 += __shfl_xor_sync(0xffffffffu, rs0, 1);
        rs0 += __shfl_xor_sync(0xffffffffu, rs0, 2);
        rs1 += __shfl_xor_sync(0xffffffffu, rs1, 1);
        rs1 += __shfl_xor_sync(0xffffffffu, rs1, 2);
        l0 += rs0; l1 += rs1;
        m0 = mn0; m1 = mn1;

        __syncwarp();
#pragma unroll
        for (int k0 = 0; k0 < FKT; k0 += 8) {
            unsigned a0 = __float_as_uint(Ps[(wrow+g  )*FST + k0+tg]);
            unsigned a1 = __float_as_uint(Ps[(wrow+g+8)*FST + k0+tg]);
            unsigned a2 = __float_as_uint(Ps[(wrow+g  )*FST + k0+tg+4]);
            unsigned a3 = __float_as_uint(Ps[(wrow+g+8)*FST + k0+tg+4]);
#pragma unroll
            for (int nj = 0; nj < 8; nj++) {
                unsigned b0 = __float_as_uint(Vs[(k0+tg  )*FST + nj*8+g]);
                unsigned b1 = __float_as_uint(Vs[(k0+tg+4)*FST + nj*8+g]);
                mma_tf32(o[nj], a0, a1, a2, a3, b0, b1);
            }
        }
    }
    float il0 = 1.f/l0, il1 = 1.f/l1;
    size_t tok0 = (size_t)(b*SS + qb*FQ + wrow + g);
    size_t tok1 = tok0 + 8;
#pragma unroll
    for (int nj = 0; nj < 8; nj++) {
        int col = h*HDIM + nj*8 + 2*tg;
        *(float2*)(out + tok0*DM + col) = make_float2(o[nj][0]*il0, o[nj][1]*il0);
        *(float2*)(out + tok1*DM + col) = make_float2(o[nj][2]*il1, o[nj][3]*il1);
    }
}

// ---------------- router ----------------
__global__ void router_kernel(const float* __restrict__ x2, const float* __restrict__ rw) {
    int t = (blockIdx.x*blockDim.x + threadIdx.x) >> 5;
    int lane = threadIdx.x & 31;
    if (t >= NT) return;
    const float* xr = x2 + (size_t)t*DM;
    float acc[NE];
#pragma unroll
    for (int e = 0; e < NE; e++) acc[e] = 0.f;
    for (int d = lane; d < DM; d += 32) {
        float xv = xr[d];
        float4 r0 = ((const float4*)rw)[d*2];
        float4 r1 = ((const float4*)rw)[d*2+1];
        acc[0]+=xv*r0.x; acc[1]+=xv*r0.y; acc[2]+=xv*r0.z; acc[3]+=xv*r0.w;
        acc[4]+=xv*r1.x; acc[5]+=xv*r1.y; acc[6]+=xv*r1.z; acc[7]+=xv*r1.w;
    }
#pragma unroll
    for (int o = 16; o; o >>= 1)
#pragma unroll
        for (int e = 0; e < NE; e++)
            acc[e] += __shfl_xor_sync(0xffffffffu, acc[e], o);
    if (lane == 0) {
        int e0 = 0; float m0 = acc[0];
#pragma unroll
        for (int e = 1; e < NE; e++) if (acc[e] > m0) { m0 = acc[e]; e0 = e; }
        int e1 = -1; float m1 = -3.4e38f;
#pragma unroll
        for (int e = 0; e < NE; e++) if (e != e0 && acc[e] > m1) { m1 = acc[e]; e1 = e; }
        float p1 = expf(m1 - m0);
        float w0 = 1.f / (1.f + p1);
        float w1 = p1 / (1.f + p1);
        g_top_e[2*t] = e0; g_top_e[2*t+1] = e1;
        g_top_w[2*t] = w0; g_top_w[2*t+1] = w1;
        atomicAdd(&g_cnt[e0], 1);
        atomicAdd(&g_cnt[e1], 1);
    }
}

__global__ void moe_init_kernel() {
    int i = blockIdx.x*blockDim.x + threadIdx.x;
    if (i < NE) { g_cnt[i] = 0; g_fill[i] = 0; }
    if (i < CAP) g_perm[i] = -1;
}

__global__ void segoff_kernel() {
    int off = 0;
    for (int e = 0; e < NE; e++) {
        g_segoff[e] = off;
        off += ((g_cnt[e] + 127) >> 7) << 7;
    }
    g_segoff[NE] = off;
    g_total = off;
}

__global__ void fill_kernel() {
    int i = blockIdx.x*blockDim.x + threadIdx.x;
    if (i >= NT*2) return;
    int e = g_top_e[i];
    int pos = g_segoff[e] + atomicAdd(&g_fill[e], 1);
    g_perm[pos] = i >> 1;
    g_tok_slot[i] = pos;
}

__global__ void combine_kernel(float* __restrict__ out) {
    int i = blockIdx.x*blockDim.x + threadIdx.x;
    int n = i >> 8, d4 = i & 255;
    int s0 = g_tok_slot[2*n], s1 = g_tok_slot[2*n+1];
    float w0 = g_top_w[2*n], w1 = g_top_w[2*n+1];
    float4 hv = *(float4*)&g_hidden[(size_t)n*DM + d4*4];
    float4 y0 = *(float4*)&g_y[(size_t)s0*DM + d4*4];
    float4 y1 = *(float4*)&g_y[(size_t)s1*DM + d4*4];
    float4 r;
    r.x = hv.x + w0*y0.x + w1*y1.x;
    r.y = hv.y + w0*y0.y + w1*y1.y;
    r.z = hv.z + w0*y0.z + w1*y1.z;
    r.w = hv.w + w0*y0.w + w1*y1.w;
    *(float4*)&out[(size_t)n*DM + d4*4] = r;
}

// ---------------- launch ----------------
extern "C" void kernel_launch(void* const* d_in, const int* in_sizes, int n_in,
                              void* d_out, int out_size) {
    const float* hs   = (const float*)d_in[0];
    const float* ln1w = (const float*)d_in[1];
    const float* ln2w = (const float*)d_in[2];
    const float* wqkv = (const float*)d_in[3];
    const float* outw = (const float*)d_in[4];
    const float* rw   = (const float*)d_in[5];
    const float* w1   = (const float*)d_in[6];
    const float* v1   = (const float*)d_in[7];
    const float* w2   = (const float*)d_in[8];
    float* out = (float*)d_out;

    float *px1, *pqkv, *pattn, *phid, *px2, *ph1, *py;
    cudaGetSymbolAddress((void**)&px1,  g_x1);
    cudaGetSymbolAddress((void**)&pqkv, g_qkv);
    cudaGetSymbolAddress((void**)&pattn,g_attn);
    cudaGetSymbolAddress((void**)&phid, g_hidden);
    cudaGetSymbolAddress((void**)&px2,  g_x2);
    cudaGetSymbolAddress((void**)&ph1,  g_h1);
    cudaGetSymbolAddress((void**)&py,   g_y);

    cudaFuncSetAttribute(flash_tc_kernel,
                         cudaFuncAttributeMaxDynamicSharedMemorySize, FLASH_SMEM);
    cudaFuncSetAttribute(sgemm_tc<1,false,false,false>,
                         cudaFuncAttributeMaxDynamicSharedMemorySize, GEMM_SMEM);
    cudaFuncSetAttribute(sgemm_tc<2,false,false,false>,
                         cudaFuncAttributeMaxDynamicSharedMemorySize, GEMM_SMEM);
    cudaFuncSetAttribute(sgemm_tc<0,false,false,true>,
                         cudaFuncAttributeMaxDynamicSharedMemorySize, GEMM_SMEM);
    cudaFuncSetAttribute(up_gemm,
                         cudaFuncAttributeMaxDynamicSharedMemorySize, UP_SMEM);

    // LN1 -> QKV(clip) -> RoPE -> attention -> out-proj(+resid)
    ln_kernel<<<NT, 256>>>(hs, ln1w, px1);
    sgemm_tc<1,false,false,false><<<dim3(QKVN/128, NT/128), 256, GEMM_SMEM>>>(
        px1, wqkv, pqkv, nullptr, NT, QKVN, DM, 0);
    ropetab_kernel<<<1, 32>>>();
    rope_kernel<<<(NT*20*32 + 255)/256, 256>>>();
    flash_tc_kernel<<<dim3(SS/FQ, BB*NH), 256, FLASH_SMEM>>>(pqkv, pattn);
    sgemm_tc<2,false,false,false><<<dim3(DM/128, NT/128), 256, GEMM_SMEM>>>(
        pattn, outw, phid, hs, NT, DM, DM, 0);

    // LN2 -> router -> top-2 dispatch
    ln_kernel<<<NT, 256>>>(phid, ln2w, px2);
    moe_init_kernel<<<(CAP + 255)/256, 256>>>();
    router_kernel<<<NT/8, 256>>>(px2, rw);
    segoff_kernel<<<1, 1>>>();
    fill_kernel<<<(NT*2 + 255)/256, 256>>>();

    // MoE: fused dual-B up (silu in epilogue), then down
    up_gemm<<<dim3(FF/128, CAP/128), 256, UP_SMEM>>>(px2, w1, v1, ph1);
    sgemm_tc<0,false,false,true><<<dim3(DM/128, CAP/128), 256, GEMM_SMEM>>>(
        ph1, w2, py, nullptr, CAP, DM, FF, (long)FF*DM);

    // resid2 + gated expert outputs
    combine_kernel<<<NT, 256>>>(out);
}

// round 9
// speedup vs baseline: 3.3323x; 1.0234x over previous
#include <cuda_runtime.h>
#include <math.h>

// ---------------- problem constants ----------------
#define BB 2
#define SS 2048
#define DM 1024
#define NH 16
#define NKV 4
#define HDIM 64
#define NE 8
#define FF 2048
#define NT (BB*SS)                    // 4096 tokens
#define QKVN (DM + 2*NKV*HDIM)        // 1536
#define CAP (2*NT + NE*128)           // 9216 padded MoE slots
#define SCALEQ 0.125f
#define CLIPV 8.0f

// ---------------- device scratch ----------------
__device__ float g_x1[NT*DM];
__device__ float g_qkv[NT*QKVN];
__device__ float g_attn[NT*DM];
__device__ float g_hidden[NT*DM];
__device__ float g_x2[NT*DM];
__device__ int   g_top_e[NT*2];
__device__ float g_top_w[NT*2];
__device__ int   g_cnt[NE];
__device__ int   g_fill[NE];
__device__ int   g_segoff[NE+1];
__device__ int   g_total;
__device__ int   g_perm[CAP];
__device__ int   g_tok_slot[NT*2];
__device__ float g_h1[CAP*FF];
__device__ float g_y[CAP*DM];
__device__ float g_invfreq[32];

// ---------------- layernorm ----------------
__global__ void ln_kernel(const float* __restrict__ x, const float* __restrict__ w,
                          float* __restrict__ out) {
    int row = blockIdx.x, tid = threadIdx.x;
    float4 v = ((const float4*)(x + (size_t)row*DM))[tid];
    float s = v.x+v.y+v.z+v.w;
    float q = v.x*v.x+v.y*v.y+v.z*v.z+v.w*v.w;
#pragma unroll
    for (int o = 16; o; o >>= 1) {
        s += __shfl_xor_sync(0xffffffffu, s, o);
        q += __shfl_xor_sync(0xffffffffu, q, o);
    }
    __shared__ float ssm[8], qsm[8];
    if ((tid & 31) == 0) { ssm[tid>>5] = s; qsm[tid>>5] = q; }
    __syncthreads();
    float ts = 0.f, tq = 0.f;
#pragma unroll
    for (int i = 0; i < 8; i++) { ts += ssm[i]; tq += qsm[i]; }
    float mu  = ts * (1.f/DM);
    float var = tq * (1.f/DM) - mu*mu;
    float rs  = rsqrtf(var + 1e-5f);
    float4 wv = ((const float4*)w)[tid];
    float4 r;
    r.x = (v.x-mu)*rs*wv.x; r.y = (v.y-mu)*rs*wv.y;
    r.z = (v.z-mu)*rs*wv.z; r.w = (v.w-mu)*rs*wv.w;
    ((float4*)(out + (size_t)row*DM))[tid] = r;
}

// ---------------- tf32 / cp.async helpers ----------------
__device__ __forceinline__ void mma_tf32(float* c,
        unsigned a0, unsigned a1, unsigned a2, unsigned a3,
        unsigned b0, unsigned b1) {
    asm volatile("mma.sync.aligned.m16n8k8.row.col.f32.tf32.tf32.f32 "
        "{%0,%1,%2,%3}, {%4,%5,%6,%7}, {%8,%9}, {%0,%1,%2,%3};"
        : "+f"(c[0]), "+f"(c[1]), "+f"(c[2]), "+f"(c[3])
        : "r"(a0), "r"(a1), "r"(a2), "r"(a3), "r"(b0), "r"(b1));
}
__device__ __forceinline__ void cp16(float* smem_dst, const float* gsrc, int src_bytes) {
    unsigned sa = (unsigned)__cvta_generic_to_shared(smem_dst);
    asm volatile("cp.async.cg.shared.global [%0], [%1], 16, %2;\n"
                 :: "r"(sa), "l"(gsrc), "r"(src_bytes));
}
#define CP_COMMIT() asm volatile("cp.async.commit_group;\n")
#define CP_WAITG3() asm volatile("cp.async.wait_group 3;\n")
#define CP_WAITG2() asm volatile("cp.async.wait_group 2;\n")
#define CP_WAITG1() asm volatile("cp.async.wait_group 1;\n")

// ---------------- pipelined tf32 GEMM: 128x128x16 tiles, 4-stage cp.async ----------------
// EPI: 0 none, 1 clip, 2 +resid
#define ASTR 20
#define BSTR 136
#define SLAB 2560
#define NSTG 4
#define GEMM_SMEM (NSTG*2*SLAB*4)         // 81920 B dynamic
template<int EPI, bool GATHER, bool BT, bool EXPERT>
__global__ void __launch_bounds__(256, 2)
sgemm_tc(const float* __restrict__ A, const float* __restrict__ Bm,
         float* __restrict__ C, const float* __restrict__ resid,
         int M, int N, int K, long ldbE) {
    int mbase = blockIdx.y * 128;
    if (EXPERT) {
        if (mbase >= g_total) return;
        int e = 0;
#pragma unroll
        for (int i = 0; i < NE; i++) if (g_segoff[i+1] <= mbase) e = i + 1;
        Bm += (size_t)e * ldbE;
    }
    int nbase = blockIdx.x * 128;
    extern __shared__ float smp[];
    int tid  = threadIdx.x;
    int lane = tid & 31, warp = tid >> 5;
    int wM = (warp & 1) * 64;
    int wN = (warp >> 1) * 32;
    int g  = lane >> 2, tg = lane & 3;

    int ar = tid >> 1, ac = (tid & 1) * 8;
    const float* arow;
    int asz = 16;
    if (GATHER) {
        int tok = g_perm[mbase + ar];
        asz  = (tok >= 0) ? 16 : 0;
        arow = A + (size_t)(tok >= 0 ? tok : 0) * K;
    } else {
        arow = A + (size_t)(mbase + ar) * K;
    }
    int bk = tid >> 4, bn = (tid & 15) * 8;

    float acc[4][4][4];
#pragma unroll
    for (int mi = 0; mi < 4; mi++)
#pragma unroll
        for (int nj = 0; nj < 4; nj++)
#pragma unroll
            for (int r = 0; r < 4; r++) acc[mi][nj][r] = 0.f;

    auto load_slab = [&](int s, int kb) {
        float* As = smp + s*(2*SLAB);
        float* Bs = As + SLAB;
        cp16(&As[ar*ASTR + ac],     arow + kb + ac,     asz);
        cp16(&As[ar*ASTR + ac + 4], arow + kb + ac + 4, asz);
        if (!BT) {
            const float* bp = Bm + (size_t)(kb + bk)*N + nbase + bn;
            cp16(&Bs[bk*BSTR + bn],     bp,     16);
            cp16(&Bs[bk*BSTR + bn + 4], bp + 4, 16);
        } else {
            const float* bp = Bm + (size_t)(nbase + ar)*K + kb + ac;
            cp16(&Bs[ar*ASTR + ac],     bp,     16);
            cp16(&Bs[ar*ASTR + ac + 4], bp + 4, 16);
        }
    };

    int ns = K >> 4;
#pragma unroll
    for (int j = 0; j < 3; j++) { load_slab(j, j*16); CP_COMMIT(); }

    for (int i = 0; i < ns; i++) {
        int s = i & (NSTG-1);
        CP_WAITG2();
        __syncthreads();
        int j = i + 3;
        if (j < ns) load_slab(j & (NSTG-1), j*16);
        CP_COMMIT();
        const float* as = smp + s*(2*SLAB);
        const float* bs = as + SLAB;
#pragma unroll
        for (int ks = 0; ks < 2; ks++) {
            int k0 = ks * 8;
            unsigned bf[4][2];
#pragma unroll
            for (int nj = 0; nj < 4; nj++) {
                int n = wN + nj*8 + g;
                if (!BT) {
                    bf[nj][0] = __float_as_uint(bs[(k0+tg)*BSTR + n]);
                    bf[nj][1] = __float_as_uint(bs[(k0+tg+4)*BSTR + n]);
                } else {
                    bf[nj][0] = __float_as_uint(bs[n*ASTR + k0+tg]);
                    bf[nj][1] = __float_as_uint(bs[n*ASTR + k0+tg+4]);
                }
            }
#pragma unroll
            for (int mi = 0; mi < 4; mi++) {
                int m = wM + mi*16 + g;
                unsigned fa0 = __float_as_uint(as[m*ASTR + k0+tg]);
                unsigned fa1 = __float_as_uint(as[(m+8)*ASTR + k0+tg]);
                unsigned fa2 = __float_as_uint(as[m*ASTR + k0+tg+4]);
                unsigned fa3 = __float_as_uint(as[(m+8)*ASTR + k0+tg+4]);
#pragma unroll
                for (int nj = 0; nj < 4; nj++)
                    mma_tf32(acc[mi][nj], fa0, fa1, fa2, fa3, bf[nj][0], bf[nj][1]);
            }
        }
    }
    // ---- epilogue ----
#pragma unroll
    for (int mi = 0; mi < 4; mi++) {
#pragma unroll
        for (int nj = 0; nj < 4; nj++) {
            int r0 = mbase + wM + mi*16 + g;
            int r1 = r0 + 8;
            int c  = nbase + wN + nj*8 + tg*2;
            float v0 = acc[mi][nj][0], v1 = acc[mi][nj][1];
            float v2 = acc[mi][nj][2], v3 = acc[mi][nj][3];
            if (EPI == 1) {
                v0 = fminf(fmaxf(v0,-CLIPV),CLIPV); v1 = fminf(fmaxf(v1,-CLIPV),CLIPV);
                v2 = fminf(fmaxf(v2,-CLIPV),CLIPV); v3 = fminf(fmaxf(v3,-CLIPV),CLIPV);
            }
            if (EPI == 2) {
                float2 r0v = *(const float2*)(resid + (size_t)r0*N + c);
                float2 r1v = *(const float2*)(resid + (size_t)r1*N + c);
                v0 += r0v.x; v1 += r0v.y; v2 += r1v.x; v3 += r1v.y;
            }
            *(float2*)(C + (size_t)r0*N + c) = make_float2(v0, v1);
            *(float2*)(C + (size_t)r1*N + c) = make_float2(v2, v3);
        }
    }
}

// ---------------- dual-B up-projection GEMM: h1 = silu(x@w1^T) * (x@v1^T) ----------------
// 128x128 tile, both B operands [N,K] (expert-segmented), A gathered. 5-stage cp.async.
#define UNSTG 5
#define UP_SMEM (UNSTG*3*SLAB*4)          // 153600 B dynamic
__global__ void __launch_bounds__(256, 1)
up_gemm(const float* __restrict__ A, const float* __restrict__ Bw,
        const float* __restrict__ Bv, float* __restrict__ C) {
    const int N = FF, K = DM;
    int mbase = blockIdx.y * 128;
    if (mbase >= g_total) return;
    int e = 0;
#pragma unroll
    for (int i = 0; i < NE; i++) if (g_segoff[i+1] <= mbase) e = i + 1;
    Bw += (size_t)e * FF * DM;
    Bv += (size_t)e * FF * DM;
    int nbase = blockIdx.x * 128;
    extern __shared__ float smp[];
    int tid  = threadIdx.x;
    int lane = tid & 31, warp = tid >> 5;
    int wM = (warp & 1) * 64;
    int wN = (warp >> 1) * 32;
    int g  = lane >> 2, tg = lane & 3;

    int ar = tid >> 1, ac = (tid & 1) * 8;
    int tok = g_perm[mbase + ar];
    int asz  = (tok >= 0) ? 16 : 0;
    const float* arow = A + (size_t)(tok >= 0 ? tok : 0) * K;
    const float* wrow = Bw + (size_t)(nbase + ar) * K;
    const float* vrow = Bv + (size_t)(nbase + ar) * K;

    float accw[4][4][4], accv[4][4][4];
#pragma unroll
    for (int mi = 0; mi < 4; mi++)
#pragma unroll
        for (int nj = 0; nj < 4; nj++)
#pragma unroll
            for (int r = 0; r < 4; r++) { accw[mi][nj][r] = 0.f; accv[mi][nj][r] = 0.f; }

    auto load_slab = [&](int s, int kb) {
        float* As = smp + s*(3*SLAB);
        float* Ws = As + SLAB;
        float* Vs = Ws + SLAB;
        cp16(&As[ar*ASTR + ac],     arow + kb + ac,     asz);
        cp16(&As[ar*ASTR + ac + 4], arow + kb + ac + 4, asz);
        cp16(&Ws[ar*ASTR + ac],     wrow + kb + ac,     16);
        cp16(&Ws[ar*ASTR + ac + 4], wrow + kb + ac + 4, 16);
        cp16(&Vs[ar*ASTR + ac],     vrow + kb + ac,     16);
        cp16(&Vs[ar*ASTR + ac + 4], vrow + kb + ac + 4, 16);
    };

    const int ns = K >> 4;   // 64
#pragma unroll
    for (int j = 0; j < 4; j++) { load_slab(j, j*16); CP_COMMIT(); }

    for (int i = 0; i < ns; i++) {
        int s = i % UNSTG;
        CP_WAITG3();
        __syncthreads();
        int j = i + 4;
        if (j < ns) load_slab(j % UNSTG, j*16);
        CP_COMMIT();
        const float* as = smp + s*(3*SLAB);
        const float* ws = as + SLAB;
        const float* vs = ws + SLAB;
#pragma unroll
        for (int ks = 0; ks < 2; ks++) {
            int k0 = ks * 8;
            unsigned bw[4][2], bv[4][2];
#pragma unroll
            for (int nj = 0; nj < 4; nj++) {
                int n = wN + nj*8 + g;
                bw[nj][0] = __float_as_uint(ws[n*ASTR + k0+tg]);
                bw[nj][1] = __float_as_uint(ws[n*ASTR + k0+tg+4]);
                bv[nj][0] = __float_as_uint(vs[n*ASTR + k0+tg]);
                bv[nj][1] = __float_as_uint(vs[n*ASTR + k0+tg+4]);
            }
#pragma unroll
            for (int mi = 0; mi < 4; mi++) {
                int m = wM + mi*16 + g;
                unsigned fa0 = __float_as_uint(as[m*ASTR + k0+tg]);
                unsigned fa1 = __float_as_uint(as[(m+8)*ASTR + k0+tg]);
                unsigned fa2 = __float_as_uint(as[m*ASTR + k0+tg+4]);
                unsigned fa3 = __float_as_uint(as[(m+8)*ASTR + k0+tg+4]);
#pragma unroll
                for (int nj = 0; nj < 4; nj++) {
                    mma_tf32(accw[mi][nj], fa0, fa1, fa2, fa3, bw[nj][0], bw[nj][1]);
                    mma_tf32(accv[mi][nj], fa0, fa1, fa2, fa3, bv[nj][0], bv[nj][1]);
                }
            }
        }
    }
    // ---- epilogue: h = silu(accw) * accv ----
#pragma unroll
    for (int mi = 0; mi < 4; mi++) {
#pragma unroll
        for (int nj = 0; nj < 4; nj++) {
            int r0 = mbase + wM + mi*16 + g;
            int r1 = r0 + 8;
            int c  = nbase + wN + nj*8 + tg*2;
            float w0 = accw[mi][nj][0], w1 = accw[mi][nj][1];
            float w2 = accw[mi][nj][2], w3 = accw[mi][nj][3];
            float v0 = accv[mi][nj][0] * (w0 / (1.f + __expf(-w0)));
            float v1 = accv[mi][nj][1] * (w1 / (1.f + __expf(-w1)));
            float v2 = accv[mi][nj][2] * (w2 / (1.f + __expf(-w2)));
            float v3 = accv[mi][nj][3] * (w3 / (1.f + __expf(-w3)));
            *(float2*)(C + (size_t)r0*N + c) = make_float2(v0, v1);
            *(float2*)(C + (size_t)r1*N + c) = make_float2(v2, v3);
        }
    }
}

// ---------------- RoPE ----------------
__global__ void ropetab_kernel() {
    int i = threadIdx.x;
    if (i < 32) g_invfreq[i] = (float)pow(10000.0, -(double)i / 32.0);
}
__global__ void rope_kernel() {
    int idx = blockIdx.x*blockDim.x + threadIdx.x;
    if (idx >= NT*20*32) return;
    int i    = idx & 31;
    int head = (idx >> 5) % 20;
    int n    = idx / (32*20);
    int s    = n & (SS - 1);
    float ang = (float)s * g_invfreq[i];
    float sn, cs;
    sincosf(ang, &sn, &cs);
    float* base = g_qkv + (size_t)n*QKVN + (head < NH ? head*HDIM : DM + (head-NH)*HDIM);
    float x1 = base[i], x2 = base[i+32];
    base[i]    = x1*cs - x2*sn;
    base[i+32] = x1*sn + x2*cs;
}

// ---------------- flash attention: QK(kt) | PV(kt-1) | softmax(kt) pipeline ----------------
#define FQ 128
#define FKT 64
#define FST 68
// Q:128 + K:2x64 + V:3x64 + P:128 rows, stride 68 words
#define FLASH_SMEM ((FQ + 2*FKT + 3*FKT + FQ)*FST*4)   // 156672 B
__global__ void __launch_bounds__(256)
flash_tc_kernel(const float* __restrict__ qkv, float* __restrict__ out) {
    extern __shared__ float sm[];
    float* Qs = sm;
    float* Kst = Qs + FQ*FST;           // 2 stages
    float* Vst = Kst + 2*FKT*FST;       // 3 stages
    float* Ps = Vst + 3*FKT*FST;
    int qb = gridDim.x - 1 - blockIdx.x;
    int bh = blockIdx.y;
    int b = bh >> 4, h = bh & 15, kh = h >> 2;
    int tid = threadIdx.x, lane = tid & 31, warp = tid >> 5;
    int g = lane >> 2, tg = lane & 3;

    // Q tile (scaled, raw fp32 — mma truncates to tf32)
    const float* qp = qkv + (size_t)(b*SS + qb*FQ)*QKVN + h*HDIM;
    for (int t = tid; t < FQ*16; t += 256) {
        int r = t >> 4, c4 = (t & 15)*4;
        float4 v = *(const float4*)(qp + (size_t)r*QKVN + c4);
        v.x *= SCALEQ; v.y *= SCALEQ; v.z *= SCALEQ; v.w *= SCALEQ;
        *(float4*)&Qs[r*FST + c4] = v;
    }

    int kvr = tid >> 2, kvc = (tid & 3) * 4;
    const float* kbase = qkv + (size_t)(b*SS)*QKVN + DM + kh*HDIM;
    auto load_kv = [&](int kst, int vst, int kt) {
        const float* kp = kbase + (size_t)(kt*FKT + kvr)*QKVN;
        const float* vp = kp + NKV*HDIM;
        float* kd = Kst + kst*FKT*FST + kvr*FST;
        float* vd = Vst + vst*FKT*FST + kvr*FST;
#pragma unroll
        for (int q = 0; q < 4; q++) {
            cp16(kd + (kvc+q)*4, kp + (kvc+q)*4, 16);
            cp16(vd + (kvc+q)*4, vp + (kvc+q)*4, 16);
        }
    };

    int wrow = warp*16;
    int grow = qb*FQ + wrow;

    float m0 = -1e30f, m1 = -1e30f, l0 = 0.f, l1 = 0.f;
    float o[8][4];
#pragma unroll
    for (int nj = 0; nj < 8; nj++)
#pragma unroll
        for (int r = 0; r < 4; r++) o[nj][r] = 0.f;

    int ktmax = 2*qb + 1;
    load_kv(0, 0, 0);
    CP_COMMIT();

    bool pend = false;
    int pkt = 0;

    for (int kt = 0; kt <= ktmax; kt++) {
        __syncthreads();                 // all warps done with buffers being overwritten
        if (kt < ktmax) load_kv((kt+1)&1, (kt+1)%3, kt+1);
        CP_COMMIT();
        CP_WAITG1();                     // K(kt), V(kt) complete
        __syncthreads();                 // visibility across threads

        bool act = (kt*FKT <= grow + 15);
        float s[8][4];
        if (act) {
            const float* Ks = Kst + (kt&1)*FKT*FST;
#pragma unroll
            for (int nj = 0; nj < 8; nj++)
#pragma unroll
                for (int r = 0; r < 4; r++) s[nj][r] = 0.f;
#pragma unroll
            for (int k0 = 0; k0 < HDIM; k0 += 8) {
                unsigned a0 = __float_as_uint(Qs[(wrow+g  )*FST + k0+tg]);
                unsigned a1 = __float_as_uint(Qs[(wrow+g+8)*FST + k0+tg]);
                unsigned a2 = __float_as_uint(Qs[(wrow+g  )*FST + k0+tg+4]);
                unsigned a3 = __float_as_uint(Qs[(wrow+g+8)*FST + k0+tg+4]);
#pragma unroll
                for (int nj = 0; nj < 8; nj++) {
                    unsigned b0 = __float_as_uint(Ks[(nj*8+g)*FST + k0+tg]);
                    unsigned b1 = __float_as_uint(Ks[(nj*8+g)*FST + k0+tg+4]);
                    mma_tf32(s[nj], a0, a1, a2, a3, b0, b1);
                }
            }
        }

        // PV of previous tile — overlaps QK result drain + upcoming softmax
        if (pend) {
            const float* Vs = Vst + (pkt%3)*FKT*FST;
#pragma unroll
            for (int k0 = 0; k0 < FKT; k0 += 8) {
                unsigned a0 = __float_as_uint(Ps[(wrow+g  )*FST + k0+tg]);
                unsigned a1 = __float_as_uint(Ps[(wrow+g+8)*FST + k0+tg]);
                unsigned a2 = __float_as_uint(Ps[(wrow+g  )*FST + k0+tg+4]);
                unsigned a3 = __float_as_uint(Ps[(wrow+g+8)*FST + k0+tg+4]);
#pragma unroll
                for (int nj = 0; nj < 8; nj++) {
                    unsigned b0 = __float_as_uint(Vs[(k0+tg  )*FST + nj*8+g]);
                    unsigned b1 = __float_as_uint(Vs[(k0+tg+4)*FST + nj*8+g]);
                    mma_tf32(o[nj], a0, a1, a2, a3, b0, b1);
                }
            }
            pend = false;
        }

        if (act) {
            if (kt >= 2*qb) {
                int r0 = grow + g, r1 = grow + g + 8;
#pragma unroll
                for (int nj = 0; nj < 8; nj++) {
                    int c = kt*FKT + nj*8 + 2*tg;
                    if (c     > r0) s[nj][0] = -1e30f;
                    if (c + 1 > r0) s[nj][1] = -1e30f;
                    if (c     > r1) s[nj][2] = -1e30f;
                    if (c + 1 > r1) s[nj][3] = -1e30f;
                }
            }
            float mt0 = -1e30f, mt1 = -1e30f;
#pragma unroll
            for (int nj = 0; nj < 8; nj++) {
                mt0 = fmaxf(mt0, fmaxf(s[nj][0], s[nj][1]));
                mt1 = fmaxf(mt1, fmaxf(s[nj][2], s[nj][3]));
            }
            mt0 = fmaxf(mt0, __shfl_xor_sync(0xffffffffu, mt0, 1));
            mt0 = fmaxf(mt0, __shfl_xor_sync(0xffffffffu, mt0, 2));
            mt1 = fmaxf(mt1, __shfl_xor_sync(0xffffffffu, mt1, 1));
            mt1 = fmaxf(mt1, __shfl_xor_sync(0xffffffffu, mt1, 2));
            float mn0 = fmaxf(m0, mt0), mn1 = fmaxf(m1, mt1);
            float c0 = __expf(m0 - mn0), c1 = __expf(m1 - mn1);
            l0 *= c0; l1 *= c1;
#pragma unroll
            for (int nj = 0; nj < 8; nj++) {
                o[nj][0] *= c0; o[nj][1] *= c0;
                o[nj][2] *= c1; o[nj][3] *= c1;
            }
            float rs0 = 0.f, rs1 = 0.f;
#pragma unroll
            for (int nj = 0; nj < 8; nj++) {
                float p0 = __expf(s[nj][0] - mn0);
                float p1 = __expf(s[nj][1] - mn0);
                float p2 = __expf(s[nj][2] - mn1);
                float p3 = __expf(s[nj][3] - mn1);
                rs0 += p0 + p1; rs1 += p2 + p3;
                int col = nj*8 + 2*tg;
                *(float2*)&Ps[(wrow+g  )*FST + col] = make_float2(p0, p1);
                *(float2*)&Ps[(wrow+g+8)*FST + col] = make_float2(p2, p3);
            }
            rs0 += __shfl_xor_sync(0xffffffffu, rs0, 1);
            rs0 += __shfl_xor_sync(0xffffffffu, rs0, 2);
            rs1 += __shfl_xor_sync(0xffffffffu, rs1, 1);
            rs1 += __shfl_xor_sync(0xffffffffu, rs1, 2);
            l0 += rs0; l1 += rs1;
            m0 = mn0; m1 = mn1;
            __syncwarp();    // warp reads back only its own P rows
            pend = true;
            pkt  = kt;
        }
    }

    // flush last pending PV
    if (pend) {
        const float* Vs = Vst + (pkt%3)*FKT*FST;
#pragma unroll
        for (int k0 = 0; k0 < FKT; k0 += 8) {
            unsigned a0 = __float_as_uint(Ps[(wrow+g  )*FST + k0+tg]);
            unsigned a1 = __float_as_uint(Ps[(wrow+g+8)*FST + k0+tg]);
            unsigned a2 = __float_as_uint(Ps[(wrow+g  )*FST + k0+tg+4]);
            unsigned a3 = __float_as_uint(Ps[(wrow+g+8)*FST + k0+tg+4]);
#pragma unroll
            for (int nj = 0; nj < 8; nj++) {
                unsigned b0 = __float_as_uint(Vs[(k0+tg  )*FST + nj*8+g]);
                unsigned b1 = __float_as_uint(Vs[(k0+tg+4)*FST + nj*8+g]);
                mma_tf32(o[nj], a0, a1, a2, a3, b0, b1);
            }
        }
    }

    float il0 = 1.f/l0, il1 = 1.f/l1;
    size_t tok0 = (size_t)(b*SS + qb*FQ + wrow + g);
    size_t tok1 = tok0 + 8;
#pragma unroll
    for (int nj = 0; nj < 8; nj++) {
        int col = h*HDIM + nj*8 + 2*tg;
        *(float2*)(out + tok0*DM + col) = make_float2(o[nj][0]*il0, o[nj][1]*il0);
        *(float2*)(out + tok1*DM + col) = make_float2(o[nj][2]*il1, o[nj][3]*il1);
    }
}

// ---------------- router ----------------
__global__ void router_kernel(const float* __restrict__ x2, const float* __restrict__ rw) {
    int t = (blockIdx.x*blockDim.x + threadIdx.x) >> 5;
    int lane = threadIdx.x & 31;
    if (t >= NT) return;
    const float* xr = x2 + (size_t)t*DM;
    float acc[NE];
#pragma unroll
    for (int e = 0; e < NE; e++) acc[e] = 0.f;
    for (int d = lane; d < DM; d += 32) {
        float xv = xr[d];
        float4 r0 = ((const float4*)rw)[d*2];
        float4 r1 = ((const float4*)rw)[d*2+1];
        acc[0]+=xv*r0.x; acc[1]+=xv*r0.y; acc[2]+=xv*r0.z; acc[3]+=xv*r0.w;
        acc[4]+=xv*r1.x; acc[5]+=xv*r1.y; acc[6]+=xv*r1.z; acc[7]+=xv*r1.w;
    }
#pragma unroll
    for (int o = 16; o; o >>= 1)
#pragma unroll
        for (int e = 0; e < NE; e++)
            acc[e] += __shfl_xor_sync(0xffffffffu, acc[e], o);
    if (lane == 0) {
        int e0 = 0; float m0 = acc[0];
#pragma unroll
        for (int e = 1; e < NE; e++) if (acc[e] > m0) { m0 = acc[e]; e0 = e; }
        int e1 = -1; float m1 = -3.4e38f;
#pragma unroll
        for (int e = 0; e < NE; e++) if (e != e0 && acc[e] > m1) { m1 = acc[e]; e1 = e; }
        float p1 = expf(m1 - m0);
        float w0 = 1.f / (1.f + p1);
        float w1 = p1 / (1.f + p1);
        g_top_e[2*t] = e0; g_top_e[2*t+1] = e1;
        g_top_w[2*t] = w0; g_top_w[2*t+1] = w1;
        atomicAdd(&g_cnt[e0], 1);
        atomicAdd(&g_cnt[e1], 1);
    }
}

__global__ void moe_init_kernel() {
    int i = blockIdx.x*blockDim.x + threadIdx.x;
    if (i < NE) { g_cnt[i] = 0; g_fill[i] = 0; }
    if (i < CAP) g_perm[i] = -1;
}

__global__ void segoff_kernel() {
    int off = 0;
    for (int e = 0; e < NE; e++) {
        g_segoff[e] = off;
        off += ((g_cnt[e] + 127) >> 7) << 7;
    }
    g_segoff[NE] = off;
    g_total = off;
}

__global__ void fill_kernel() {
    int i = blockIdx.x*blockDim.x + threadIdx.x;
    if (i >= NT*2) return;
    int e = g_top_e[i];
    int pos = g_segoff[e] + atomicAdd(&g_fill[e], 1);
    g_perm[pos] = i >> 1;
    g_tok_slot[i] = pos;
}

__global__ void combine_kernel(float* __restrict__ out) {
    int i = blockIdx.x*blockDim.x + threadIdx.x;
    int n = i >> 8, d4 = i & 255;
    int s0 = g_tok_slot[2*n], s1 = g_tok_slot[2*n+1];
    float w0 = g_top_w[2*n], w1 = g_top_w[2*n+1];
    float4 hv = *(float4*)&g_hidden[(size_t)n*DM + d4*4];
    float4 y0 = *(float4*)&g_y[(size_t)s0*DM + d4*4];
    float4 y1 = *(float4*)&g_y[(size_t)s1*DM + d4*4];
    float4 r;
    r.x = hv.x + w0*y0.x + w1*y1.x;
    r.y = hv.y + w0*y0.y + w1*y1.y;
    r.z = hv.z + w0*y0.z + w1*y1.z;
    r.w = hv.w + w0*y0.w + w1*y1.w;
    *(float4*)&out[(size_t)n*DM + d4*4] = r;
}

// ---------------- launch ----------------
extern "C" void kernel_launch(void* const* d_in, const int* in_sizes, int n_in,
                              void* d_out, int out_size) {
    const float* hs   = (const float*)d_in[0];
    const float* ln1w = (const float*)d_in[1];
    const float* ln2w = (const float*)d_in[2];
    const float* wqkv = (const float*)d_in[3];
    const float* outw = (const float*)d_in[4];
    const float* rw   = (const float*)d_in[5];
    const float* w1   = (const float*)d_in[6];
    const float* v1   = (const float*)d_in[7];
    const float* w2   = (const float*)d_in[8];
    float* out = (float*)d_out;

    float *px1, *pqkv, *pattn, *phid, *px2, *ph1, *py;
    cudaGetSymbolAddress((void**)&px1,  g_x1);
    cudaGetSymbolAddress((void**)&pqkv, g_qkv);
    cudaGetSymbolAddress((void**)&pattn,g_attn);
    cudaGetSymbolAddress((void**)&phid, g_hidden);
    cudaGetSymbolAddress((void**)&px2,  g_x2);
    cudaGetSymbolAddress((void**)&ph1,  g_h1);
    cudaGetSymbolAddress((void**)&py,   g_y);

    cudaFuncSetAttribute(flash_tc_kernel,
                         cudaFuncAttributeMaxDynamicSharedMemorySize, FLASH_SMEM);
    cudaFuncSetAttribute(sgemm_tc<1,false,false,false>,
                         cudaFuncAttributeMaxDynamicSharedMemorySize, GEMM_SMEM);
    cudaFuncSetAttribute(sgemm_tc<2,false,false,false>,
                         cudaFuncAttributeMaxDynamicSharedMemorySize, GEMM_SMEM);
    cudaFuncSetAttribute(sgemm_tc<0,false,false,true>,
                         cudaFuncAttributeMaxDynamicSharedMemorySize, GEMM_SMEM);
    cudaFuncSetAttribute(up_gemm,
                         cudaFuncAttributeMaxDynamicSharedMemorySize, UP_SMEM);

    // LN1 -> QKV(clip) -> RoPE -> attention -> out-proj(+resid)
    ln_kernel<<<NT, 256>>>(hs, ln1w, px1);
    sgemm_tc<1,false,false,false><<<dim3(QKVN/128, NT/128), 256, GEMM_SMEM>>>(
        px1, wqkv, pqkv, nullptr, NT, QKVN, DM, 0);
    ropetab_kernel<<<1, 32>>>();
    rope_kernel<<<(NT*20*32 + 255)/256, 256>>>();
    flash_tc_kernel<<<dim3(SS/FQ, BB*NH), 256, FLASH_SMEM>>>(pqkv, pattn);
    sgemm_tc<2,false,false,false><<<dim3(DM/128, NT/128), 256, GEMM_SMEM>>>(
        pattn, outw, phid, hs, NT, DM, DM, 0);

    // LN2 -> router -> top-2 dispatch
    ln_kernel<<<NT, 256>>>(phid, ln2w, px2);
    moe_init_kernel<<<(CAP + 255)/256, 256>>>();
    router_kernel<<<NT/8, 256>>>(px2, rw);
    segoff_kernel<<<1, 1>>>();
    fill_kernel<<<(NT*2 + 255)/256, 256>>>();

    // MoE: fused dual-B up (silu in epilogue), then down
    up_gemm<<<dim3(FF/128, CAP/128), 256, UP_SMEM>>>(px2, w1, v1, ph1);
    sgemm_tc<0,false,false,true><<<dim3(DM/128, CAP/128), 256, GEMM_SMEM>>>(
        ph1, w2, py, nullptr, CAP, DM, FF, (long)FF*DM);

    // resid2 + gated expert outputs
    combine_kernel<<<NT, 256>>>(out);
}

// round 10
// speedup vs baseline: 4.8409x; 1.4527x over previous
#include <cuda_runtime.h>
#include <cuda_fp16.h>
#include <math.h>

// ---------------- problem constants ----------------
#define BB 2
#define SS 2048
#define DM 1024
#define NH 16
#define NKV 4
#define HDIM 64
#define NE 8
#define FF 2048
#define NT (BB*SS)                    // 4096 tokens
#define QKVN (DM + 2*NKV*HDIM)        // 1536
#define CAP (2*NT + NE*128)           // 9216 padded MoE slots
#define SCALEQ 0.125f
#define CLIPV 8.0f

// ---------------- device scratch ----------------
__device__ float g_qkv[NT*QKVN];
__device__ float g_hidden[NT*DM];
__device__ float g_x2[NT*DM];
__device__ int   g_top_e[NT*2];
__device__ float g_top_w[NT*2];
__device__ int   g_cnt[NE];
__device__ int   g_fill[NE];
__device__ int   g_segoff[NE+1];
__device__ int   g_total;
__device__ int   g_perm[CAP];
__device__ int   g_tok_slot[NT*2];
__device__ float g_y[CAP*DM];
__device__ float g_invfreq[32];
// fp16 buffers
__device__ __half g_x1h[NT*DM];
__device__ __half g_x2h[NT*DM];
__device__ __half g_attnh[NT*DM];
__device__ __half g_h1h[CAP*FF];
__device__ __half g_wqkvh[QKVN*DM];   // [N][K]
__device__ __half g_outwh[DM*DM];     // [N][K]
__device__ __half g_w1h[NE*FF*DM];    // [N][K] per expert (native)
__device__ __half g_v1h[NE*FF*DM];
__device__ __half g_w2h[NE*DM*FF];    // [N=DM][K=FF] per expert (transposed)

// ---------------- weight conversion ----------------
__global__ void conv_h(const float* __restrict__ in, __half* __restrict__ out, int n4) {
    int i = blockIdx.x*blockDim.x + threadIdx.x;
    if (i >= n4) return;
    float4 v = ((const float4*)in)[i];
    ((half2*)out)[i*2]   = __floats2half2_rn(v.x, v.y);
    ((half2*)out)[i*2+1] = __floats2half2_rn(v.z, v.w);
}
__global__ void convT_h(const float* __restrict__ in, __half* __restrict__ out,
                        int R, int C) {
    __shared__ float t[32][33];
    int e = blockIdx.z;
    in  += (size_t)e*R*C;
    out += (size_t)e*R*C;
    int bx = blockIdx.x*32, by = blockIdx.y*32;
    int tx = threadIdx.x, ty = threadIdx.y;
#pragma unroll
    for (int k = 0; k < 32; k += 8)
        t[ty+k][tx] = in[(size_t)(by+ty+k)*C + bx+tx];
    __syncthreads();
#pragma unroll
    for (int k = 0; k < 32; k += 8)
        out[(size_t)(bx+ty+k)*R + by+tx] = __float2half_rn(t[tx][ty+k]);
}

// ---------------- layernorm (fp32 in; optional fp32 + fp16 out) ----------------
template<bool OUTF, bool OUTH>
__global__ void ln_kernel(const float* __restrict__ x, const float* __restrict__ w,
                          float* __restrict__ outf, __half* __restrict__ outh) {
    int row = blockIdx.x, tid = threadIdx.x;
    float4 v = ((const float4*)(x + (size_t)row*DM))[tid];
    float s = v.x+v.y+v.z+v.w;
    float q = v.x*v.x+v.y*v.y+v.z*v.z+v.w*v.w;
#pragma unroll
    for (int o = 16; o; o >>= 1) {
        s += __shfl_xor_sync(0xffffffffu, s, o);
        q += __shfl_xor_sync(0xffffffffu, q, o);
    }
    __shared__ float ssm[8], qsm[8];
    if ((tid & 31) == 0) { ssm[tid>>5] = s; qsm[tid>>5] = q; }
    __syncthreads();
    float ts = 0.f, tq = 0.f;
#pragma unroll
    for (int i = 0; i < 8; i++) { ts += ssm[i]; tq += qsm[i]; }
    float mu  = ts * (1.f/DM);
    float var = tq * (1.f/DM) - mu*mu;
    float rs  = rsqrtf(var + 1e-5f);
    float4 wv = ((const float4*)w)[tid];
    float4 r;
    r.x = (v.x-mu)*rs*wv.x; r.y = (v.y-mu)*rs*wv.y;
    r.z = (v.z-mu)*rs*wv.z; r.w = (v.w-mu)*rs*wv.w;
    if (OUTF) ((float4*)(outf + (size_t)row*DM))[tid] = r;
    if (OUTH) {
        ((half2*)(outh + (size_t)row*DM))[tid*2]   = __floats2half2_rn(r.x, r.y);
        ((half2*)(outh + (size_t)row*DM))[tid*2+1] = __floats2half2_rn(r.z, r.w);
    }
}

// ---------------- mma / cp.async helpers ----------------
__device__ __forceinline__ void mma_tf32(float* c,
        unsigned a0, unsigned a1, unsigned a2, unsigned a3,
        unsigned b0, unsigned b1) {
    asm volatile("mma.sync.aligned.m16n8k8.row.col.f32.tf32.tf32.f32 "
        "{%0,%1,%2,%3}, {%4,%5,%6,%7}, {%8,%9}, {%0,%1,%2,%3};"
        : "+f"(c[0]), "+f"(c[1]), "+f"(c[2]), "+f"(c[3])
        : "r"(a0), "r"(a1), "r"(a2), "r"(a3), "r"(b0), "r"(b1));
}
__device__ __forceinline__ void mma_f16(float* c,
        unsigned a0, unsigned a1, unsigned a2, unsigned a3,
        unsigned b0, unsigned b1) {
    asm volatile("mma.sync.aligned.m16n8k16.row.col.f32.f16.f16.f32 "
        "{%0,%1,%2,%3}, {%4,%5,%6,%7}, {%8,%9}, {%0,%1,%2,%3};"
        : "+f"(c[0]), "+f"(c[1]), "+f"(c[2]), "+f"(c[3])
        : "r"(a0), "r"(a1), "r"(a2), "r"(a3), "r"(b0), "r"(b1));
}
__device__ __forceinline__ void cp16(void* smem_dst, const void* gsrc, int src_bytes) {
    unsigned sa = (unsigned)__cvta_generic_to_shared(smem_dst);
    asm volatile("cp.async.cg.shared.global [%0], [%1], 16, %2;\n"
                 :: "r"(sa), "l"(gsrc), "r"(src_bytes));
}
#define CP_COMMIT() asm volatile("cp.async.commit_group;\n")
#define CP_WAITG2() asm volatile("cp.async.wait_group 2;\n")
#define CP_WAITG1() asm volatile("cp.async.wait_group 1;\n")

// ---------------- fp16 GEMM: 128x128 tile, K=32 halfs/slab, 4-stage cp.async ------
// A [M,K] half row-major (opt gathered), B [N,K] half K-major (opt expert), C fp32.
// EPI: 0 none, 1 clip, 2 +resid
#define HSTRW 20                    // words per 40-half row
#define HSLABW (128*HSTRW)          // 2560 words per slab
#define HNSTG 4
#define HGEMM_SMEM (HNSTG*2*HSLABW*4)   // 81920 B
template<int EPI, bool GATHER, bool EXPERT>
__global__ void __launch_bounds__(256, 2)
hgemm(const __half* __restrict__ A, const __half* __restrict__ Bm,
      float* __restrict__ C, const float* __restrict__ resid,
      int N, int K, long ldbE) {
    int mbase = blockIdx.y * 128;
    if (EXPERT) {
        if (mbase >= g_total) return;
        int e = 0;
#pragma unroll
        for (int i = 0; i < NE; i++) if (g_segoff[i+1] <= mbase) e = i + 1;
        Bm += (size_t)e * ldbE;
    }
    int nbase = blockIdx.x * 128;
    extern __shared__ unsigned smw[];
    int tid  = threadIdx.x;
    int lane = tid & 31, warp = tid >> 5;
    int wM = (warp & 1) * 64;
    int wN = (warp >> 1) * 32;
    int g  = lane >> 2, tg = lane & 3;

    int ar = tid >> 1, ac = (tid & 1) * 16;   // row, first half index
    const __half* arow;
    int asz = 16;
    if (GATHER) {
        int tok = g_perm[mbase + ar];
        asz  = (tok >= 0) ? 16 : 0;
        arow = A + (size_t)(tok >= 0 ? tok : 0) * K;
    } else {
        arow = A + (size_t)(mbase + ar) * K;
    }
    const __half* brow = Bm + (size_t)(nbase + ar) * K;

    float acc[4][4][4];
#pragma unroll
    for (int mi = 0; mi < 4; mi++)
#pragma unroll
        for (int nj = 0; nj < 4; nj++)
#pragma unroll
            for (int r = 0; r < 4; r++) acc[mi][nj][r] = 0.f;

    auto load_slab = [&](int s, int kb) {
        unsigned* As = smw + s*(2*HSLABW);
        unsigned* Bs = As + HSLABW;
        cp16(&As[ar*HSTRW + ac/2],     arow + kb + ac,     asz);
        cp16(&As[ar*HSTRW + ac/2 + 4], arow + kb + ac + 8, asz);
        cp16(&Bs[ar*HSTRW + ac/2],     brow + kb + ac,     16);
        cp16(&Bs[ar*HSTRW + ac/2 + 4], brow + kb + ac + 8, 16);
    };

    int ns = K >> 5;
#pragma unroll
    for (int j = 0; j < 3; j++) { load_slab(j, j*32); CP_COMMIT(); }

    for (int i = 0; i < ns; i++) {
        int s = i & (HNSTG-1);
        CP_WAITG2();
        __syncthreads();
        int j = i + 3;
        if (j < ns) load_slab(j & (HNSTG-1), j*32);
        CP_COMMIT();
        const unsigned* as = smw + s*(2*HSLABW);
        const unsigned* bs = as + HSLABW;
#pragma unroll
        for (int ks = 0; ks < 2; ks++) {
            int k0w = ks * 8;    // 16 halfs per step = 8 words
            unsigned bf[4][2];
#pragma unroll
            for (int nj = 0; nj < 4; nj++) {
                int n = wN + nj*8 + g;
                bf[nj][0] = bs[n*HSTRW + k0w + tg];
                bf[nj][1] = bs[n*HSTRW + k0w + 4 + tg];
            }
#pragma unroll
            for (int mi = 0; mi < 4; mi++) {
                int m = wM + mi*16 + g;
                unsigned a0 = as[m*HSTRW + k0w + tg];
                unsigned a1 = as[(m+8)*HSTRW + k0w + tg];
                unsigned a2 = as[m*HSTRW + k0w + 4 + tg];
                unsigned a3 = as[(m+8)*HSTRW + k0w + 4 + tg];
#pragma unroll
                for (int nj = 0; nj < 4; nj++)
                    mma_f16(acc[mi][nj], a0, a1, a2, a3, bf[nj][0], bf[nj][1]);
            }
        }
    }
    // ---- epilogue (fp32 out) ----
#pragma unroll
    for (int mi = 0; mi < 4; mi++) {
#pragma unroll
        for (int nj = 0; nj < 4; nj++) {
            int r0 = mbase + wM + mi*16 + g;
            int r1 = r0 + 8;
            int c  = nbase + wN + nj*8 + tg*2;
            float v0 = acc[mi][nj][0], v1 = acc[mi][nj][1];
            float v2 = acc[mi][nj][2], v3 = acc[mi][nj][3];
            if (EPI == 1) {
                v0 = fminf(fmaxf(v0,-CLIPV),CLIPV); v1 = fminf(fmaxf(v1,-CLIPV),CLIPV);
                v2 = fminf(fmaxf(v2,-CLIPV),CLIPV); v3 = fminf(fmaxf(v3,-CLIPV),CLIPV);
            }
            if (EPI == 2) {
                float2 r0v = *(const float2*)(resid + (size_t)r0*N + c);
                float2 r1v = *(const float2*)(resid + (size_t)r1*N + c);
                v0 += r0v.x; v1 += r0v.y; v2 += r1v.x; v3 += r1v.y;
            }
            *(float2*)(C + (size_t)r0*N + c) = make_float2(v0, v1);
            *(float2*)(C + (size_t)r1*N + c) = make_float2(v2, v3);
        }
    }
}

// ---------------- fp16 dual-B up GEMM: h1 = silu(x@w1^T)*(x@v1^T), fp16 out -------
#define UNSTG 4
#define UP_SMEM (UNSTG*3*HSLABW*4)     // 122880 B
__global__ void __launch_bounds__(256, 1)
up_hgemm(const __half* __restrict__ A, const __half* __restrict__ Bw,
         const __half* __restrict__ Bv, __half* __restrict__ C) {
    const int N = FF, K = DM;
    int mbase = blockIdx.y * 128;
    if (mbase >= g_total) return;
    int e = 0;
#pragma unroll
    for (int i = 0; i < NE; i++) if (g_segoff[i+1] <= mbase) e = i + 1;
    Bw += (size_t)e * FF * DM;
    Bv += (size_t)e * FF * DM;
    int nbase = blockIdx.x * 128;
    extern __shared__ unsigned smw[];
    int tid  = threadIdx.x;
    int lane = tid & 31, warp = tid >> 5;
    int wM = (warp & 1) * 64;
    int wN = (warp >> 1) * 32;
    int g  = lane >> 2, tg = lane & 3;

    int ar = tid >> 1, ac = (tid & 1) * 16;
    int tok = g_perm[mbase + ar];
    int asz  = (tok >= 0) ? 16 : 0;
    const __half* arow = A + (size_t)(tok >= 0 ? tok : 0) * K;
    const __half* wrow = Bw + (size_t)(nbase + ar) * K;
    const __half* vrow = Bv + (size_t)(nbase + ar) * K;

    float accw[4][4][4], accv[4][4][4];
#pragma unroll
    for (int mi = 0; mi < 4; mi++)
#pragma unroll
        for (int nj = 0; nj < 4; nj++)
#pragma unroll
            for (int r = 0; r < 4; r++) { accw[mi][nj][r] = 0.f; accv[mi][nj][r] = 0.f; }

    auto load_slab = [&](int s, int kb) {
        unsigned* As = smw + s*(3*HSLABW);
        unsigned* Ws = As + HSLABW;
        unsigned* Vs = Ws + HSLABW;
        cp16(&As[ar*HSTRW + ac/2],     arow + kb + ac,     asz);
        cp16(&As[ar*HSTRW + ac/2 + 4], arow + kb + ac + 8, asz);
        cp16(&Ws[ar*HSTRW + ac/2],     wrow + kb + ac,     16);
        cp16(&Ws[ar*HSTRW + ac/2 + 4], wrow + kb + ac + 8, 16);
        cp16(&Vs[ar*HSTRW + ac/2],     vrow + kb + ac,     16);
        cp16(&Vs[ar*HSTRW + ac/2 + 4], vrow + kb + ac + 8, 16);
    };

    const int ns = K >> 5;   // 32
#pragma unroll
    for (int j = 0; j < 3; j++) { load_slab(j, j*32); CP_COMMIT(); }

    for (int i = 0; i < ns; i++) {
        int s = i & (UNSTG-1);
        CP_WAITG2();
        __syncthreads();
        int j = i + 3;
        if (j < ns) load_slab(j & (UNSTG-1), j*32);
        CP_COMMIT();
        const unsigned* as = smw + s*(3*HSLABW);
        const unsigned* ws = as + HSLABW;
        const unsigned* vs = ws + HSLABW;
#pragma unroll
        for (int ks = 0; ks < 2; ks++) {
            int k0w = ks * 8;
            unsigned bw[4][2], bv[4][2];
#pragma unroll
            for (int nj = 0; nj < 4; nj++) {
                int n = wN + nj*8 + g;
                bw[nj][0] = ws[n*HSTRW + k0w + tg];
                bw[nj][1] = ws[n*HSTRW + k0w + 4 + tg];
                bv[nj][0] = vs[n*HSTRW + k0w + tg];
                bv[nj][1] = vs[n*HSTRW + k0w + 4 + tg];
            }
#pragma unroll
            for (int mi = 0; mi < 4; mi++) {
                int m = wM + mi*16 + g;
                unsigned a0 = as[m*HSTRW + k0w + tg];
                unsigned a1 = as[(m+8)*HSTRW + k0w + tg];
                unsigned a2 = as[m*HSTRW + k0w + 4 + tg];
                unsigned a3 = as[(m+8)*HSTRW + k0w + 4 + tg];
#pragma unroll
                for (int nj = 0; nj < 4; nj++) {
                    mma_f16(accw[mi][nj], a0, a1, a2, a3, bw[nj][0], bw[nj][1]);
                    mma_f16(accv[mi][nj], a0, a1, a2, a3, bv[nj][0], bv[nj][1]);
                }
            }
        }
    }
    // ---- epilogue: h = silu(accw)*accv, fp16 out ----
#pragma unroll
    for (int mi = 0; mi < 4; mi++) {
#pragma unroll
        for (int nj = 0; nj < 4; nj++) {
            int r0 = mbase + wM + mi*16 + g;
            int r1 = r0 + 8;
            int c  = nbase + wN + nj*8 + tg*2;
            float w0 = accw[mi][nj][0], w1 = accw[mi][nj][1];
            float w2 = accw[mi][nj][2], w3 = accw[mi][nj][3];
            float v0 = accv[mi][nj][0] * (w0 / (1.f + __expf(-w0)));
            float v1 = accv[mi][nj][1] * (w1 / (1.f + __expf(-w1)));
            float v2 = accv[mi][nj][2] * (w2 / (1.f + __expf(-w2)));
            float v3 = accv[mi][nj][3] * (w3 / (1.f + __expf(-w3)));
            *(half2*)(C + (size_t)r0*N + c) = __floats2half2_rn(v0, v1);
            *(half2*)(C + (size_t)r1*N + c) = __floats2half2_rn(v2, v3);
        }
    }
}

// ---------------- RoPE ----------------
__global__ void ropetab_kernel() {
    int i = threadIdx.x;
    if (i < 32) g_invfreq[i] = (float)pow(10000.0, -(double)i / 32.0);
}
__global__ void rope_kernel() {
    int idx = blockIdx.x*blockDim.x + threadIdx.x;
    if (idx >= NT*20*32) return;
    int i    = idx & 31;
    int head = (idx >> 5) % 20;
    int n    = idx / (32*20);
    int s    = n & (SS - 1);
    float ang = (float)s * g_invfreq[i];
    float sn, cs;
    sincosf(ang, &sn, &cs);
    float* base = g_qkv + (size_t)n*QKVN + (head < NH ? head*HDIM : DM + (head-NH)*HDIM);
    float x1 = base[i], x2 = base[i+32];
    base[i]    = x1*cs - x2*sn;
    base[i+32] = x1*sn + x2*cs;
}

// ---------------- flash attention (tf32, pipelined; fp16 output) ----------------
#define FQ 128
#define FKT 64
#define FST 68
#define FLASH_SMEM ((FQ + 2*FKT + 3*FKT + FQ)*FST*4)   // 156672 B
__global__ void __launch_bounds__(256)
flash_tc_kernel(const float* __restrict__ qkv, __half* __restrict__ out) {
    extern __shared__ float sm[];
    float* Qs = sm;
    float* Kst = Qs + FQ*FST;
    float* Vst = Kst + 2*FKT*FST;
    float* Ps = Vst + 3*FKT*FST;
    int qb = gridDim.x - 1 - blockIdx.x;
    int bh = blockIdx.y;
    int b = bh >> 4, h = bh & 15, kh = h >> 2;
    int tid = threadIdx.x, lane = tid & 31, warp = tid >> 5;
    int g = lane >> 2, tg = lane & 3;

    const float* qp = qkv + (size_t)(b*SS + qb*FQ)*QKVN + h*HDIM;
    for (int t = tid; t < FQ*16; t += 256) {
        int r = t >> 4, c4 = (t & 15)*4;
        float4 v = *(const float4*)(qp + (size_t)r*QKVN + c4);
        v.x *= SCALEQ; v.y *= SCALEQ; v.z *= SCALEQ; v.w *= SCALEQ;
        *(float4*)&Qs[r*FST + c4] = v;
    }

    int kvr = tid >> 2, kvc = (tid & 3) * 4;
    const float* kbase = qkv + (size_t)(b*SS)*QKVN + DM + kh*HDIM;
    auto load_kv = [&](int kst, int vst, int kt) {
        const float* kp = kbase + (size_t)(kt*FKT + kvr)*QKVN;
        const float* vp = kp + NKV*HDIM;
        float* kd = Kst + kst*FKT*FST + kvr*FST;
        float* vd = Vst + vst*FKT*FST + kvr*FST;
#pragma unroll
        for (int q = 0; q < 4; q++) {
            cp16(kd + (kvc+q)*4, kp + (kvc+q)*4, 16);
            cp16(vd + (kvc+q)*4, vp + (kvc+q)*4, 16);
        }
    };

    int wrow = warp*16;
    int grow = qb*FQ + wrow;

    float m0 = -1e30f, m1 = -1e30f, l0 = 0.f, l1 = 0.f;
    float o[8][4];
#pragma unroll
    for (int nj = 0; nj < 8; nj++)
#pragma unroll
        for (int r = 0; r < 4; r++) o[nj][r] = 0.f;

    int ktmax = 2*qb + 1;
    load_kv(0, 0, 0);
    CP_COMMIT();

    bool pend = false;
    int pkt = 0;

    for (int kt = 0; kt <= ktmax; kt++) {
        __syncthreads();
        if (kt < ktmax) load_kv((kt+1)&1, (kt+1)%3, kt+1);
        CP_COMMIT();
        CP_WAITG1();
        __syncthreads();

        bool act = (kt*FKT <= grow + 15);
        float s[8][4];
        if (act) {
            const float* Ks = Kst + (kt&1)*FKT*FST;
#pragma unroll
            for (int nj = 0; nj < 8; nj++)
#pragma unroll
                for (int r = 0; r < 4; r++) s[nj][r] = 0.f;
#pragma unroll
            for (int k0 = 0; k0 < HDIM; k0 += 8) {
                unsigned a0 = __float_as_uint(Qs[(wrow+g  )*FST + k0+tg]);
                unsigned a1 = __float_as_uint(Qs[(wrow+g+8)*FST + k0+tg]);
                unsigned a2 = __float_as_uint(Qs[(wrow+g  )*FST + k0+tg+4]);
                unsigned a3 = __float_as_uint(Qs[(wrow+g+8)*FST + k0+tg+4]);
#pragma unroll
                for (int nj = 0; nj < 8; nj++) {
                    unsigned b0 = __float_as_uint(Ks[(nj*8+g)*FST + k0+tg]);
                    unsigned b1 = __float_as_uint(Ks[(nj*8+g)*FST + k0+tg+4]);
                    mma_tf32(s[nj], a0, a1, a2, a3, b0, b1);
                }
            }
        }

        if (pend) {
            const float* Vs = Vst + (pkt%3)*FKT*FST;
#pragma unroll
            for (int k0 = 0; k0 < FKT; k0 += 8) {
                unsigned a0 = __float_as_uint(Ps[(wrow+g  )*FST + k0+tg]);
                unsigned a1 = __float_as_uint(Ps[(wrow+g+8)*FST + k0+tg]);
                unsigned a2 = __float_as_uint(Ps[(wrow+g  )*FST + k0+tg+4]);
                unsigned a3 = __float_as_uint(Ps[(wrow+g+8)*FST + k0+tg+4]);
#pragma unroll
                for (int nj = 0; nj < 8; nj++) {
                    unsigned b0 = __float_as_uint(Vs[(k0+tg  )*FST + nj*8+g]);
                    unsigned b1 = __float_as_uint(Vs[(k0+tg+4)*FST + nj*8+g]);
                    mma_tf32(o[nj], a0, a1, a2, a3, b0, b1);
                }
            }
            pend = false;
        }

        if (act) {
            if (kt >= 2*qb) {
                int r0 = grow + g, r1 = grow + g + 8;
#pragma unroll
                for (int nj = 0; nj < 8; nj++) {
                    int c = kt*FKT + nj*8 + 2*tg;
                    if (c     > r0) s[nj][0] = -1e30f;
                    if (c + 1 > r0) s[nj][1] = -1e30f;
                    if (c     > r1) s[nj][2] = -1e30f;
                    if (c + 1 > r1) s[nj][3] = -1e30f;
                }
            }
            float mt0 = -1e30f, mt1 = -1e30f;
#pragma unroll
            for (int nj = 0; nj < 8; nj++) {
                mt0 = fmaxf(mt0, fmaxf(s[nj][0], s[nj][1]));
                mt1 = fmaxf(mt1, fmaxf(s[nj][2], s[nj][3]));
            }
            mt0 = fmaxf(mt0, __shfl_xor_sync(0xffffffffu, mt0, 1));
            mt0 = fmaxf(mt0, __shfl_xor_sync(0xffffffffu, mt0, 2));
            mt1 = fmaxf(mt1, __shfl_xor_sync(0xffffffffu, mt1, 1));
            mt1 = fmaxf(mt1, __shfl_xor_sync(0xffffffffu, mt1, 2));
            float mn0 = fmaxf(m0, mt0), mn1 = fmaxf(m1, mt1);
            float c0 = __expf(m0 - mn0), c1 = __expf(m1 - mn1);
            l0 *= c0; l1 *= c1;
#pragma unroll
            for (int nj = 0; nj < 8; nj++) {
                o[nj][0] *= c0; o[nj][1] *= c0;
                o[nj][2] *= c1; o[nj][3] *= c1;
            }
            float rs0 = 0.f, rs1 = 0.f;
#pragma unroll
            for (int nj = 0; nj < 8; nj++) {
                float p0 = __expf(s[nj][0] - mn0);
                float p1 = __expf(s[nj][1] - mn0);
                float p2 = __expf(s[nj][2] - mn1);
                float p3 = __expf(s[nj][3] - mn1);
                rs0 += p0 + p1; rs1 += p2 + p3;
                int col = nj*8 + 2*tg;
                *(float2*)&Ps[(wrow+g  )*FST + col] = make_float2(p0, p1);
                *(float2*)&Ps[(wrow+g+8)*FST + col] = make_float2(p2, p3);
            }
            rs0 += __shfl_xor_sync(0xffffffffu, rs0, 1);
            rs0 += __shfl_xor_sync(0xffffffffu, rs0, 2);
            rs1 += __shfl_xor_sync(0xffffffffu, rs1, 1);
            rs1 += __shfl_xor_sync(0xffffffffu, rs1, 2);
            l0 += rs0; l1 += rs1;
            m0 = mn0; m1 = mn1;
            __syncwarp();
            pend = true;
            pkt  = kt;
        }
    }

    if (pend) {
        const float* Vs = Vst + (pkt%3)*FKT*FST;
#pragma unroll
        for (int k0 = 0; k0 < FKT; k0 += 8) {
            unsigned a0 = __float_as_uint(Ps[(wrow+g  )*FST + k0+tg]);
            unsigned a1 = __float_as_uint(Ps[(wrow+g+8)*FST + k0+tg]);
            unsigned a2 = __float_as_uint(Ps[(wrow+g  )*FST + k0+tg+4]);
            unsigned a3 = __float_as_uint(Ps[(wrow+g+8)*FST + k0+tg+4]);
#pragma unroll
            for (int nj = 0; nj < 8; nj++) {
                unsigned b0 = __float_as_uint(Vs[(k0+tg  )*FST + nj*8+g]);
                unsigned b1 = __float_as_uint(Vs[(k0+tg+4)*FST + nj*8+g]);
                mma_tf32(o[nj], a0, a1, a2, a3, b0, b1);
            }
        }
    }

    float il0 = 1.f/l0, il1 = 1.f/l1;
    size_t tok0 = (size_t)(b*SS + qb*FQ + wrow + g);
    size_t tok1 = tok0 + 8;
#pragma unroll
    for (int nj = 0; nj < 8; nj++) {
        int col = h*HDIM + nj*8 + 2*tg;
        *(half2*)(out + tok0*DM + col) = __floats2half2_rn(o[nj][0]*il0, o[nj][1]*il0);
        *(half2*)(out + tok1*DM + col) = __floats2half2_rn(o[nj][2]*il1, o[nj][3]*il1);
    }
}

// ---------------- router (fp32 logits) ----------------
__global__ void router_kernel(const float* __restrict__ x2, const float* __restrict__ rw) {
    int t = (blockIdx.x*blockDim.x + threadIdx.x) >> 5;
    int lane = threadIdx.x & 31;
    if (t >= NT) return;
    const float* xr = x2 + (size_t)t*DM;
    float acc[NE];
#pragma unroll
    for (int e = 0; e < NE; e++) acc[e] = 0.f;
    for (int d = lane; d < DM; d += 32) {
        float xv = xr[d];
        float4 r0 = ((const float4*)rw)[d*2];
        float4 r1 = ((const float4*)rw)[d*2+1];
        acc[0]+=xv*r0.x; acc[1]+=xv*r0.y; acc[2]+=xv*r0.z; acc[3]+=xv*r0.w;
        acc[4]+=xv*r1.x; acc[5]+=xv*r1.y; acc[6]+=xv*r1.z; acc[7]+=xv*r1.w;
    }
#pragma unroll
    for (int o = 16; o; o >>= 1)
#pragma unroll
        for (int e = 0; e < NE; e++)
            acc[e] += __shfl_xor_sync(0xffffffffu, acc[e], o);
    if (lane == 0) {
        int e0 = 0; float m0 = acc[0];
#pragma unroll
        for (int e = 1; e < NE; e++) if (acc[e] > m0) { m0 = acc[e]; e0 = e; }
        int e1 = -1; float m1 = -3.4e38f;
#pragma unroll
        for (int e = 0; e < NE; e++) if (e != e0 && acc[e] > m1) { m1 = acc[e]; e1 = e; }
        float p1 = expf(m1 - m0);
        float w0 = 1.f / (1.f + p1);
        float w1 = p1 / (1.f + p1);
        g_top_e[2*t] = e0; g_top_e[2*t+1] = e1;
        g_top_w[2*t] = w0; g_top_w[2*t+1] = w1;
        atomicAdd(&g_cnt[e0], 1);
        atomicAdd(&g_cnt[e1], 1);
    }
}

__global__ void moe_init_kernel() {
    int i = blockIdx.x*blockDim.x + threadIdx.x;
    if (i < NE) { g_cnt[i] = 0; g_fill[i] = 0; }
    if (i < CAP) g_perm[i] = -1;
}

__global__ void segoff_kernel() {
    int off = 0;
    for (int e = 0; e < NE; e++) {
        g_segoff[e] = off;
        off += ((g_cnt[e] + 127) >> 7) << 7;
    }
    g_segoff[NE] = off;
    g_total = off;
}

__global__ void fill_kernel() {
    int i = blockIdx.x*blockDim.x + threadIdx.x;
    if (i >= NT*2) return;
    int e = g_top_e[i];
    int pos = g_segoff[e] + atomicAdd(&g_fill[e], 1);
    g_perm[pos] = i >> 1;
    g_tok_slot[i] = pos;
}

__global__ void combine_kernel(float* __restrict__ out) {
    int i = blockIdx.x*blockDim.x + threadIdx.x;
    int n = i >> 8, d4 = i & 255;
    int s0 = g_tok_slot[2*n], s1 = g_tok_slot[2*n+1];
    float w0 = g_top_w[2*n], w1 = g_top_w[2*n+1];
    float4 hv = *(float4*)&g_hidden[(size_t)n*DM + d4*4];
    float4 y0 = *(float4*)&g_y[(size_t)s0*DM + d4*4];
    float4 y1 = *(float4*)&g_y[(size_t)s1*DM + d4*4];
    float4 r;
    r.x = hv.x + w0*y0.x + w1*y1.x;
    r.y = hv.y + w0*y0.y + w1*y1.y;
    r.z = hv.z + w0*y0.z + w1*y1.z;
    r.w = hv.w + w0*y0.w + w1*y1.w;
    *(float4*)&out[(size_t)n*DM + d4*4] = r;
}

// ---------------- launch ----------------
extern "C" void kernel_launch(void* const* d_in, const int* in_sizes, int n_in,
                              void* d_out, int out_size) {
    const float* hs   = (const float*)d_in[0];
    const float* ln1w = (const float*)d_in[1];
    const float* ln2w = (const float*)d_in[2];
    const float* wqkv = (const float*)d_in[3];
    const float* outw = (const float*)d_in[4];
    const float* rw   = (const float*)d_in[5];
    const float* w1   = (const float*)d_in[6];
    const float* v1   = (const float*)d_in[7];
    const float* w2   = (const float*)d_in[8];
    float* out = (float*)d_out;

    float *pqkv, *phid, *px2, *py;
    __half *px1h, *px2h, *pattnh, *ph1h, *pwqkvh, *poutwh, *pw1h, *pv1h, *pw2h;
    cudaGetSymbolAddress((void**)&pqkv,  g_qkv);
    cudaGetSymbolAddress((void**)&phid,  g_hidden);
    cudaGetSymbolAddress((void**)&px2,   g_x2);
    cudaGetSymbolAddress((void**)&py,    g_y);
    cudaGetSymbolAddress((void**)&px1h,  g_x1h);
    cudaGetSymbolAddress((void**)&px2h,  g_x2h);
    cudaGetSymbolAddress((void**)&pattnh,g_attnh);
    cudaGetSymbolAddress((void**)&ph1h,  g_h1h);
    cudaGetSymbolAddress((void**)&pwqkvh,g_wqkvh);
    cudaGetSymbolAddress((void**)&poutwh,g_outwh);
    cudaGetSymbolAddress((void**)&pw1h,  g_w1h);
    cudaGetSymbolAddress((void**)&pv1h,  g_v1h);
    cudaGetSymbolAddress((void**)&pw2h,  g_w2h);

    cudaFuncSetAttribute(flash_tc_kernel,
                         cudaFuncAttributeMaxDynamicSharedMemorySize, FLASH_SMEM);
    cudaFuncSetAttribute(hgemm<1,false,false>,
                         cudaFuncAttributeMaxDynamicSharedMemorySize, HGEMM_SMEM);
    cudaFuncSetAttribute(hgemm<2,false,false>,
                         cudaFuncAttributeMaxDynamicSharedMemorySize, HGEMM_SMEM);
    cudaFuncSetAttribute(hgemm<0,false,true>,
                         cudaFuncAttributeMaxDynamicSharedMemorySize, HGEMM_SMEM);
    cudaFuncSetAttribute(up_hgemm,
                         cudaFuncAttributeMaxDynamicSharedMemorySize, UP_SMEM);

    // ---- weight conversion (per launch; deterministic, graph-capturable) ----
    conv_h<<<(NE*FF*DM/4 + 255)/256, 256>>>(w1, pw1h, NE*FF*DM/4);
    conv_h<<<(NE*FF*DM/4 + 255)/256, 256>>>(v1, pv1h, NE*FF*DM/4);
    convT_h<<<dim3(QKVN/32, DM/32, 1), dim3(32,8)>>>(wqkv, pwqkvh, DM, QKVN);
    convT_h<<<dim3(DM/32,   DM/32, 1), dim3(32,8)>>>(outw, poutwh, DM, DM);
    convT_h<<<dim3(DM/32,   FF/32, NE), dim3(32,8)>>>(w2,  pw2h,   FF, DM);

    // LN1 -> QKV(clip) -> RoPE -> attention -> out-proj(+resid)
    ln_kernel<false,true><<<NT, 256>>>(hs, ln1w, nullptr, px1h);
    hgemm<1,false,false><<<dim3(QKVN/128, NT/128), 256, HGEMM_SMEM>>>(
        px1h, pwqkvh, pqkv, nullptr, QKVN, DM, 0);
    ropetab_kernel<<<1, 32>>>();
    rope_kernel<<<(NT*20*32 + 255)/256, 256>>>();
    flash_tc_kernel<<<dim3(SS/FQ, BB*NH), 256, FLASH_SMEM>>>(pqkv, pattnh);
    hgemm<2,false,false><<<dim3(DM/128, NT/128), 256, HGEMM_SMEM>>>(
        pattnh, poutwh, phid, hs, DM, DM, 0);

    // LN2 -> router -> top-2 dispatch
    ln_kernel<true,true><<<NT, 256>>>(phid, ln2w, px2, px2h);
    moe_init_kernel<<<(CAP + 255)/256, 256>>>();
    router_kernel<<<NT/8, 256>>>(px2, rw);
    segoff_kernel<<<1, 1>>>();
    fill_kernel<<<(NT*2 + 255)/256, 256>>>();

    // MoE: fused dual-B up (silu epilogue, fp16 out), then down
    up_hgemm<<<dim3(FF/128, CAP/128), 256, UP_SMEM>>>(px2h, pw1h, pv1h, ph1h);
    hgemm<0,false,true><<<dim3(DM/128, CAP/128), 256, HGEMM_SMEM>>>(
        ph1h, pw2h, py, nullptr, DM, FF, (long)DM*FF);

    // resid2 + gated expert outputs
    combine_kernel<<<NT, 256>>>(out);
}

// round 11
// speedup vs baseline: 5.5729x; 1.1512x over previous
#include <cuda_runtime.h>
#include <cuda_fp16.h>
#include <math.h>

// ---------------- problem constants ----------------
#define BB 2
#define SS 2048
#define DM 1024
#define NH 16
#define NKV 4
#define HDIM 64
#define NE 8
#define FF 2048
#define NT (BB*SS)                    // 4096 tokens
#define QKVN (DM + 2*NKV*HDIM)        // 1536
#define CAP (2*NT + NE*128)           // 9216 padded MoE slots
#define SCALEQ 0.125f
#define CLIPV 8.0f

// ---------------- device scratch ----------------
__device__ float g_qkv[NT*QKVN];
__device__ float g_hidden[NT*DM];
__device__ float g_x2[NT*DM];
__device__ int   g_top_e[NT*2];
__device__ float g_top_w[NT*2];
__device__ int   g_cnt[NE];
__device__ int   g_fill[NE];
__device__ int   g_segoff[NE+1];
__device__ int   g_total;
__device__ int   g_perm[CAP];
__device__ int   g_tok_slot[NT*2];
__device__ float g_y[CAP*DM];
__device__ float g_invfreq[32];
// fp16 buffers
__device__ __half g_x1h[NT*DM];
__device__ __half g_x2h[NT*DM];
__device__ __half g_attnh[NT*DM];
__device__ __half g_h1h[CAP*FF];
__device__ __half g_qkvh[NT*QKVN];           // roped q (scaled) + roped k (v slots unused)
__device__ __half g_vth[BB*NKV*HDIM*SS];     // V transposed: [b][kvh][dim][seq]
__device__ __half g_wqkvh[QKVN*DM];
__device__ __half g_outwh[DM*DM];
__device__ __half g_w1h[NE*FF*DM];
__device__ __half g_v1h[NE*FF*DM];
__device__ __half g_w2h[NE*DM*FF];

// ---------------- weight conversion ----------------
__global__ void conv_h(const float* __restrict__ in, __half* __restrict__ out, int n4) {
    int i = blockIdx.x*blockDim.x + threadIdx.x;
    if (i >= n4) return;
    float4 v = ((const float4*)in)[i];
    ((half2*)out)[i*2]   = __floats2half2_rn(v.x, v.y);
    ((half2*)out)[i*2+1] = __floats2half2_rn(v.z, v.w);
}
__global__ void convT_h(const float* __restrict__ in, __half* __restrict__ out,
                        int R, int C) {
    __shared__ float t[32][33];
    int e = blockIdx.z;
    in  += (size_t)e*R*C;
    out += (size_t)e*R*C;
    int bx = blockIdx.x*32, by = blockIdx.y*32;
    int tx = threadIdx.x, ty = threadIdx.y;
#pragma unroll
    for (int k = 0; k < 32; k += 8)
        t[ty+k][tx] = in[(size_t)(by+ty+k)*C + bx+tx];
    __syncthreads();
#pragma unroll
    for (int k = 0; k < 32; k += 8)
        out[(size_t)(bx+ty+k)*R + by+tx] = __float2half_rn(t[tx][ty+k]);
}

// ---------------- layernorm ----------------
template<bool OUTF, bool OUTH>
__global__ void ln_kernel(const float* __restrict__ x, const float* __restrict__ w,
                          float* __restrict__ outf, __half* __restrict__ outh) {
    int row = blockIdx.x, tid = threadIdx.x;
    float4 v = ((const float4*)(x + (size_t)row*DM))[tid];
    float s = v.x+v.y+v.z+v.w;
    float q = v.x*v.x+v.y*v.y+v.z*v.z+v.w*v.w;
#pragma unroll
    for (int o = 16; o; o >>= 1) {
        s += __shfl_xor_sync(0xffffffffu, s, o);
        q += __shfl_xor_sync(0xffffffffu, q, o);
    }
    __shared__ float ssm[8], qsm[8];
    if ((tid & 31) == 0) { ssm[tid>>5] = s; qsm[tid>>5] = q; }
    __syncthreads();
    float ts = 0.f, tq = 0.f;
#pragma unroll
    for (int i = 0; i < 8; i++) { ts += ssm[i]; tq += qsm[i]; }
    float mu  = ts * (1.f/DM);
    float var = tq * (1.f/DM) - mu*mu;
    float rs  = rsqrtf(var + 1e-5f);
    float4 wv = ((const float4*)w)[tid];
    float4 r;
    r.x = (v.x-mu)*rs*wv.x; r.y = (v.y-mu)*rs*wv.y;
    r.z = (v.z-mu)*rs*wv.z; r.w = (v.w-mu)*rs*wv.w;
    if (OUTF) ((float4*)(outf + (size_t)row*DM))[tid] = r;
    if (OUTH) {
        ((half2*)(outh + (size_t)row*DM))[tid*2]   = __floats2half2_rn(r.x, r.y);
        ((half2*)(outh + (size_t)row*DM))[tid*2+1] = __floats2half2_rn(r.z, r.w);
    }
}

// ---------------- mma / cp.async helpers ----------------
__device__ __forceinline__ void mma_f16(float* c,
        unsigned a0, unsigned a1, unsigned a2, unsigned a3,
        unsigned b0, unsigned b1) {
    asm volatile("mma.sync.aligned.m16n8k16.row.col.f32.f16.f16.f32 "
        "{%0,%1,%2,%3}, {%4,%5,%6,%7}, {%8,%9}, {%0,%1,%2,%3};"
        : "+f"(c[0]), "+f"(c[1]), "+f"(c[2]), "+f"(c[3])
        : "r"(a0), "r"(a1), "r"(a2), "r"(a3), "r"(b0), "r"(b1));
}
__device__ __forceinline__ void cp16(void* smem_dst, const void* gsrc, int src_bytes) {
    unsigned sa = (unsigned)__cvta_generic_to_shared(smem_dst);
    asm volatile("cp.async.cg.shared.global [%0], [%1], 16, %2;\n"
                 :: "r"(sa), "l"(gsrc), "r"(src_bytes));
}
#define CP_COMMIT() asm volatile("cp.async.commit_group;\n")
#define CP_WAITG2() asm volatile("cp.async.wait_group 2;\n")
#define CP_WAITG1() asm volatile("cp.async.wait_group 1;\n")

// ---------------- fp16 GEMM: 128x128 tile, K=32 halfs/slab, 4-stage cp.async ------
#define HSTRW 20
#define HSLABW (128*HSTRW)
#define HNSTG 4
#define HGEMM_SMEM (HNSTG*2*HSLABW*4)   // 81920 B
template<int EPI, bool GATHER, bool EXPERT>
__global__ void __launch_bounds__(256, 2)
hgemm(const __half* __restrict__ A, const __half* __restrict__ Bm,
      float* __restrict__ C, const float* __restrict__ resid,
      int N, int K, long ldbE) {
    int mbase = blockIdx.y * 128;
    if (EXPERT) {
        if (mbase >= g_total) return;
        int e = 0;
#pragma unroll
        for (int i = 0; i < NE; i++) if (g_segoff[i+1] <= mbase) e = i + 1;
        Bm += (size_t)e * ldbE;
    }
    int nbase = blockIdx.x * 128;
    extern __shared__ unsigned smw[];
    int tid  = threadIdx.x;
    int lane = tid & 31, warp = tid >> 5;
    int wM = (warp & 1) * 64;
    int wN = (warp >> 1) * 32;
    int g  = lane >> 2, tg = lane & 3;

    int ar = tid >> 1, ac = (tid & 1) * 16;
    const __half* arow;
    int asz = 16;
    if (GATHER) {
        int tok = g_perm[mbase + ar];
        asz  = (tok >= 0) ? 16 : 0;
        arow = A + (size_t)(tok >= 0 ? tok : 0) * K;
    } else {
        arow = A + (size_t)(mbase + ar) * K;
    }
    const __half* brow = Bm + (size_t)(nbase + ar) * K;

    float acc[4][4][4];
#pragma unroll
    for (int mi = 0; mi < 4; mi++)
#pragma unroll
        for (int nj = 0; nj < 4; nj++)
#pragma unroll
            for (int r = 0; r < 4; r++) acc[mi][nj][r] = 0.f;

    auto load_slab = [&](int s, int kb) {
        unsigned* As = smw + s*(2*HSLABW);
        unsigned* Bs = As + HSLABW;
        cp16(&As[ar*HSTRW + ac/2],     arow + kb + ac,     asz);
        cp16(&As[ar*HSTRW + ac/2 + 4], arow + kb + ac + 8, asz);
        cp16(&Bs[ar*HSTRW + ac/2],     brow + kb + ac,     16);
        cp16(&Bs[ar*HSTRW + ac/2 + 4], brow + kb + ac + 8, 16);
    };

    int ns = K >> 5;
#pragma unroll
    for (int j = 0; j < 3; j++) { load_slab(j, j*32); CP_COMMIT(); }

    for (int i = 0; i < ns; i++) {
        int s = i & (HNSTG-1);
        CP_WAITG2();
        __syncthreads();
        int j = i + 3;
        if (j < ns) load_slab(j & (HNSTG-1), j*32);
        CP_COMMIT();
        const unsigned* as = smw + s*(2*HSLABW);
        const unsigned* bs = as + HSLABW;
#pragma unroll
        for (int ks = 0; ks < 2; ks++) {
            int k0w = ks * 8;
            unsigned bf[4][2];
#pragma unroll
            for (int nj = 0; nj < 4; nj++) {
                int n = wN + nj*8 + g;
                bf[nj][0] = bs[n*HSTRW + k0w + tg];
                bf[nj][1] = bs[n*HSTRW + k0w + 4 + tg];
            }
#pragma unroll
            for (int mi = 0; mi < 4; mi++) {
                int m = wM + mi*16 + g;
                unsigned a0 = as[m*HSTRW + k0w + tg];
                unsigned a1 = as[(m+8)*HSTRW + k0w + tg];
                unsigned a2 = as[m*HSTRW + k0w + 4 + tg];
                unsigned a3 = as[(m+8)*HSTRW + k0w + 4 + tg];
#pragma unroll
                for (int nj = 0; nj < 4; nj++)
                    mma_f16(acc[mi][nj], a0, a1, a2, a3, bf[nj][0], bf[nj][1]);
            }
        }
    }
#pragma unroll
    for (int mi = 0; mi < 4; mi++) {
#pragma unroll
        for (int nj = 0; nj < 4; nj++) {
            int r0 = mbase + wM + mi*16 + g;
            int r1 = r0 + 8;
            int c  = nbase + wN + nj*8 + tg*2;
            float v0 = acc[mi][nj][0], v1 = acc[mi][nj][1];
            float v2 = acc[mi][nj][2], v3 = acc[mi][nj][3];
            if (EPI == 1) {
                v0 = fminf(fmaxf(v0,-CLIPV),CLIPV); v1 = fminf(fmaxf(v1,-CLIPV),CLIPV);
                v2 = fminf(fmaxf(v2,-CLIPV),CLIPV); v3 = fminf(fmaxf(v3,-CLIPV),CLIPV);
            }
            if (EPI == 2) {
                float2 r0v = *(const float2*)(resid + (size_t)r0*N + c);
                float2 r1v = *(const float2*)(resid + (size_t)r1*N + c);
                v0 += r0v.x; v1 += r0v.y; v2 += r1v.x; v3 += r1v.y;
            }
            *(float2*)(C + (size_t)r0*N + c) = make_float2(v0, v1);
            *(float2*)(C + (size_t)r1*N + c) = make_float2(v2, v3);
        }
    }
}

// ---------------- fp16 dual-B up GEMM ----------------
#define UNSTG 4
#define UP_SMEM (UNSTG*3*HSLABW*4)     // 122880 B
__global__ void __launch_bounds__(256, 1)
up_hgemm(const __half* __restrict__ A, const __half* __restrict__ Bw,
         const __half* __restrict__ Bv, __half* __restrict__ C) {
    const int N = FF, K = DM;
    int mbase = blockIdx.y * 128;
    if (mbase >= g_total) return;
    int e = 0;
#pragma unroll
    for (int i = 0; i < NE; i++) if (g_segoff[i+1] <= mbase) e = i + 1;
    Bw += (size_t)e * FF * DM;
    Bv += (size_t)e * FF * DM;
    int nbase = blockIdx.x * 128;
    extern __shared__ unsigned smw[];
    int tid  = threadIdx.x;
    int lane = tid & 31, warp = tid >> 5;
    int wM = (warp & 1) * 64;
    int wN = (warp >> 1) * 32;
    int g  = lane >> 2, tg = lane & 3;

    int ar = tid >> 1, ac = (tid & 1) * 16;
    int tok = g_perm[mbase + ar];
    int asz  = (tok >= 0) ? 16 : 0;
    const __half* arow = A + (size_t)(tok >= 0 ? tok : 0) * K;
    const __half* wrow = Bw + (size_t)(nbase + ar) * K;
    const __half* vrow = Bv + (size_t)(nbase + ar) * K;

    float accw[4][4][4], accv[4][4][4];
#pragma unroll
    for (int mi = 0; mi < 4; mi++)
#pragma unroll
        for (int nj = 0; nj < 4; nj++)
#pragma unroll
            for (int r = 0; r < 4; r++) { accw[mi][nj][r] = 0.f; accv[mi][nj][r] = 0.f; }

    auto load_slab = [&](int s, int kb) {
        unsigned* As = smw + s*(3*HSLABW);
        unsigned* Ws = As + HSLABW;
        unsigned* Vs = Ws + HSLABW;
        cp16(&As[ar*HSTRW + ac/2],     arow + kb + ac,     asz);
        cp16(&As[ar*HSTRW + ac/2 + 4], arow + kb + ac + 8, asz);
        cp16(&Ws[ar*HSTRW + ac/2],     wrow + kb + ac,     16);
        cp16(&Ws[ar*HSTRW + ac/2 + 4], wrow + kb + ac + 8, 16);
        cp16(&Vs[ar*HSTRW + ac/2],     vrow + kb + ac,     16);
        cp16(&Vs[ar*HSTRW + ac/2 + 4], vrow + kb + ac + 8, 16);
    };

    const int ns = K >> 5;
#pragma unroll
    for (int j = 0; j < 3; j++) { load_slab(j, j*32); CP_COMMIT(); }

    for (int i = 0; i < ns; i++) {
        int s = i & (UNSTG-1);
        CP_WAITG2();
        __syncthreads();
        int j = i + 3;
        if (j < ns) load_slab(j & (UNSTG-1), j*32);
        CP_COMMIT();
        const unsigned* as = smw + s*(3*HSLABW);
        const unsigned* ws = as + HSLABW;
        const unsigned* vs = ws + HSLABW;
#pragma unroll
        for (int ks = 0; ks < 2; ks++) {
            int k0w = ks * 8;
            unsigned bw[4][2], bv[4][2];
#pragma unroll
            for (int nj = 0; nj < 4; nj++) {
                int n = wN + nj*8 + g;
                bw[nj][0] = ws[n*HSTRW + k0w + tg];
                bw[nj][1] = ws[n*HSTRW + k0w + 4 + tg];
                bv[nj][0] = vs[n*HSTRW + k0w + tg];
                bv[nj][1] = vs[n*HSTRW + k0w + 4 + tg];
            }
#pragma unroll
            for (int mi = 0; mi < 4; mi++) {
                int m = wM + mi*16 + g;
                unsigned a0 = as[m*HSTRW + k0w + tg];
                unsigned a1 = as[(m+8)*HSTRW + k0w + tg];
                unsigned a2 = as[m*HSTRW + k0w + 4 + tg];
                unsigned a3 = as[(m+8)*HSTRW + k0w + 4 + tg];
#pragma unroll
                for (int nj = 0; nj < 4; nj++) {
                    mma_f16(accw[mi][nj], a0, a1, a2, a3, bw[nj][0], bw[nj][1]);
                    mma_f16(accv[mi][nj], a0, a1, a2, a3, bv[nj][0], bv[nj][1]);
                }
            }
        }
    }
#pragma unroll
    for (int mi = 0; mi < 4; mi++) {
#pragma unroll
        for (int nj = 0; nj < 4; nj++) {
            int r0 = mbase + wM + mi*16 + g;
            int r1 = r0 + 8;
            int c  = nbase + wN + nj*8 + tg*2;
            float w0 = accw[mi][nj][0], w1 = accw[mi][nj][1];
            float w2 = accw[mi][nj][2], w3 = accw[mi][nj][3];
            float v0 = accv[mi][nj][0] * (w0 / (1.f + __expf(-w0)));
            float v1 = accv[mi][nj][1] * (w1 / (1.f + __expf(-w1)));
            float v2 = accv[mi][nj][2] * (w2 / (1.f + __expf(-w2)));
            float v3 = accv[mi][nj][3] * (w3 / (1.f + __expf(-w3)));
            *(half2*)(C + (size_t)r0*N + c) = __floats2half2_rn(v0, v1);
            *(half2*)(C + (size_t)r1*N + c) = __floats2half2_rn(v2, v3);
        }
    }
}

// ---------------- RoPE: fp32 qkv -> fp16 roped q (scaled) + roped k ----------------
__global__ void ropetab_kernel() {
    int i = threadIdx.x;
    if (i < 32) g_invfreq[i] = (float)pow(10000.0, -(double)i / 32.0);
}
__global__ void rope_conv_kernel() {
    int idx = blockIdx.x*blockDim.x + threadIdx.x;
    if (idx >= NT*20*32) return;
    int i    = idx & 31;
    int head = (idx >> 5) % 20;
    int n    = idx / (32*20);
    int s    = n & (SS - 1);
    float ang = (float)s * g_invfreq[i];
    float sn, cs;
    sincosf(ang, &sn, &cs);
    size_t off = (size_t)n*QKVN + (head < NH ? head*HDIM : DM + (head-NH)*HDIM);
    const float* base = g_qkv + off;
    float x1 = base[i], x2 = base[i+32];
    float y1 = x1*cs - x2*sn;
    float y2 = x1*sn + x2*cs;
    if (head < NH) { y1 *= SCALEQ; y2 *= SCALEQ; }
    g_qkvh[off + i]      = __float2half_rn(y1);
    g_qkvh[off + i + 32] = __float2half_rn(y2);
}
// V transpose: g_qkv v slots [tok][kvh][d] -> g_vth [b][kvh][d][s], fp16
__global__ void vt_kernel() {
    __shared__ float t[32][33];
    int bk = blockIdx.z;                   // b*NKV + kvh
    int b  = bk >> 2, kvh = bk & 3;
    int s0 = blockIdx.x*32, d0 = blockIdx.y*32;
    int tx = threadIdx.x, ty = threadIdx.y;
    const float* src = g_qkv + (size_t)(b*SS)*QKVN + DM + NKV*HDIM + kvh*HDIM;
#pragma unroll
    for (int k = 0; k < 32; k += 8)
        t[ty+k][tx] = src[(size_t)(s0+ty+k)*QKVN + d0+tx];
    __syncthreads();
    __half* dst = g_vth + ((size_t)bk*HDIM)*SS;
#pragma unroll
    for (int k = 0; k < 32; k += 8)
        dst[(size_t)(d0+ty+k)*SS + s0+tx] = __float2half_rn(t[tx][ty+k]);
}

// ---------------- fp16 flash attention: QK | PV(prev) | softmax pipeline ----------------
#define FQ 128
#define FKT 64
#define FSTW 36    // words per 64-half row (+pad)
// words: Q 128 + K 2x64 + Vt 3x64 + P 128 rows
#define FLASH_SMEM ((FQ + 2*FKT + 3*FKT + FQ)*FSTW*4)   // 82944 B
__global__ void __launch_bounds__(256)
flash_h_kernel(const __half* __restrict__ qkvh, const __half* __restrict__ vth,
               __half* __restrict__ out) {
    extern __shared__ unsigned smw[];
    unsigned* Qs = smw;
    unsigned* Kst = Qs + FQ*FSTW;
    unsigned* Vst = Kst + 2*FKT*FSTW;
    unsigned* Ps = Vst + 3*FKT*FSTW;
    int qb = gridDim.x - 1 - blockIdx.x;
    int bh = blockIdx.y;
    int b = bh >> 4, h = bh & 15, kh = h >> 2;
    int tid = threadIdx.x, lane = tid & 31, warp = tid >> 5;
    int g = lane >> 2, tg = lane & 3;

    // Q tile via cp.async (pre-scaled, roped fp16)
    {
        const __half* qp = qkvh + (size_t)(b*SS + qb*FQ)*QKVN + h*HDIM;
        int r = tid >> 1;
        int c0 = (tid & 1) * 4;    // first of 4 chunks (8 halfs each)
#pragma unroll
        for (int q = 0; q < 4; q++)
            cp16(&Qs[r*FSTW + (c0+q)*4], qp + (size_t)r*QKVN + (c0+q)*8, 16);
    }
    int kvr = tid >> 2, kvc = (tid & 3) * 2;   // row, first of 2 chunks
    const __half* kbase = qkvh + (size_t)(b*SS)*QKVN + DM + kh*HDIM;
    const __half* vtb = vth + ((size_t)(b*NKV + kh)*HDIM)*SS;
    auto load_kv = [&](int kst, int vst, int kt) {
        const __half* kp = kbase + (size_t)(kt*FKT + kvr)*QKVN;
        const __half* vp = vtb + (size_t)kvr*SS + kt*FKT;   // row = dim
        unsigned* kd = Kst + kst*FKT*FSTW + kvr*FSTW;
        unsigned* vd = Vst + vst*FKT*FSTW + kvr*FSTW;
#pragma unroll
        for (int q = 0; q < 2; q++) {
            cp16(kd + (kvc+q)*4, kp + (kvc+q)*8, 16);
            cp16(vd + (kvc+q)*4, vp + (kvc+q)*8, 16);
        }
    };

    int wrow = warp*16;
    int grow = qb*FQ + wrow;

    float m0 = -1e30f, m1 = -1e30f, l0 = 0.f, l1 = 0.f;
    float o[8][4];
#pragma unroll
    for (int nj = 0; nj < 8; nj++)
#pragma unroll
        for (int r = 0; r < 4; r++) o[nj][r] = 0.f;

    int ktmax = 2*qb + 1;
    load_kv(0, 0, 0);
    CP_COMMIT();

    bool pend = false;
    int pkt = 0;

    for (int kt = 0; kt <= ktmax; kt++) {
        __syncthreads();
        if (kt < ktmax) load_kv((kt+1)&1, (kt+1)%3, kt+1);
        CP_COMMIT();
        CP_WAITG1();
        __syncthreads();

        bool act = (kt*FKT <= grow + 15);
        float s[8][4];
        if (act) {
            const unsigned* Ks = Kst + (kt&1)*FKT*FSTW;
#pragma unroll
            for (int nj = 0; nj < 8; nj++)
#pragma unroll
                for (int r = 0; r < 4; r++) s[nj][r] = 0.f;
#pragma unroll
            for (int k0w = 0; k0w < 32; k0w += 8) {   // 4 k16 steps over HDIM=64
                unsigned a0 = Qs[(wrow+g  )*FSTW + k0w+tg];
                unsigned a1 = Qs[(wrow+g+8)*FSTW + k0w+tg];
                unsigned a2 = Qs[(wrow+g  )*FSTW + k0w+4+tg];
                unsigned a3 = Qs[(wrow+g+8)*FSTW + k0w+4+tg];
#pragma unroll
                for (int nj = 0; nj < 8; nj++) {
                    unsigned b0 = Ks[(nj*8+g)*FSTW + k0w+tg];
                    unsigned b1 = Ks[(nj*8+g)*FSTW + k0w+4+tg];
                    mma_f16(s[nj], a0, a1, a2, a3, b0, b1);
                }
            }
        }

        if (pend) {
            const unsigned* Vs = Vst + (pkt%3)*FKT*FSTW;
#pragma unroll
            for (int k0w = 0; k0w < 32; k0w += 8) {   // 4 k16 steps over 64 keys
                unsigned a0 = Ps[(wrow+g  )*FSTW + k0w+tg];
                unsigned a1 = Ps[(wrow+g+8)*FSTW + k0w+tg];
                unsigned a2 = Ps[(wrow+g  )*FSTW + k0w+4+tg];
                unsigned a3 = Ps[(wrow+g+8)*FSTW + k0w+4+tg];
#pragma unroll
                for (int nj = 0; nj < 8; nj++) {
                    unsigned b0 = Vs[(nj*8+g)*FSTW + k0w+tg];
                    unsigned b1 = Vs[(nj*8+g)*FSTW + k0w+4+tg];
                    mma_f16(o[nj], a0, a1, a2, a3, b0, b1);
                }
            }
            pend = false;
        }

        if (act) {
            if (kt >= 2*qb) {
                int r0 = grow + g, r1 = grow + g + 8;
#pragma unroll
                for (int nj = 0; nj < 8; nj++) {
                    int c = kt*FKT + nj*8 + 2*tg;
                    if (c     > r0) s[nj][0] = -1e30f;
                    if (c + 1 > r0) s[nj][1] = -1e30f;
                    if (c     > r1) s[nj][2] = -1e30f;
                    if (c + 1 > r1) s[nj][3] = -1e30f;
                }
            }
            float mt0 = -1e30f, mt1 = -1e30f;
#pragma unroll
            for (int nj = 0; nj < 8; nj++) {
                mt0 = fmaxf(mt0, fmaxf(s[nj][0], s[nj][1]));
                mt1 = fmaxf(mt1, fmaxf(s[nj][2], s[nj][3]));
            }
            mt0 = fmaxf(mt0, __shfl_xor_sync(0xffffffffu, mt0, 1));
            mt0 = fmaxf(mt0, __shfl_xor_sync(0xffffffffu, mt0, 2));
            mt1 = fmaxf(mt1, __shfl_xor_sync(0xffffffffu, mt1, 1));
            mt1 = fmaxf(mt1, __shfl_xor_sync(0xffffffffu, mt1, 2));
            float mn0 = fmaxf(m0, mt0), mn1 = fmaxf(m1, mt1);
            float c0 = __expf(m0 - mn0), c1 = __expf(m1 - mn1);
            l0 *= c0; l1 *= c1;
#pragma unroll
            for (int nj = 0; nj < 8; nj++) {
                o[nj][0] *= c0; o[nj][1] *= c0;
                o[nj][2] *= c1; o[nj][3] *= c1;
            }
            float rs0 = 0.f, rs1 = 0.f;
#pragma unroll
            for (int nj = 0; nj < 8; nj++) {
                float p0 = __expf(s[nj][0] - mn0);
                float p1 = __expf(s[nj][1] - mn0);
                float p2 = __expf(s[nj][2] - mn1);
                float p3 = __expf(s[nj][3] - mn1);
                rs0 += p0 + p1; rs1 += p2 + p3;
                int w = nj*4 + tg;
                ((half2*)Ps)[ ((wrow+g  )*FSTW + w) ] = __floats2half2_rn(p0, p1);
                ((half2*)Ps)[ ((wrow+g+8)*FSTW + w) ] = __floats2half2_rn(p2, p3);
            }
            rs0 += __shfl_xor_sync(0xffffffffu, rs0, 1);
            rs0 += __shfl_xor_sync(0xffffffffu, rs0, 2);
            rs1 += __shfl_xor_sync(0xffffffffu, rs1, 1);
            rs1 += __shfl_xor_sync(0xffffffffu, rs1, 2);
            l0 += rs0; l1 += rs1;
            m0 = mn0; m1 = mn1;
            __syncwarp();
            pend = true;
            pkt  = kt;
        }
    }

    if (pend) {
        const unsigned* Vs = Vst + (pkt%3)*FKT*FSTW;
#pragma unroll
        for (int k0w = 0; k0w < 32; k0w += 8) {
            unsigned a0 = Ps[(wrow+g  )*FSTW + k0w+tg];
            unsigned a1 = Ps[(wrow+g+8)*FSTW + k0w+tg];
            unsigned a2 = Ps[(wrow+g  )*FSTW + k0w+4+tg];
            unsigned a3 = Ps[(wrow+g+8)*FSTW + k0w+4+tg];
#pragma unroll
            for (int nj = 0; nj < 8; nj++) {
                unsigned b0 = Vs[(nj*8+g)*FSTW + k0w+tg];
                unsigned b1 = Vs[(nj*8+g)*FSTW + k0w+4+tg];
                mma_f16(o[nj], a0, a1, a2, a3, b0, b1);
            }
        }
    }

    float il0 = 1.f/l0, il1 = 1.f/l1;
    size_t tok0 = (size_t)(b*SS + qb*FQ + wrow + g);
    size_t tok1 = tok0 + 8;
#pragma unroll
    for (int nj = 0; nj < 8; nj++) {
        int col = h*HDIM + nj*8 + 2*tg;
        *(half2*)(out + tok0*DM + col) = __floats2half2_rn(o[nj][0]*il0, o[nj][1]*il0);
        *(half2*)(out + tok1*DM + col) = __floats2half2_rn(o[nj][2]*il1, o[nj][3]*il1);
    }
}

// ---------------- router ----------------
__global__ void router_kernel(const float* __restrict__ x2, const float* __restrict__ rw) {
    int t = (blockIdx.x*blockDim.x + threadIdx.x) >> 5;
    int lane = threadIdx.x & 31;
    if (t >= NT) return;
    const float* xr = x2 + (size_t)t*DM;
    float acc[NE];
#pragma unroll
    for (int e = 0; e < NE; e++) acc[e] = 0.f;
    for (int d = lane; d < DM; d += 32) {
        float xv = xr[d];
        float4 r0 = ((const float4*)rw)[d*2];
        float4 r1 = ((const float4*)rw)[d*2+1];
        acc[0]+=xv*r0.x; acc[1]+=xv*r0.y; acc[2]+=xv*r0.z; acc[3]+=xv*r0.w;
        acc[4]+=xv*r1.x; acc[5]+=xv*r1.y; acc[6]+=xv*r1.z; acc[7]+=xv*r1.w;
    }
#pragma unroll
    for (int o = 16; o; o >>= 1)
#pragma unroll
        for (int e = 0; e < NE; e++)
            acc[e] += __shfl_xor_sync(0xffffffffu, acc[e], o);
    if (lane == 0) {
        int e0 = 0; float m0 = acc[0];
#pragma unroll
        for (int e = 1; e < NE; e++) if (acc[e] > m0) { m0 = acc[e]; e0 = e; }
        int e1 = -1; float m1 = -3.4e38f;
#pragma unroll
        for (int e = 0; e < NE; e++) if (e != e0 && acc[e] > m1) { m1 = acc[e]; e1 = e; }
        float p1 = expf(m1 - m0);
        float w0 = 1.f / (1.f + p1);
        float w1 = p1 / (1.f + p1);
        g_top_e[2*t] = e0; g_top_e[2*t+1] = e1;
        g_top_w[2*t] = w0; g_top_w[2*t+1] = w1;
        atomicAdd(&g_cnt[e0], 1);
        atomicAdd(&g_cnt[e1], 1);
    }
}

__global__ void moe_init_kernel() {
    int i = blockIdx.x*blockDim.x + threadIdx.x;
    if (i < NE) { g_cnt[i] = 0; g_fill[i] = 0; }
    if (i < CAP) g_perm[i] = -1;
}

__global__ void segoff_kernel() {
    int off = 0;
    for (int e = 0; e < NE; e++) {
        g_segoff[e] = off;
        off += ((g_cnt[e] + 127) >> 7) << 7;
    }
    g_segoff[NE] = off;
    g_total = off;
}

__global__ void fill_kernel() {
    int i = blockIdx.x*blockDim.x + threadIdx.x;
    if (i >= NT*2) return;
    int e = g_top_e[i];
    int pos = g_segoff[e] + atomicAdd(&g_fill[e], 1);
    g_perm[pos] = i >> 1;
    g_tok_slot[i] = pos;
}

__global__ void combine_kernel(float* __restrict__ out) {
    int i = blockIdx.x*blockDim.x + threadIdx.x;
    int n = i >> 8, d4 = i & 255;
    int s0 = g_tok_slot[2*n], s1 = g_tok_slot[2*n+1];
    float w0 = g_top_w[2*n], w1 = g_top_w[2*n+1];
    float4 hv = *(float4*)&g_hidden[(size_t)n*DM + d4*4];
    float4 y0 = *(float4*)&g_y[(size_t)s0*DM + d4*4];
    float4 y1 = *(float4*)&g_y[(size_t)s1*DM + d4*4];
    float4 r;
    r.x = hv.x + w0*y0.x + w1*y1.x;
    r.y = hv.y + w0*y0.y + w1*y1.y;
    r.z = hv.z + w0*y0.z + w1*y1.z;
    r.w = hv.w + w0*y0.w + w1*y1.w;
    *(float4*)&out[(size_t)n*DM + d4*4] = r;
}

// ---------------- launch ----------------
extern "C" void kernel_launch(void* const* d_in, const int* in_sizes, int n_in,
                              void* d_out, int out_size) {
    const float* hs   = (const float*)d_in[0];
    const float* ln1w = (const float*)d_in[1];
    const float* ln2w = (const float*)d_in[2];
    const float* wqkv = (const float*)d_in[3];
    const float* outw = (const float*)d_in[4];
    const float* rw   = (const float*)d_in[5];
    const float* w1   = (const float*)d_in[6];
    const float* v1   = (const float*)d_in[7];
    const float* w2   = (const float*)d_in[8];
    float* out = (float*)d_out;

    float *pqkv, *phid, *px2, *py;
    __half *px1h, *px2h, *pattnh, *ph1h, *pqkvh, *pvth;
    __half *pwqkvh, *poutwh, *pw1h, *pv1h, *pw2h;
    cudaGetSymbolAddress((void**)&pqkv,  g_qkv);
    cudaGetSymbolAddress((void**)&phid,  g_hidden);
    cudaGetSymbolAddress((void**)&px2,   g_x2);
    cudaGetSymbolAddress((void**)&py,    g_y);
    cudaGetSymbolAddress((void**)&px1h,  g_x1h);
    cudaGetSymbolAddress((void**)&px2h,  g_x2h);
    cudaGetSymbolAddress((void**)&pattnh,g_attnh);
    cudaGetSymbolAddress((void**)&ph1h,  g_h1h);
    cudaGetSymbolAddress((void**)&pqkvh, g_qkvh);
    cudaGetSymbolAddress((void**)&pvth,  g_vth);
    cudaGetSymbolAddress((void**)&pwqkvh,g_wqkvh);
    cudaGetSymbolAddress((void**)&poutwh,g_outwh);
    cudaGetSymbolAddress((void**)&pw1h,  g_w1h);
    cudaGetSymbolAddress((void**)&pv1h,  g_v1h);
    cudaGetSymbolAddress((void**)&pw2h,  g_w2h);

    cudaFuncSetAttribute(flash_h_kernel,
                         cudaFuncAttributeMaxDynamicSharedMemorySize, FLASH_SMEM);
    cudaFuncSetAttribute(hgemm<1,false,false>,
                         cudaFuncAttributeMaxDynamicSharedMemorySize, HGEMM_SMEM);
    cudaFuncSetAttribute(hgemm<2,false,false>,
                         cudaFuncAttributeMaxDynamicSharedMemorySize, HGEMM_SMEM);
    cudaFuncSetAttribute(hgemm<0,false,true>,
                         cudaFuncAttributeMaxDynamicSharedMemorySize, HGEMM_SMEM);
    cudaFuncSetAttribute(up_hgemm,
                         cudaFuncAttributeMaxDynamicSharedMemorySize, UP_SMEM);

    // ---- weight conversion ----
    conv_h<<<(NE*FF*DM/4 + 255)/256, 256>>>(w1, pw1h, NE*FF*DM/4);
    conv_h<<<(NE*FF*DM/4 + 255)/256, 256>>>(v1, pv1h, NE*FF*DM/4);
    convT_h<<<dim3(QKVN/32, DM/32, 1), dim3(32,8)>>>(wqkv, pwqkvh, DM, QKVN);
    convT_h<<<dim3(DM/32,   DM/32, 1), dim3(32,8)>>>(outw, poutwh, DM, DM);
    convT_h<<<dim3(DM/32,   FF/32, NE), dim3(32,8)>>>(w2,  pw2h,   FF, DM);

    // LN1 -> QKV(clip) -> RoPE(fp16) + V^T -> attention -> out-proj(+resid)
    ln_kernel<false,true><<<NT, 256>>>(hs, ln1w, nullptr, px1h);
    hgemm<1,false,false><<<dim3(QKVN/128, NT/128), 256, HGEMM_SMEM>>>(
        px1h, pwqkvh, pqkv, nullptr, QKVN, DM, 0);
    ropetab_kernel<<<1, 32>>>();
    rope_conv_kernel<<<(NT*20*32 + 255)/256, 256>>>();
    vt_kernel<<<dim3(SS/32, HDIM/32, BB*NKV), dim3(32,8)>>>();
    flash_h_kernel<<<dim3(SS/FQ, BB*NH), 256, FLASH_SMEM>>>(pqkvh, pvth, pattnh);
    hgemm<2,false,false><<<dim3(DM/128, NT/128), 256, HGEMM_SMEM>>>(
        pattnh, poutwh, phid, hs, DM, DM, 0);

    // LN2 -> router -> top-2 dispatch
    ln_kernel<true,true><<<NT, 256>>>(phid, ln2w, px2, px2h);
    moe_init_kernel<<<(CAP + 255)/256, 256>>>();
    router_kernel<<<NT/8, 256>>>(px2, rw);
    segoff_kernel<<<1, 1>>>();
    fill_kernel<<<(NT*2 + 255)/256, 256>>>();

    // MoE: fused dual-B up (silu epilogue, fp16 out), then down
    up_hgemm<<<dim3(FF/128, CAP/128), 256, UP_SMEM>>>(px2h, pw1h, pv1h, ph1h);
    hgemm<0,false,true><<<dim3(DM/128, CAP/128), 256, HGEMM_SMEM>>>(
        ph1h, pw2h, py, nullptr, DM, FF, (long)DM*FF);

    // resid2 + gated expert outputs
    combine_kernel<<<NT, 256>>>(out);
}